// round 1
// baseline (speedup 1.0000x reference)
#include <cuda_runtime.h>

// ---------------- problem constants ----------------
#define NN 2048          // nodes
#define CD 512           // input channels
#define DD 128           // embed dim
#define KP 1024          // pooled nodes
#define NW 64            // 2048 bits / 32
#define INVT 14.285714285714286f   // 1/0.07

// ---------------- device scratch (no allocations allowed) ----------------
__device__ __align__(16) float g_fet[NN*DD];
__device__ __align__(16) float g_fes[NN*DD];
__device__ __align__(16) float g_G[NN*NN];          // gram scratch (reused 3x)
__device__ __align__(16) float g_An[NN*NN];         // normalized adjacency
__device__ unsigned g_bits[NN*NW];                  // adjacency bitmask
__device__ float g_deg[NN];
__device__ __align__(16) float g_h1[2][NN*DD];
__device__ __align__(16) float g_h2[2][NN*DD];
__device__ __align__(16) float g_fg[2][NN*DD];      // [0]=teacher,[1]=student
__device__ float g_scores[NN];
__device__ int   g_idx[KP];
__device__ float g_vals[KP];
__device__ __align__(16) float g_newh[2][KP*DD];
__device__ __align__(16) float g_Anp[KP*KP];
__device__ float g_degp[KP];
__device__ __align__(16) float g_h1p[2][KP*DD];
__device__ __align__(16) float g_fp[2][KP*DD];
__device__ __align__(16) float g_part[16][NN*DD];   // split-K partials (2 z * 8 slots)
__device__ float g_rl[NN], g_cl[NN], g_rlp[KP], g_clp[KP];

// ---------------- GEMM: C[M,128] = A[M,K] @ B[K,128], split-K into partials ----------------
// grid: (M/64, nKchunks, 2).  Writes partial slot (z*nsl + sbase + blockIdx.y).
__global__ void k_gemm_nn_sk(const float* __restrict__ A0, const float* __restrict__ A1, int lda,
                             const float* __restrict__ B0, const float* __restrict__ B1,
                             float* __restrict__ P, int M, int Kchunk, int sbase, int nsl)
{
    __shared__ float As[16][64];
    __shared__ float Bs[16][128];
    const float* A = blockIdx.z ? A1 : A0;
    const float* B = blockIdx.z ? B1 : B0;
    int row0 = blockIdx.x * 64;
    int k0 = blockIdx.y * Kchunk;
    float* Pout = P + (size_t)(blockIdx.z * nsl + sbase + blockIdx.y) * ((size_t)M * 128);
    int tid = threadIdx.x;
    int tx = tid & 31, ty = tid >> 5;           // tx: 32 col-groups of 4, ty: 8 row-groups of 8
    int ar = tid >> 2, ac = (tid & 3) << 2;     // A tile loader
    int bc = (tid & 31) << 2, bk = tid >> 5;    // B tile loader
    float acc[8][4];
#pragma unroll
    for (int i = 0; i < 8; i++)
#pragma unroll
        for (int j = 0; j < 4; j++) acc[i][j] = 0.f;

    for (int kt = k0; kt < k0 + Kchunk; kt += 16) {
        float4 av = *(const float4*)(A + (size_t)(row0 + ar) * lda + kt + ac);
        As[ac + 0][ar] = av.x; As[ac + 1][ar] = av.y; As[ac + 2][ar] = av.z; As[ac + 3][ar] = av.w;
        *(float4*)&Bs[bk][bc]     = *(const float4*)(B + (size_t)(kt + bk) * 128 + bc);
        *(float4*)&Bs[bk + 8][bc] = *(const float4*)(B + (size_t)(kt + bk + 8) * 128 + bc);
        __syncthreads();
#pragma unroll
        for (int kk = 0; kk < 16; kk++) {
            float4 b4 = *(float4*)&Bs[kk][tx << 2];
            float4 a0 = *(float4*)&As[kk][ty << 3];
            float4 a1 = *(float4*)&As[kk][(ty << 3) + 4];
            float bb[4] = {b4.x, b4.y, b4.z, b4.w};
            float aa[8] = {a0.x, a0.y, a0.z, a0.w, a1.x, a1.y, a1.z, a1.w};
#pragma unroll
            for (int i = 0; i < 8; i++)
#pragma unroll
                for (int j = 0; j < 4; j++)
                    acc[i][j] += aa[i] * bb[j];
        }
        __syncthreads();
    }
#pragma unroll
    for (int i = 0; i < 8; i++) {
        float4 v = make_float4(acc[i][0], acc[i][1], acc[i][2], acc[i][3]);
        *(float4*)(Pout + (size_t)(row0 + (ty << 3) + i) * 128 + (tx << 2)) = v;
    }
}

// ---------------- GEMM NT: C[M,N] = A[M,128] @ B[N,128]^T ----------------
// grid: (M/64, N/64)
__global__ void k_gemm_nt(const float* __restrict__ A, const float* __restrict__ Bt,
                          float* __restrict__ Cm, int ldc)
{
    __shared__ float As[16][64];
    __shared__ float Bs[16][64];
    int row0 = blockIdx.x * 64, col0 = blockIdx.y * 64;
    int tid = threadIdx.x;
    int tx = tid & 15, ty = tid >> 4;
    int ar = tid >> 2, ac = (tid & 3) << 2;
    float acc[4][4];
#pragma unroll
    for (int i = 0; i < 4; i++)
#pragma unroll
        for (int j = 0; j < 4; j++) acc[i][j] = 0.f;

    for (int kt = 0; kt < 128; kt += 16) {
        float4 av = *(const float4*)(A + (size_t)(row0 + ar) * 128 + kt + ac);
        As[ac + 0][ar] = av.x; As[ac + 1][ar] = av.y; As[ac + 2][ar] = av.z; As[ac + 3][ar] = av.w;
        float4 bv = *(const float4*)(Bt + (size_t)(col0 + ar) * 128 + kt + ac);
        Bs[ac + 0][ar] = bv.x; Bs[ac + 1][ar] = bv.y; Bs[ac + 2][ar] = bv.z; Bs[ac + 3][ar] = bv.w;
        __syncthreads();
#pragma unroll
        for (int kk = 0; kk < 16; kk++) {
            float4 a4 = *(float4*)&As[kk][ty << 2];
            float4 b4 = *(float4*)&Bs[kk][tx << 2];
            float aa[4] = {a4.x, a4.y, a4.z, a4.w};
            float bb[4] = {b4.x, b4.y, b4.z, b4.w};
#pragma unroll
            for (int i = 0; i < 4; i++)
#pragma unroll
                for (int j = 0; j < 4; j++)
                    acc[i][j] += aa[i] * bb[j];
        }
        __syncthreads();
    }
#pragma unroll
    for (int i = 0; i < 4; i++) {
        float4 v = make_float4(acc[i][0], acc[i][1], acc[i][2], acc[i][3]);
        *(float4*)(Cm + (size_t)(row0 + (ty << 2) + i) * ldc + col0 + (tx << 2)) = v;
    }
}

// ---------------- reduce split-K partials (+bias), grid (cnt/256,1,2) ----------------
__global__ void k_reduce(const float* __restrict__ P, int nsl, int cnt,
                         float* __restrict__ O0, float* __restrict__ O1,
                         const float* __restrict__ bias)
{
    float* O = blockIdx.z ? O1 : O0;
    const float* Pz = P + (size_t)blockIdx.z * nsl * cnt;
    int i = blockIdx.x * 256 + threadIdx.x;
    float s = bias ? bias[i & 127] : 0.f;
    for (int k = 0; k < nsl; k++) s += Pz[(size_t)k * cnt + i];
    O[i] = s;
}

// ---------------- row l2-normalize in place, grid (M,1,2), 128 threads ----------------
__global__ void k_l2norm(float* __restrict__ X0, float* __restrict__ X1)
{
    float* X = blockIdx.z ? X1 : X0;
    int r = blockIdx.x, t = threadIdx.x;
    float v = X[(size_t)r * 128 + t];
    float s = v * v;
    for (int o = 16; o; o >>= 1) s += __shfl_xor_sync(~0u, s, o);
    __shared__ float ws[4];
    if ((t & 31) == 0) ws[t >> 5] = s;
    __syncthreads();
    float tot = ws[0] + ws[1] + ws[2] + ws[3];
    X[(size_t)r * 128 + t] = v * rsqrtf(tot);
}

// ---------------- adjacency bitmask from gram (strict >0, self loops) ----------------
__global__ void k_bits()
{
    int t = blockIdx.x * 256 + threadIdx.x;     // < NN*NW
    int i = t >> 6, w = t & 63;
    const float* row = g_G + (size_t)i * NN + w * 32;
    unsigned m = 0;
#pragma unroll
    for (int b = 0; b < 32; b++)
        if (row[b] > 0.f) m |= 1u << b;
    if (w == (i >> 5)) m |= 1u << (i & 31);     // self loop
    g_bits[t] = m;
}

__global__ void k_deg()
{
    int i = blockIdx.x * 256 + threadIdx.x;
    int s = 0;
#pragma unroll
    for (int w = 0; w < NW; w++) s += __popc(g_bits[i * NW + w]);
    g_deg[i] = (float)s;
}

__global__ void k_an()
{
    int gi = blockIdx.x * 256 + threadIdx.x;    // < NN*NN
    int i = gi >> 11, j = gi & 2047;
    bool a = (g_G[(size_t)gi] > 0.f) || (i == j);
    g_An[(size_t)gi] = a ? rsqrtf(g_deg[i] * g_deg[j]) : 0.f;
}

// ---------------- pooling scores: sigmoid(f_gt @ W_pool + b) ----------------
__global__ void k_scores(const float* __restrict__ Wp, const float* __restrict__ bp)
{
    int warp = threadIdx.x >> 5, lane = threadIdx.x & 31;
    int r = blockIdx.x * 8 + warp;
    const float* x = g_fg[0] + (size_t)r * DD;
    float s = x[lane] * Wp[lane] + x[lane + 32] * Wp[lane + 32]
            + x[lane + 64] * Wp[lane + 64] + x[lane + 96] * Wp[lane + 96];
    for (int o = 16; o; o >>= 1) s += __shfl_xor_sync(~0u, s, o);
    if (lane == 0) g_scores[r] = 1.f / (1.f + __expf(-(s + bp[0])));
}

// ---------------- top-1024 of 2048 via bitonic sort (1 block, 1024 threads) ----------------
__global__ void k_topk()
{
    __shared__ float sv[2048];
    __shared__ int   si[2048];
    int t = threadIdx.x;
    sv[t] = g_scores[t];           si[t] = t;
    sv[t + 1024] = g_scores[t + 1024]; si[t + 1024] = t + 1024;
    __syncthreads();
    for (int k = 2; k <= 2048; k <<= 1)
        for (int j = k >> 1; j > 0; j >>= 1) {
            int i = ((t & ~(j - 1)) << 1) | (t & (j - 1));
            int p = i | j;
            float a = sv[i], b = sv[p];
            int ia = si[i], ib = si[p];
            bool agtb = (a > b) || (a == b && ia < ib);
            bool up = ((i & k) == 0);
            if (up ^ agtb) { sv[i] = b; sv[p] = a; si[i] = ib; si[p] = ia; }
            __syncthreads();
        }
    g_vals[t] = sv[t];
    g_idx[t] = si[t];
}

// ---------------- gather pooled features, grid (KP*DD/256,1,2) ----------------
__global__ void k_gather()
{
    int z = blockIdx.z;
    int gi = blockIdx.x * 256 + threadIdx.x;
    int r = gi >> 7, c = gi & 127;
    g_newh[z][gi] = g_fg[z][(size_t)g_idx[r] * DD + c] * g_vals[r];
}

// ---------------- 2-hop pooled adjacency via bitmask AND ----------------
__global__ void k_sub()
{
    int gi = blockIdx.x * 256 + threadIdx.x;    // < KP*KP
    int i = gi >> 10, j = gi & 1023;
    const unsigned* bi = &g_bits[(size_t)g_idx[i] * NW];
    const unsigned* bj = &g_bits[(size_t)g_idx[j] * NW];
    float v = 0.f;
    for (int w = 0; w < NW; w++)
        if (bi[w] & bj[w]) { v = 1.f; break; }
    g_Anp[gi] = v;
}

__global__ void k_degp()
{
    int r = blockIdx.x, t = threadIdx.x;
    float s = 0.f;
    for (int j = t; j < KP; j += 256) s += g_Anp[(size_t)r * KP + j];
    for (int o = 16; o; o >>= 1) s += __shfl_xor_sync(~0u, s, o);
    __shared__ float ws[8];
    if ((t & 31) == 0) ws[t >> 5] = s;
    __syncthreads();
    if (t == 0) {
        float tot = 0;
        for (int i = 0; i < 8; i++) tot += ws[i];
        g_degp[r] = tot;
    }
}

__global__ void k_anp()
{
    int gi = blockIdx.x * 256 + threadIdx.x;
    int i = gi >> 10, j = gi & 1023;
    float v = g_Anp[gi];
    g_Anp[gi] = (v != 0.f) ? rsqrtf(g_degp[i] * g_degp[j]) : 0.f;
}

// ---------------- NCE: per-row loss term (lse - pos/T) ----------------
__global__ void k_nce_row(const float* __restrict__ Gm, int n, float* __restrict__ outv)
{
    int r = blockIdx.x;
    const float* row = Gm + (size_t)r * n;
    float s = 0.f;
    for (int j = threadIdx.x; j < n; j += 256)
        s += __expf(row[j] * INVT - INVT);
    for (int o = 16; o; o >>= 1) s += __shfl_xor_sync(~0u, s, o);
    __shared__ float ws[8];
    if ((threadIdx.x & 31) == 0) ws[threadIdx.x >> 5] = s;
    __syncthreads();
    if (threadIdx.x == 0) {
        float tot = 0;
        for (int i = 0; i < 8; i++) tot += ws[i];
        outv[r] = INVT + __logf(tot) - row[r] * INVT;
    }
}

// ---------------- NCE: per-column loss term ----------------
__global__ void k_nce_col(const float* __restrict__ Gm, int n, float* __restrict__ outv)
{
    int c = blockIdx.x * 256 + threadIdx.x;
    float s0 = 0.f, s1 = 0.f, s2 = 0.f, s3 = 0.f;
    for (int r = 0; r < n; r += 4) {
        s0 += __expf(Gm[(size_t)(r + 0) * n + c] * INVT - INVT);
        s1 += __expf(Gm[(size_t)(r + 1) * n + c] * INVT - INVT);
        s2 += __expf(Gm[(size_t)(r + 2) * n + c] * INVT - INVT);
        s3 += __expf(Gm[(size_t)(r + 3) * n + c] * INVT - INVT);
    }
    float s = (s0 + s1) + (s2 + s3);
    outv[c] = INVT + __logf(s) - Gm[(size_t)c * n + c] * INVT;
}

// ---------------- deterministic final reduction ----------------
__global__ void k_final(float* __restrict__ out)
{
    int t = threadIdx.x;
    float sg = 0.f, sp = 0.f;
    for (int i = t; i < NN; i += 256) sg += g_rl[i] + g_cl[i];
    for (int i = t; i < KP; i += 256) sp += g_rlp[i] + g_clp[i];
    for (int o = 16; o; o >>= 1) {
        sg += __shfl_xor_sync(~0u, sg, o);
        sp += __shfl_xor_sync(~0u, sp, o);
    }
    __shared__ float wg[8], wp[8];
    if ((t & 31) == 0) { wg[t >> 5] = sg; wp[t >> 5] = sp; }
    __syncthreads();
    if (t == 0) {
        float a = 0, b = 0;
        for (int i = 0; i < 8; i++) { a += wg[i]; b += wp[i]; }
        out[0] = a * (1.f / NN) + b * (1.f / KP);
    }
}

// ---------------- host ----------------
extern "C" void kernel_launch(void* const* d_in, const int* in_sizes, int n_in,
                              void* d_out, int out_size)
{
    (void)in_sizes; (void)n_in; (void)out_size;
    const float* fs    = (const float*)d_in[0];
    const float* ft    = (const float*)d_in[1];
    const float* We    = (const float*)d_in[2];
    const float* be    = (const float*)d_in[3];
    const float* Wg    = (const float*)d_in[4];
    const float* bg    = (const float*)d_in[5];
    const float* Wpool = (const float*)d_in[6];
    const float* bpool = (const float*)d_in[7];
    const float* Wgp   = (const float*)d_in[8];
    const float* bgp   = (const float*)d_in[9];

    void *p;
    cudaGetSymbolAddress(&p, g_fes);  float* FES = (float*)p;
    cudaGetSymbolAddress(&p, g_fet);  float* FET = (float*)p;
    cudaGetSymbolAddress(&p, g_G);    float* G   = (float*)p;
    cudaGetSymbolAddress(&p, g_An);   float* AN  = (float*)p;
    cudaGetSymbolAddress(&p, g_h1);   float* H1  = (float*)p;
    cudaGetSymbolAddress(&p, g_h2);   float* H2  = (float*)p;
    cudaGetSymbolAddress(&p, g_fg);   float* FG  = (float*)p;
    cudaGetSymbolAddress(&p, g_newh); float* NH  = (float*)p;
    cudaGetSymbolAddress(&p, g_h1p);  float* H1P = (float*)p;
    cudaGetSymbolAddress(&p, g_fp);   float* FP  = (float*)p;
    cudaGetSymbolAddress(&p, g_part); float* PART= (float*)p;
    cudaGetSymbolAddress(&p, g_Anp);  float* ANP = (float*)p;
    cudaGetSymbolAddress(&p, g_rl);   float* RL  = (float*)p;
    cudaGetSymbolAddress(&p, g_cl);   float* CL  = (float*)p;
    cudaGetSymbolAddress(&p, g_rlp);  float* RLP = (float*)p;
    cudaGetSymbolAddress(&p, g_clp);  float* CLP = (float*)p;

    const int ND = NN * DD;    // 262144
    const int KD = KP * DD;    // 131072

    // 1) embed both branches: f = l2norm(x @ W_embed + b)
    k_gemm_nn_sk<<<dim3(32, 4, 2), 256>>>(fs, ft, CD, We, We, PART, NN, 128, 0, 4);
    k_reduce<<<dim3(ND / 256, 1, 2), 256>>>(PART, 4, ND, FES, FET, be);
    k_l2norm<<<dim3(NN, 1, 2), 128>>>(FES, FET);

    // 2) adjacency from teacher gram
    k_gemm_nt<<<dim3(32, 32), 256>>>(FET, FET, G, NN);
    k_bits<<<dim3(NN * NW / 256), 256>>>();
    k_deg<<<dim3(NN / 256), 256>>>();
    k_an<<<dim3(NN * NN / 256), 256>>>();

    // 3) TAGConv k=2 on both branches: h1 = An@h0, h2 = An@h1
    k_gemm_nn_sk<<<dim3(32, 8, 2), 256>>>(AN, AN, NN, FET, FES, PART, NN, 256, 0, 8);
    k_reduce<<<dim3(ND / 256, 1, 2), 256>>>(PART, 8, ND, H1, H1 + ND, nullptr);
    k_gemm_nn_sk<<<dim3(32, 8, 2), 256>>>(AN, AN, NN, H1, H1 + ND, PART, NN, 256, 0, 8);
    k_reduce<<<dim3(ND / 256, 1, 2), 256>>>(PART, 8, ND, H2, H2 + ND, nullptr);
    // f_g = l2norm(h0@W0 + h1@W1 + h2@W2 + b)
    k_gemm_nn_sk<<<dim3(32, 1, 2), 256>>>(FET, FES, 128, Wg, Wg, PART, NN, 128, 0, 3);
    k_gemm_nn_sk<<<dim3(32, 1, 2), 256>>>(H1, H1 + ND, 128, Wg + 128 * 128, Wg + 128 * 128, PART, NN, 128, 1, 3);
    k_gemm_nn_sk<<<dim3(32, 1, 2), 256>>>(H2, H2 + ND, 128, Wg + 256 * 128, Wg + 256 * 128, PART, NN, 128, 2, 3);
    k_reduce<<<dim3(ND / 256, 1, 2), 256>>>(PART, 3, ND, FG, FG + ND, bg);
    k_l2norm<<<dim3(NN, 1, 2), 128>>>(FG, FG + ND);

    // 4) stage-1 NCE (G buffer reused; bits/deg already extracted)
    k_gemm_nt<<<dim3(32, 32), 256>>>(FG, FG + ND, G, NN);
    k_nce_row<<<NN, 256>>>(G, NN, RL);
    k_nce_col<<<NN / 256, 256>>>(G, NN, CL);

    // 5) pooling
    k_scores<<<NN / 8, 256>>>(Wpool, bpool);
    k_topk<<<1, 1024>>>();
    k_gather<<<dim3(KD / 256, 1, 2), 256>>>();
    k_sub<<<dim3(KP * KP / 256), 256>>>();
    k_degp<<<KP, 256>>>();
    k_anp<<<dim3(KP * KP / 256), 256>>>();

    // 6) pooled TAGConv k=1
    k_gemm_nn_sk<<<dim3(16, 8, 2), 256>>>(ANP, ANP, KP, NH, NH + KD, PART, KP, 128, 0, 8);
    k_reduce<<<dim3(KD / 256, 1, 2), 256>>>(PART, 8, KD, H1P, H1P + KD, nullptr);
    k_gemm_nn_sk<<<dim3(16, 1, 2), 256>>>(NH, NH + KD, 128, Wgp, Wgp, PART, KP, 128, 0, 2);
    k_gemm_nn_sk<<<dim3(16, 1, 2), 256>>>(H1P, H1P + KD, 128, Wgp + 128 * 128, Wgp + 128 * 128, PART, KP, 128, 1, 2);
    k_reduce<<<dim3(KD / 256, 1, 2), 256>>>(PART, 2, KD, FP, FP + KD, bgp);
    k_l2norm<<<dim3(KP, 1, 2), 128>>>(FP, FP + KD);

    // 7) pooled NCE
    k_gemm_nt<<<dim3(16, 16), 256>>>(FP, FP + KD, G, KP);
    k_nce_row<<<KP, 256>>>(G, KP, RLP);
    k_nce_col<<<KP / 256, 256>>>(G, KP, CLP);

    // 8) final scalar
    k_final<<<1, 256>>>((float*)d_out);
}

// round 2
// speedup vs baseline: 1.4131x; 1.4131x over previous
#include <cuda_runtime.h>

// ---------------- problem constants ----------------
#define NN 2048
#define CD 512
#define DD 128
#define KP 1024
#define NW 64            // 2048 bits / 32
#define NWP 32           // 1024 bits / 32
#define INVT 14.285714285714286f

// ---------------- device scratch ----------------
__device__ __align__(16) float g_fet[NN*DD];
__device__ __align__(16) float g_fes[NN*DD];
__device__ __align__(16) float g_G[NN*NN];
__device__ unsigned g_bits[NN*NW];
__device__ unsigned g_bitsp[KP*NWP];
__device__ float g_dinv[NN];
__device__ float g_dinvp[KP];
__device__ __align__(16) float g_h1[2][NN*DD];
__device__ __align__(16) float g_h2[2][NN*DD];
__device__ __align__(16) float g_hs[2][NN*DD];
__device__ __align__(16) float g_fg[2][NN*DD];
__device__ float g_scores[NN];
__device__ int   g_idx[KP];
__device__ float g_vals[KP];
__device__ __align__(16) float g_newh[2][KP*DD];
__device__ __align__(16) float g_nhs[2][KP*DD];
__device__ __align__(16) float g_h1p[2][KP*DD];
__device__ __align__(16) float g_fp[2][KP*DD];
__device__ __align__(16) float g_part[8][NN*DD];
__device__ float g_cpart[8][NN];
__device__ float g_rl[NN], g_cl[NN], g_rlp[KP], g_clp[KP];

// ---------------- tf32 helpers ----------------
__device__ __forceinline__ unsigned f2tf(float x) {
    unsigned r; asm("cvt.rna.tf32.f32 %0, %1;" : "=r"(r) : "f"(x)); return r;
}
__device__ __forceinline__ void mma8(float c[4], unsigned a0, unsigned a1, unsigned a2, unsigned a3,
                                     unsigned b0, unsigned b1) {
    asm volatile("mma.sync.aligned.m16n8k8.row.col.f32.tf32.tf32.f32 "
                 "{%0,%1,%2,%3}, {%4,%5,%6,%7}, {%8,%9}, {%0,%1,%2,%3};\n"
                 : "+f"(c[0]), "+f"(c[1]), "+f"(c[2]), "+f"(c[3])
                 : "r"(a0), "r"(a1), "r"(a2), "r"(a3), "r"(b0), "r"(b1));
}

// ---------------- MMA NN (always 3-pass split): C[M,128] = A[M,K]@B[K,128] -> partial slot ----------------
// grid (M/128, K/Kchunk, 2), block 256 (8 warps, 2x4, warp tile 64x32)
__global__ void __launch_bounds__(256) k_mma_nn(
    const float* __restrict__ A0, const float* __restrict__ A1, int lda,
    const float* __restrict__ B0, const float* __restrict__ B1,
    float* __restrict__ P, int M, int Kchunk, int sbase, int nsl)
{
    __shared__ unsigned sAh[16][132], sAl[16][132];
    __shared__ unsigned sBh[16][136], sBl[16][136];
    const float* A = blockIdx.z ? A1 : A0;
    const float* B = blockIdx.z ? B1 : B0;
    const int row0 = blockIdx.x * 128;
    const int k0 = blockIdx.y * Kchunk;
    float* Pout = P + (size_t)(blockIdx.z * nsl + sbase + blockIdx.y) * ((size_t)M * 128);
    const int tid = threadIdx.x, lane = tid & 31, w = tid >> 5;
    const int wm = w >> 2, wn = w & 3, grp = lane >> 2, qid = lane & 3;

    float acc[4][4][4];
#pragma unroll
    for (int t = 0; t < 4; t++)
#pragma unroll
        for (int u = 0; u < 4; u++)
#pragma unroll
            for (int v = 0; v < 4; v++) acc[t][u][v] = 0.f;

    const int ar = tid >> 1, akb = (tid & 1) * 8;
    const int bk = tid >> 4, bnb = (tid & 15) * 8;

    for (int kt = k0; kt < k0 + Kchunk; kt += 16) {
        const float* asrc = A + (size_t)(row0 + ar) * lda + kt + akb;
        float4 av0 = *(const float4*)asrc;
        float4 av1 = *(const float4*)(asrc + 4);
        float avv[8] = {av0.x, av0.y, av0.z, av0.w, av1.x, av1.y, av1.z, av1.w};
#pragma unroll
        for (int i = 0; i < 8; i++) {
            unsigned h = f2tf(avv[i]);
            sAh[akb + i][ar] = h;
            sAl[akb + i][ar] = f2tf(avv[i] - __uint_as_float(h));
        }
        const float* bsrc = B + (size_t)(kt + bk) * 128 + bnb;
        float4 bv0 = *(const float4*)bsrc;
        float4 bv1 = *(const float4*)(bsrc + 4);
        float bvv[8] = {bv0.x, bv0.y, bv0.z, bv0.w, bv1.x, bv1.y, bv1.z, bv1.w};
#pragma unroll
        for (int i = 0; i < 8; i++) {
            unsigned h = f2tf(bvv[i]);
            sBh[bk][bnb + i] = h;
            sBl[bk][bnb + i] = f2tf(bvv[i] - __uint_as_float(h));
        }
        __syncthreads();
#pragma unroll
        for (int kk = 0; kk < 16; kk += 8) {
            unsigned ah[4][4], bh[4][2];
#pragma unroll
            for (int t = 0; t < 4; t++) {
                int r = wm * 64 + t * 16 + grp;
                ah[t][0] = sAh[kk + qid][r];     ah[t][1] = sAh[kk + qid][r + 8];
                ah[t][2] = sAh[kk + qid + 4][r]; ah[t][3] = sAh[kk + qid + 4][r + 8];
            }
#pragma unroll
            for (int u = 0; u < 4; u++) {
                int c = wn * 32 + u * 8 + grp;
                bh[u][0] = sBh[kk + qid][c]; bh[u][1] = sBh[kk + qid + 4][c];
            }
#pragma unroll
            for (int t = 0; t < 4; t++)
#pragma unroll
                for (int u = 0; u < 4; u++)
                    mma8(acc[t][u], ah[t][0], ah[t][1], ah[t][2], ah[t][3], bh[u][0], bh[u][1]);
            {
                unsigned bl[4][2];
#pragma unroll
                for (int u = 0; u < 4; u++) {
                    int c = wn * 32 + u * 8 + grp;
                    bl[u][0] = sBl[kk + qid][c]; bl[u][1] = sBl[kk + qid + 4][c];
                }
#pragma unroll
                for (int t = 0; t < 4; t++)
#pragma unroll
                    for (int u = 0; u < 4; u++)
                        mma8(acc[t][u], ah[t][0], ah[t][1], ah[t][2], ah[t][3], bl[u][0], bl[u][1]);
            }
            {
                unsigned al[4][4];
#pragma unroll
                for (int t = 0; t < 4; t++) {
                    int r = wm * 64 + t * 16 + grp;
                    al[t][0] = sAl[kk + qid][r];     al[t][1] = sAl[kk + qid][r + 8];
                    al[t][2] = sAl[kk + qid + 4][r]; al[t][3] = sAl[kk + qid + 4][r + 8];
                }
#pragma unroll
                for (int t = 0; t < 4; t++)
#pragma unroll
                    for (int u = 0; u < 4; u++)
                        mma8(acc[t][u], al[t][0], al[t][1], al[t][2], al[t][3], bh[u][0], bh[u][1]);
            }
        }
        __syncthreads();
    }
#pragma unroll
    for (int t = 0; t < 4; t++) {
        int r = row0 + wm * 64 + t * 16 + grp;
#pragma unroll
        for (int u = 0; u < 4; u++) {
            int c = wn * 32 + u * 8 + qid * 2;
            *(float2*)(Pout + (size_t)r * 128 + c)       = make_float2(acc[t][u][0], acc[t][u][1]);
            *(float2*)(Pout + (size_t)(r + 8) * 128 + c) = make_float2(acc[t][u][2], acc[t][u][3]);
        }
    }
}

// ---------------- MMA NT gram: C[M,N] = F[M,128] @ Gm[N,128]^T ----------------
// grid (M/128, N/128); SPLIT=1 -> 3-pass fp32-accurate
template<int SPLIT>
__global__ void __launch_bounds__(256) k_mma_nt(
    const float* __restrict__ F, const float* __restrict__ Gm,
    float* __restrict__ C, int ldc)
{
    __shared__ unsigned sAh[16][132];
    __shared__ unsigned sAl[SPLIT ? 16 : 1][132];
    __shared__ unsigned sBh[16][136];
    __shared__ unsigned sBl[SPLIT ? 16 : 1][136];
    const int row0 = blockIdx.x * 128, col0 = blockIdx.y * 128;
    const int tid = threadIdx.x, lane = tid & 31, w = tid >> 5;
    const int wm = w >> 2, wn = w & 3, grp = lane >> 2, qid = lane & 3;

    float acc[4][4][4];
#pragma unroll
    for (int t = 0; t < 4; t++)
#pragma unroll
        for (int u = 0; u < 4; u++)
#pragma unroll
            for (int v = 0; v < 4; v++) acc[t][u][v] = 0.f;

    const int fr = tid >> 1, fkb = (tid & 1) * 8;

    for (int kt = 0; kt < 128; kt += 16) {
        const float* fsrc = F + (size_t)(row0 + fr) * 128 + kt + fkb;
        float4 v0 = *(const float4*)fsrc;
        float4 v1 = *(const float4*)(fsrc + 4);
        float vv[8] = {v0.x, v0.y, v0.z, v0.w, v1.x, v1.y, v1.z, v1.w};
#pragma unroll
        for (int i = 0; i < 8; i++) {
            unsigned h = f2tf(vv[i]);
            sAh[fkb + i][fr] = h;
            if (SPLIT) sAl[fkb + i][fr] = f2tf(vv[i] - __uint_as_float(h));
        }
        const float* gsrc = Gm + (size_t)(col0 + fr) * 128 + kt + fkb;
        float4 u0 = *(const float4*)gsrc;
        float4 u1 = *(const float4*)(gsrc + 4);
        float uu[8] = {u0.x, u0.y, u0.z, u0.w, u1.x, u1.y, u1.z, u1.w};
#pragma unroll
        for (int i = 0; i < 8; i++) {
            unsigned h = f2tf(uu[i]);
            sBh[fkb + i][fr] = h;
            if (SPLIT) sBl[fkb + i][fr] = f2tf(uu[i] - __uint_as_float(h));
        }
        __syncthreads();
#pragma unroll
        for (int kk = 0; kk < 16; kk += 8) {
            unsigned ah[4][4], bh[4][2];
#pragma unroll
            for (int t = 0; t < 4; t++) {
                int r = wm * 64 + t * 16 + grp;
                ah[t][0] = sAh[kk + qid][r];     ah[t][1] = sAh[kk + qid][r + 8];
                ah[t][2] = sAh[kk + qid + 4][r]; ah[t][3] = sAh[kk + qid + 4][r + 8];
            }
#pragma unroll
            for (int u = 0; u < 4; u++) {
                int c = wn * 32 + u * 8 + grp;
                bh[u][0] = sBh[kk + qid][c]; bh[u][1] = sBh[kk + qid + 4][c];
            }
#pragma unroll
            for (int t = 0; t < 4; t++)
#pragma unroll
                for (int u = 0; u < 4; u++)
                    mma8(acc[t][u], ah[t][0], ah[t][1], ah[t][2], ah[t][3], bh[u][0], bh[u][1]);
            if (SPLIT) {
                unsigned bl[4][2];
#pragma unroll
                for (int u = 0; u < 4; u++) {
                    int c = wn * 32 + u * 8 + grp;
                    bl[u][0] = sBl[kk + qid][c]; bl[u][1] = sBl[kk + qid + 4][c];
                }
#pragma unroll
                for (int t = 0; t < 4; t++)
#pragma unroll
                    for (int u = 0; u < 4; u++)
                        mma8(acc[t][u], ah[t][0], ah[t][1], ah[t][2], ah[t][3], bl[u][0], bl[u][1]);
                unsigned al[4][4];
#pragma unroll
                for (int t = 0; t < 4; t++) {
                    int r = wm * 64 + t * 16 + grp;
                    al[t][0] = sAl[kk + qid][r];     al[t][1] = sAl[kk + qid][r + 8];
                    al[t][2] = sAl[kk + qid + 4][r]; al[t][3] = sAl[kk + qid + 4][r + 8];
                }
#pragma unroll
                for (int t = 0; t < 4; t++)
#pragma unroll
                    for (int u = 0; u < 4; u++)
                        mma8(acc[t][u], al[t][0], al[t][1], al[t][2], al[t][3], bh[u][0], bh[u][1]);
            }
        }
        __syncthreads();
    }
#pragma unroll
    for (int t = 0; t < 4; t++) {
        int r = row0 + wm * 64 + t * 16 + grp;
#pragma unroll
        for (int u = 0; u < 4; u++) {
            int c = col0 + wn * 32 + u * 8 + qid * 2;
            *(float2*)(C + (size_t)r * ldc + c)       = make_float2(acc[t][u][0], acc[t][u][1]);
            *(float2*)(C + (size_t)(r + 8) * ldc + c) = make_float2(acc[t][u][2], acc[t][u][3]);
        }
    }
}

// ---------------- MMA binary-A: Y[M,128] = A_bits @ H[K,128] (exact A, tf32 H) ----------------
// grid (M/128, K/Kchunk, 2)
__global__ void __launch_bounds__(256) k_mma_bin(
    const unsigned* __restrict__ bits, int nw,
    const float* __restrict__ H0, const float* __restrict__ H1,
    float* __restrict__ P, int M, int Kchunk, int nsl)
{
    __shared__ unsigned sA[32][132];
    __shared__ unsigned sB[32][136];
    const float* H = blockIdx.z ? H1 : H0;
    const int row0 = blockIdx.x * 128;
    const int k0 = blockIdx.y * Kchunk;
    float* Pout = P + (size_t)(blockIdx.z * nsl + blockIdx.y) * ((size_t)M * 128);
    const int tid = threadIdx.x, lane = tid & 31, w = tid >> 5;
    const int wm = w >> 2, wn = w & 3, grp = lane >> 2, qid = lane & 3;

    float acc[4][4][4];
#pragma unroll
    for (int t = 0; t < 4; t++)
#pragma unroll
        for (int u = 0; u < 4; u++)
#pragma unroll
            for (int v = 0; v < 4; v++) acc[t][u][v] = 0.f;

    const int br = tid & 127, bkh = tid >> 7;
    const int hk = tid >> 3, hn = (tid & 7) * 16;

    for (int kt = k0; kt < k0 + Kchunk; kt += 32) {
        unsigned word = bits[(size_t)(row0 + br) * nw + (kt >> 5)];
#pragma unroll
        for (int i = 0; i < 16; i++) {
            int k = bkh * 16 + i;
            sA[k][br] = ((word >> k) & 1u) ? 0x3f800000u : 0u;
        }
        const float* hsrc = H + (size_t)(kt + hk) * 128 + hn;
#pragma unroll
        for (int j = 0; j < 4; j++) {
            float4 v = *(const float4*)(hsrc + j * 4);
            sB[hk][hn + j * 4 + 0] = f2tf(v.x);
            sB[hk][hn + j * 4 + 1] = f2tf(v.y);
            sB[hk][hn + j * 4 + 2] = f2tf(v.z);
            sB[hk][hn + j * 4 + 3] = f2tf(v.w);
        }
        __syncthreads();
#pragma unroll
        for (int kk = 0; kk < 32; kk += 8) {
            unsigned ah[4][4], bh[4][2];
#pragma unroll
            for (int t = 0; t < 4; t++) {
                int r = wm * 64 + t * 16 + grp;
                ah[t][0] = sA[kk + qid][r];     ah[t][1] = sA[kk + qid][r + 8];
                ah[t][2] = sA[kk + qid + 4][r]; ah[t][3] = sA[kk + qid + 4][r + 8];
            }
#pragma unroll
            for (int u = 0; u < 4; u++) {
                int c = wn * 32 + u * 8 + grp;
                bh[u][0] = sB[kk + qid][c]; bh[u][1] = sB[kk + qid + 4][c];
            }
#pragma unroll
            for (int t = 0; t < 4; t++)
#pragma unroll
                for (int u = 0; u < 4; u++)
                    mma8(acc[t][u], ah[t][0], ah[t][1], ah[t][2], ah[t][3], bh[u][0], bh[u][1]);
        }
        __syncthreads();
    }
#pragma unroll
    for (int t = 0; t < 4; t++) {
        int r = row0 + wm * 64 + t * 16 + grp;
#pragma unroll
        for (int u = 0; u < 4; u++) {
            int c = wn * 32 + u * 8 + qid * 2;
            *(float2*)(Pout + (size_t)r * 128 + c)       = make_float2(acc[t][u][0], acc[t][u][1]);
            *(float2*)(Pout + (size_t)(r + 8) * 128 + c) = make_float2(acc[t][u][2], acc[t][u][3]);
        }
    }
}

// ---------------- reduce partials (+bias) ----------------
__global__ void k_reduce(const float* __restrict__ P, int nsl, int cnt,
                         float* __restrict__ O0, float* __restrict__ O1,
                         const float* __restrict__ bias)
{
    float* O = blockIdx.z ? O1 : O0;
    const float* Pz = P + (size_t)blockIdx.z * nsl * cnt;
    int i = blockIdx.x * 256 + threadIdx.x;
    float s = bias ? bias[i & 127] : 0.f;
    for (int k = 0; k < nsl; k++) s += Pz[(size_t)k * cnt + i];
    O[i] = s;
}

// reduce with row scale: O = dinv*sum, optional S = dinv^2*sum
__global__ void k_reduce_s(const float* __restrict__ P, int nsl, int cnt,
                           float* __restrict__ O0, float* __restrict__ O1,
                           float* __restrict__ S0, float* __restrict__ S1,
                           const float* __restrict__ dinv)
{
    float* O = blockIdx.z ? O1 : O0;
    float* S = blockIdx.z ? S1 : S0;
    const float* Pz = P + (size_t)blockIdx.z * nsl * cnt;
    int i = blockIdx.x * 256 + threadIdx.x;
    float s = 0.f;
    for (int k = 0; k < nsl; k++) s += Pz[(size_t)k * cnt + i];
    float d = dinv[i >> 7];
    O[i] = d * s;
    if (S) S[i] = d * d * s;
}

// row scale: O = I * dinv[row]
__global__ void k_scale(const float* __restrict__ I0, const float* __restrict__ I1,
                        float* __restrict__ O0, float* __restrict__ O1,
                        const float* __restrict__ dinv)
{
    const float* I = blockIdx.z ? I1 : I0;
    float* O = blockIdx.z ? O1 : O0;
    int i = blockIdx.x * 256 + threadIdx.x;
    O[i] = I[i] * dinv[i >> 7];
}

// ---------------- l2 normalize rows ----------------
__global__ void k_l2norm(float* __restrict__ X0, float* __restrict__ X1)
{
    float* X = blockIdx.z ? X1 : X0;
    int r = blockIdx.x, t = threadIdx.x;
    float v = X[(size_t)r * 128 + t];
    float s = v * v;
    for (int o = 16; o; o >>= 1) s += __shfl_xor_sync(~0u, s, o);
    __shared__ float ws[4];
    if ((t & 31) == 0) ws[t >> 5] = s;
    __syncthreads();
    float tot = ws[0] + ws[1] + ws[2] + ws[3];
    X[(size_t)r * 128 + t] = v * rsqrtf(tot);
}

// ---------------- adjacency bits / dinv ----------------
__global__ void k_bits()
{
    int t = blockIdx.x * 256 + threadIdx.x;
    int i = t >> 6, w = t & 63;
    const float* row = g_G + (size_t)i * NN + w * 32;
    unsigned m = 0;
#pragma unroll
    for (int b = 0; b < 32; b++)
        if (row[b] > 0.f) m |= 1u << b;
    if (w == (i >> 5)) m |= 1u << (i & 31);
    g_bits[t] = m;
}

__global__ void k_dinv()
{
    int i = blockIdx.x * 256 + threadIdx.x;
    int s = 0;
#pragma unroll
    for (int w = 0; w < NW; w++) s += __popc(g_bits[i * NW + w]);
    g_dinv[i] = rsqrtf((float)s);
}

__global__ void k_dinvp()
{
    int i = blockIdx.x * 256 + threadIdx.x;
    int s = 0;
#pragma unroll
    for (int w = 0; w < NWP; w++) s += __popc(g_bitsp[i * NWP + w]);
    g_dinvp[i] = rsqrtf((float)s);
}

// ---------------- pooling scores ----------------
__global__ void k_scores(const float* __restrict__ Wp, const float* __restrict__ bp)
{
    int warp = threadIdx.x >> 5, lane = threadIdx.x & 31;
    int r = blockIdx.x * 8 + warp;
    const float* x = g_fg[0] + (size_t)r * DD;
    float s = x[lane] * Wp[lane] + x[lane + 32] * Wp[lane + 32]
            + x[lane + 64] * Wp[lane + 64] + x[lane + 96] * Wp[lane + 96];
    for (int o = 16; o; o >>= 1) s += __shfl_xor_sync(~0u, s, o);
    if (lane == 0) g_scores[r] = 1.f / (1.f + __expf(-(s + bp[0])));
}

// ---------------- top-1024 bitonic ----------------
__global__ void k_topk()
{
    __shared__ float sv[2048];
    __shared__ int   si[2048];
    int t = threadIdx.x;
    sv[t] = g_scores[t];               si[t] = t;
    sv[t + 1024] = g_scores[t + 1024]; si[t + 1024] = t + 1024;
    __syncthreads();
    for (int k = 2; k <= 2048; k <<= 1)
        for (int j = k >> 1; j > 0; j >>= 1) {
            int i = ((t & ~(j - 1)) << 1) | (t & (j - 1));
            int p = i | j;
            float a = sv[i], b = sv[p];
            int ia = si[i], ib = si[p];
            bool agtb = (a > b) || (a == b && ia < ib);
            bool up = ((i & k) == 0);
            if (up ^ agtb) { sv[i] = b; sv[p] = a; si[i] = ib; si[p] = ia; }
            __syncthreads();
        }
    g_vals[t] = sv[t];
    g_idx[t] = si[t];
}

// ---------------- gather pooled features ----------------
__global__ void k_gather()
{
    int z = blockIdx.z;
    int gi = blockIdx.x * 256 + threadIdx.x;
    int r = gi >> 7;
    g_newh[z][gi] = g_fg[z][(size_t)g_idx[r] * DD + (gi & 127)] * g_vals[r];
}

// ---------------- pooled 2-hop adjacency bitmask ----------------
__global__ void k_subbits()
{
    int gi = blockIdx.x * 256 + threadIdx.x;
    int i = gi >> 10, j = gi & 1023;
    const unsigned* bi = g_bits + (size_t)g_idx[i] * NW;
    const unsigned* bj = g_bits + (size_t)g_idx[j] * NW;
    bool c = false;
    for (int w = 0; w < NW && !c; w++) c = (bi[w] & bj[w]) != 0u;
    unsigned word = __ballot_sync(~0u, c);
    if ((j & 31) == 0) g_bitsp[i * NWP + (j >> 5)] = word;
}

// ---------------- NCE ----------------
__global__ void k_nce_row(const float* __restrict__ Gm, int n, float* __restrict__ outv)
{
    int r = blockIdx.x;
    const float* row = Gm + (size_t)r * n;
    float s = 0.f;
    for (int j = threadIdx.x; j < n; j += 256)
        s += __expf(row[j] * INVT - INVT);
    for (int o = 16; o; o >>= 1) s += __shfl_xor_sync(~0u, s, o);
    __shared__ float ws[8];
    if ((threadIdx.x & 31) == 0) ws[threadIdx.x >> 5] = s;
    __syncthreads();
    if (threadIdx.x == 0) {
        float tot = 0;
        for (int i = 0; i < 8; i++) tot += ws[i];
        outv[r] = INVT + __logf(tot) - row[r] * INVT;
    }
}

__global__ void k_nce_colp(const float* __restrict__ Gm, int n)
{
    int c = blockIdx.x * 256 + threadIdx.x;
    int L = n >> 3;
    int r0 = blockIdx.y * L;
    float s0 = 0.f, s1 = 0.f, s2 = 0.f, s3 = 0.f;
    for (int r = r0; r < r0 + L; r += 4) {
        s0 += __expf(Gm[(size_t)(r + 0) * n + c] * INVT - INVT);
        s1 += __expf(Gm[(size_t)(r + 1) * n + c] * INVT - INVT);
        s2 += __expf(Gm[(size_t)(r + 2) * n + c] * INVT - INVT);
        s3 += __expf(Gm[(size_t)(r + 3) * n + c] * INVT - INVT);
    }
    g_cpart[blockIdx.y][c] = (s0 + s1) + (s2 + s3);
}

__global__ void k_nce_colf(const float* __restrict__ Gm, int n, float* __restrict__ outv)
{
    int c = blockIdx.x * 256 + threadIdx.x;
    float s = 0.f;
#pragma unroll
    for (int k = 0; k < 8; k++) s += g_cpart[k][c];
    outv[c] = INVT + __logf(s) - Gm[(size_t)c * n + c] * INVT;
}

// ---------------- final reduction ----------------
__global__ void k_final(float* __restrict__ out)
{
    int t = threadIdx.x;
    float sg = 0.f, sp = 0.f;
    for (int i = t; i < NN; i += 256) sg += g_rl[i] + g_cl[i];
    for (int i = t; i < KP; i += 256) sp += g_rlp[i] + g_clp[i];
    for (int o = 16; o; o >>= 1) {
        sg += __shfl_xor_sync(~0u, sg, o);
        sp += __shfl_xor_sync(~0u, sp, o);
    }
    __shared__ float wg[8], wp[8];
    if ((t & 31) == 0) { wg[t >> 5] = sg; wp[t >> 5] = sp; }
    __syncthreads();
    if (t == 0) {
        float a = 0, b = 0;
        for (int i = 0; i < 8; i++) { a += wg[i]; b += wp[i]; }
        out[0] = a * (1.f / NN) + b * (1.f / KP);
    }
}

// ---------------- host ----------------
extern "C" void kernel_launch(void* const* d_in, const int* in_sizes, int n_in,
                              void* d_out, int out_size)
{
    (void)in_sizes; (void)n_in; (void)out_size;
    const float* fs    = (const float*)d_in[0];
    const float* ft    = (const float*)d_in[1];
    const float* We    = (const float*)d_in[2];
    const float* be    = (const float*)d_in[3];
    const float* Wg    = (const float*)d_in[4];
    const float* bg    = (const float*)d_in[5];
    const float* Wpool = (const float*)d_in[6];
    const float* bpool = (const float*)d_in[7];
    const float* Wgp   = (const float*)d_in[8];
    const float* bgp   = (const float*)d_in[9];

    void* p;
    cudaGetSymbolAddress(&p, g_fes);   float* FES  = (float*)p;
    cudaGetSymbolAddress(&p, g_fet);   float* FET  = (float*)p;
    cudaGetSymbolAddress(&p, g_G);     float* G    = (float*)p;
    cudaGetSymbolAddress(&p, g_bits);  unsigned* BITS  = (unsigned*)p;
    cudaGetSymbolAddress(&p, g_bitsp); unsigned* BITSP = (unsigned*)p;
    cudaGetSymbolAddress(&p, g_dinv);  float* DINV  = (float*)p;
    cudaGetSymbolAddress(&p, g_dinvp); float* DINVP = (float*)p;
    cudaGetSymbolAddress(&p, g_h1);    float* H1   = (float*)p;
    cudaGetSymbolAddress(&p, g_h2);    float* H2   = (float*)p;
    cudaGetSymbolAddress(&p, g_hs);    float* HS   = (float*)p;
    cudaGetSymbolAddress(&p, g_fg);    float* FG   = (float*)p;
    cudaGetSymbolAddress(&p, g_newh);  float* NH   = (float*)p;
    cudaGetSymbolAddress(&p, g_nhs);   float* NHS  = (float*)p;
    cudaGetSymbolAddress(&p, g_h1p);   float* H1P  = (float*)p;
    cudaGetSymbolAddress(&p, g_fp);    float* FP   = (float*)p;
    cudaGetSymbolAddress(&p, g_part);  float* PART = (float*)p;
    cudaGetSymbolAddress(&p, g_rl);    float* RL   = (float*)p;
    cudaGetSymbolAddress(&p, g_cl);    float* CL   = (float*)p;
    cudaGetSymbolAddress(&p, g_rlp);   float* RLP  = (float*)p;
    cudaGetSymbolAddress(&p, g_clp);   float* CLP  = (float*)p;

    const int ND = NN * DD;
    const int KD = KP * DD;

    // 1) embed (split tf32): f = l2norm(x @ We + be)
    k_mma_nn<<<dim3(16, 4, 2), 256>>>(fs, ft, CD, We, We, PART, NN, 128, 0, 4);
    k_reduce<<<dim3(ND / 256, 1, 2), 256>>>(PART, 4, ND, FES, FET, be);
    k_l2norm<<<dim3(NN, 1, 2), 128>>>(FES, FET);

    // 2) adjacency gram (split tf32 = fp32-accurate threshold)
    k_mma_nt<1><<<dim3(16, 16), 256>>>(FET, FET, G, NN);
    k_bits<<<NN * NW / 256, 256>>>();
    k_dinv<<<NN / 256, 256>>>();

    // 3) TAGConv k=2 via exact binary MMA
    k_scale<<<dim3(ND / 256, 1, 2), 256>>>(FET, FES, HS, HS + ND, DINV);
    k_mma_bin<<<dim3(16, 4, 2), 256>>>(BITS, NW, HS, HS + ND, PART, NN, 512, 4);
    k_reduce_s<<<dim3(ND / 256, 1, 2), 256>>>(PART, 4, ND, H1, H1 + ND, HS, HS + ND, DINV);
    k_mma_bin<<<dim3(16, 4, 2), 256>>>(BITS, NW, HS, HS + ND, PART, NN, 512, 4);
    k_reduce_s<<<dim3(ND / 256, 1, 2), 256>>>(PART, 4, ND, H2, H2 + ND, (float*)0, (float*)0, DINV);

    // 4) concat @ Wg (split tf32)
    k_mma_nn<<<dim3(16, 1, 2), 256>>>(FET, FES, DD, Wg, Wg, PART, NN, 128, 0, 3);
    k_mma_nn<<<dim3(16, 1, 2), 256>>>(H1, H1 + ND, DD, Wg + 128 * 128, Wg + 128 * 128, PART, NN, 128, 1, 3);
    k_mma_nn<<<dim3(16, 1, 2), 256>>>(H2, H2 + ND, DD, Wg + 256 * 128, Wg + 256 * 128, PART, NN, 128, 2, 3);
    k_reduce<<<dim3(ND / 256, 1, 2), 256>>>(PART, 3, ND, FG, FG + ND, bg);
    k_l2norm<<<dim3(NN, 1, 2), 128>>>(FG, FG + ND);

    // 5) stage-1 NCE
    k_mma_nt<0><<<dim3(16, 16), 256>>>(FG, FG + ND, G, NN);
    k_nce_row<<<NN, 256>>>(G, NN, RL);
    k_nce_colp<<<dim3(NN / 256, 8), 256>>>(G, NN);
    k_nce_colf<<<NN / 256, 256>>>(G, NN, CL);

    // 6) pooling
    k_scores<<<NN / 8, 256>>>(Wpool, bpool);
    k_topk<<<1, 1024>>>();
    k_gather<<<dim3(KD / 256, 1, 2), 256>>>();
    k_subbits<<<KP * KP / 256, 256>>>();
    k_dinvp<<<KP / 256, 256>>>();

    // 7) pooled TAGConv k=1 (binary MMA)
    k_scale<<<dim3(KD / 256, 1, 2), 256>>>(NH, NH + KD, NHS, NHS + KD, DINVP);
    k_mma_bin<<<dim3(8, 2, 2), 256>>>(BITSP, NWP, NHS, NHS + KD, PART, KP, 512, 2);
    k_reduce_s<<<dim3(KD / 256, 1, 2), 256>>>(PART, 2, KD, H1P, H1P + KD, (float*)0, (float*)0, DINVP);
    k_mma_nn<<<dim3(8, 1, 2), 256>>>(NH, NH + KD, DD, Wgp, Wgp, PART, KP, 128, 0, 2);
    k_mma_nn<<<dim3(8, 1, 2), 256>>>(H1P, H1P + KD, DD, Wgp + 128 * 128, Wgp + 128 * 128, PART, KP, 128, 1, 2);
    k_reduce<<<dim3(KD / 256, 1, 2), 256>>>(PART, 2, KD, FP, FP + KD, bgp);
    k_l2norm<<<dim3(KP, 1, 2), 128>>>(FP, FP + KD);

    // 8) pooled NCE
    k_mma_nt<0><<<dim3(8, 8), 256>>>(FP, FP + KD, G, KP);
    k_nce_row<<<KP, 256>>>(G, KP, RLP);
    k_nce_colp<<<dim3(KP / 256, 8), 256>>>(G, KP);
    k_nce_colf<<<KP / 256, 256>>>(G, KP, CLP);

    // 9) final scalar
    k_final<<<1, 256>>>((float*)d_out);
}

// round 3
// speedup vs baseline: 2.1157x; 1.4972x over previous
#include <cuda_runtime.h>

// ---------------- problem constants ----------------
#define NN 2048
#define CD 512
#define DD 128
#define KP 1024
#define NW 64            // 2048 bits / 32
#define NWP 32           // 1024 bits / 32
#define INVT 14.285714285714286f

// ---------------- device scratch ----------------
__device__ __align__(16) float g_fet[NN*DD];
__device__ __align__(16) float g_fes[NN*DD];
__device__ unsigned g_bits[NN*NW];
__device__ unsigned g_bitsp[KP*NWP];
__device__ float g_dinv[NN];
__device__ float g_dinvp[KP];
__device__ __align__(16) float g_hs[2][NN*DD];     // D^-1/2-scaled features
__device__ __align__(16) float g_nhs[2][KP*DD];
__device__ __align__(16) float g_fg[2][NN*DD];     // [0]=teacher,[1]=student
__device__ __align__(16) float g_fp[2][KP*DD];
__device__ __align__(16) float g_cat[2][NN*384];   // concat [h0|h1|h2]
__device__ __align__(16) float g_catp[2][KP*256];  // pooled concat
__device__ float g_scores[NN];
__device__ int   g_idx[KP];
__device__ float g_vals[KP];
__device__ __align__(16) float g_part[8][NN*DD];   // split-K partials
__device__ float g_rp[16*NN], g_cp[16*NN], g_diag[NN];
__device__ float g_rl[NN], g_cl[NN], g_rlp[KP], g_clp[KP];

// ---------------- tf32 helpers ----------------
__device__ __forceinline__ unsigned f2tf(float x) {
    unsigned r; asm("cvt.rna.tf32.f32 %0, %1;" : "=r"(r) : "f"(x)); return r;
}
__device__ __forceinline__ void mma8(float c[4], unsigned a0, unsigned a1, unsigned a2, unsigned a3,
                                     unsigned b0, unsigned b1) {
    asm volatile("mma.sync.aligned.m16n8k8.row.col.f32.tf32.tf32.f32 "
                 "{%0,%1,%2,%3}, {%4,%5,%6,%7}, {%8,%9}, {%0,%1,%2,%3};\n"
                 : "+f"(c[0]), "+f"(c[1]), "+f"(c[2]), "+f"(c[3])
                 : "r"(a0), "r"(a1), "r"(a2), "r"(a3), "r"(b0), "r"(b1));
}

// ---- MMA over one 16-K stage, 3-pass tf32 split (fp32-accurate) ----
__device__ __forceinline__ void mma_tile_split(
    float acc[4][4][4], const float (*__restrict__ sa)[132], const float (*__restrict__ sb)[136],
    int wm, int wn, int grp, int qid)
{
#pragma unroll
    for (int kk = 0; kk < 16; kk += 8) {
        float araw[4][4], braw[4][2];
        unsigned ah[4][4], bh[4][2];
#pragma unroll
        for (int t = 0; t < 4; t++) {
            int r = wm*64 + t*16 + grp;
            araw[t][0] = sa[kk+qid][r];   araw[t][1] = sa[kk+qid][r+8];
            araw[t][2] = sa[kk+qid+4][r]; araw[t][3] = sa[kk+qid+4][r+8];
#pragma unroll
            for (int j = 0; j < 4; j++) ah[t][j] = f2tf(araw[t][j]);
        }
#pragma unroll
        for (int u = 0; u < 4; u++) {
            int c = wn*32 + u*8 + grp;
            braw[u][0] = sb[kk+qid][c]; braw[u][1] = sb[kk+qid+4][c];
            bh[u][0] = f2tf(braw[u][0]); bh[u][1] = f2tf(braw[u][1]);
        }
#pragma unroll
        for (int t = 0; t < 4; t++)
#pragma unroll
            for (int u = 0; u < 4; u++)
                mma8(acc[t][u], ah[t][0],ah[t][1],ah[t][2],ah[t][3], bh[u][0],bh[u][1]);
        {
            unsigned bl[4][2];
#pragma unroll
            for (int u = 0; u < 4; u++) {
                bl[u][0] = f2tf(braw[u][0] - __uint_as_float(bh[u][0]));
                bl[u][1] = f2tf(braw[u][1] - __uint_as_float(bh[u][1]));
            }
#pragma unroll
            for (int t = 0; t < 4; t++)
#pragma unroll
                for (int u = 0; u < 4; u++)
                    mma8(acc[t][u], ah[t][0],ah[t][1],ah[t][2],ah[t][3], bl[u][0],bl[u][1]);
        }
        {
            unsigned al[4][4];
#pragma unroll
            for (int t = 0; t < 4; t++)
#pragma unroll
                for (int j = 0; j < 4; j++)
                    al[t][j] = f2tf(araw[t][j] - __uint_as_float(ah[t][j]));
#pragma unroll
            for (int t = 0; t < 4; t++)
#pragma unroll
                for (int u = 0; u < 4; u++)
                    mma8(acc[t][u], al[t][0],al[t][1],al[t][2],al[t][3], bh[u][0],bh[u][1]);
        }
    }
}

// ---- MMA over one 16-K stage, single-pass tf32 ----
__device__ __forceinline__ void mma_tile_1p(
    float acc[4][4][4], const float (*__restrict__ sa)[132], const float (*__restrict__ sb)[136],
    int wm, int wn, int grp, int qid)
{
#pragma unroll
    for (int kk = 0; kk < 16; kk += 8) {
        unsigned ah[4][4], bh[4][2];
#pragma unroll
        for (int t = 0; t < 4; t++) {
            int r = wm*64 + t*16 + grp;
            ah[t][0] = f2tf(sa[kk+qid][r]);   ah[t][1] = f2tf(sa[kk+qid][r+8]);
            ah[t][2] = f2tf(sa[kk+qid+4][r]); ah[t][3] = f2tf(sa[kk+qid+4][r+8]);
        }
#pragma unroll
        for (int u = 0; u < 4; u++) {
            int c = wn*32 + u*8 + grp;
            bh[u][0] = f2tf(sb[kk+qid][c]); bh[u][1] = f2tf(sb[kk+qid+4][c]);
        }
#pragma unroll
        for (int t = 0; t < 4; t++)
#pragma unroll
            for (int u = 0; u < 4; u++)
                mma8(acc[t][u], ah[t][0],ah[t][1],ah[t][2],ah[t][3], bh[u][0],bh[u][1]);
    }
}

// ---------------- NN GEMM, split-tf32, double-buffered: C[M,128]=A[M,K]@B[K,128] ----------------
// grid (M/128, K/Kchunk, 2), block 256
__global__ void __launch_bounds__(256) k_mma_nn(
    const float* __restrict__ A0, const float* __restrict__ A1, int lda,
    const float* __restrict__ B,
    float* __restrict__ P, int M, int Kchunk, int nsl)
{
    __shared__ float sA[2][16][132];
    __shared__ float sB[2][16][136];
    const float* A = blockIdx.z ? A1 : A0;
    const int row0 = blockIdx.x * 128;
    const int k0 = blockIdx.y * Kchunk;
    float* Pout = P + (size_t)(blockIdx.z * nsl + blockIdx.y) * ((size_t)M * 128);
    const int tid = threadIdx.x, lane = tid & 31, w = tid >> 5;
    const int wm = w >> 2, wn = w & 3, grp = lane >> 2, qid = lane & 3;

    float acc[4][4][4];
#pragma unroll
    for (int t = 0; t < 4; t++)
#pragma unroll
        for (int u = 0; u < 4; u++)
#pragma unroll
            for (int v = 0; v < 4; v++) acc[t][u][v] = 0.f;

    const int ar = tid >> 1, akb = (tid & 1) * 8;
    const int bk = tid >> 4, bnb = (tid & 15) * 8;
    float ra[8], rb[8];

    {
        const float* as_ = A + (size_t)(row0 + ar) * lda + k0 + akb;
        float4 a0 = *(const float4*)as_, a1 = *(const float4*)(as_ + 4);
        ra[0]=a0.x; ra[1]=a0.y; ra[2]=a0.z; ra[3]=a0.w; ra[4]=a1.x; ra[5]=a1.y; ra[6]=a1.z; ra[7]=a1.w;
        const float* bs_ = B + (size_t)(k0 + bk) * 128 + bnb;
        float4 b0 = *(const float4*)bs_, b1 = *(const float4*)(bs_ + 4);
        rb[0]=b0.x; rb[1]=b0.y; rb[2]=b0.z; rb[3]=b0.w; rb[4]=b1.x; rb[5]=b1.y; rb[6]=b1.z; rb[7]=b1.w;
    }
    const int nIter = Kchunk / 16;
#pragma unroll
    for (int i = 0; i < 8; i++) sA[0][akb + i][ar] = ra[i];
#pragma unroll
    for (int i = 0; i < 8; i++) sB[0][bk][bnb + i] = rb[i];
    __syncthreads();

    for (int it = 0; it < nIter; ++it) {
        const int cur = it & 1;
        const bool more = (it + 1) < nIter;
        if (more) {
            int kt = k0 + (it + 1) * 16;
            const float* as_ = A + (size_t)(row0 + ar) * lda + kt + akb;
            float4 a0 = *(const float4*)as_, a1 = *(const float4*)(as_ + 4);
            ra[0]=a0.x; ra[1]=a0.y; ra[2]=a0.z; ra[3]=a0.w; ra[4]=a1.x; ra[5]=a1.y; ra[6]=a1.z; ra[7]=a1.w;
            const float* bs_ = B + (size_t)(kt + bk) * 128 + bnb;
            float4 b0 = *(const float4*)bs_, b1 = *(const float4*)(bs_ + 4);
            rb[0]=b0.x; rb[1]=b0.y; rb[2]=b0.z; rb[3]=b0.w; rb[4]=b1.x; rb[5]=b1.y; rb[6]=b1.z; rb[7]=b1.w;
        }
        mma_tile_split(acc, sA[cur], sB[cur], wm, wn, grp, qid);
        if (more) {
#pragma unroll
            for (int i = 0; i < 8; i++) sA[cur ^ 1][akb + i][ar] = ra[i];
#pragma unroll
            for (int i = 0; i < 8; i++) sB[cur ^ 1][bk][bnb + i] = rb[i];
        }
        __syncthreads();
    }
#pragma unroll
    for (int t = 0; t < 4; t++) {
        int r = row0 + wm * 64 + t * 16 + grp;
#pragma unroll
        for (int u = 0; u < 4; u++) {
            int c = wn * 32 + u * 8 + qid * 2;
            *(float2*)(Pout + (size_t)r * 128 + c)       = make_float2(acc[t][u][0], acc[t][u][1]);
            *(float2*)(Pout + (size_t)(r + 8) * 128 + c) = make_float2(acc[t][u][2], acc[t][u][3]);
        }
    }
}

// ---------------- adjacency gram: bits = (F F^T > 0), fused epilogue, no G ----------------
// grid (16,16), block 256
__global__ void __launch_bounds__(256) k_mma_nt_adj(const float* __restrict__ F)
{
    __shared__ float sA[2][16][132];
    __shared__ float sB[2][16][136];
    const int row0 = blockIdx.x * 128, col0 = blockIdx.y * 128;
    const int tid = threadIdx.x, lane = tid & 31, w = tid >> 5;
    const int wm = w >> 2, wn = w & 3, grp = lane >> 2, qid = lane & 3;

    float acc[4][4][4];
#pragma unroll
    for (int t = 0; t < 4; t++)
#pragma unroll
        for (int u = 0; u < 4; u++)
#pragma unroll
            for (int v = 0; v < 4; v++) acc[t][u][v] = 0.f;

    const int fr = tid >> 1, fkb = (tid & 1) * 8;
    float ra[8], rb[8];
    {
        const float* as_ = F + (size_t)(row0 + fr) * 128 + fkb;
        float4 a0 = *(const float4*)as_, a1 = *(const float4*)(as_ + 4);
        ra[0]=a0.x; ra[1]=a0.y; ra[2]=a0.z; ra[3]=a0.w; ra[4]=a1.x; ra[5]=a1.y; ra[6]=a1.z; ra[7]=a1.w;
        const float* bs_ = F + (size_t)(col0 + fr) * 128 + fkb;
        float4 b0 = *(const float4*)bs_, b1 = *(const float4*)(bs_ + 4);
        rb[0]=b0.x; rb[1]=b0.y; rb[2]=b0.z; rb[3]=b0.w; rb[4]=b1.x; rb[5]=b1.y; rb[6]=b1.z; rb[7]=b1.w;
    }
#pragma unroll
    for (int i = 0; i < 8; i++) sA[0][fkb + i][fr] = ra[i];
#pragma unroll
    for (int i = 0; i < 8; i++) sB[0][fkb + i][fr] = rb[i];
    __syncthreads();

    for (int it = 0; it < 8; ++it) {
        const int cur = it & 1;
        const bool more = it < 7;
        if (more) {
            int kt = (it + 1) * 16;
            const float* as_ = F + (size_t)(row0 + fr) * 128 + kt + fkb;
            float4 a0 = *(const float4*)as_, a1 = *(const float4*)(as_ + 4);
            ra[0]=a0.x; ra[1]=a0.y; ra[2]=a0.z; ra[3]=a0.w; ra[4]=a1.x; ra[5]=a1.y; ra[6]=a1.z; ra[7]=a1.w;
            const float* bs_ = F + (size_t)(col0 + fr) * 128 + kt + fkb;
            float4 b0 = *(const float4*)bs_, b1 = *(const float4*)(bs_ + 4);
            rb[0]=b0.x; rb[1]=b0.y; rb[2]=b0.z; rb[3]=b0.w; rb[4]=b1.x; rb[5]=b1.y; rb[6]=b1.z; rb[7]=b1.w;
        }
        mma_tile_split(acc, sA[cur], sB[cur], wm, wn, grp, qid);
        if (more) {
#pragma unroll
            for (int i = 0; i < 8; i++) sA[cur ^ 1][fkb + i][fr] = ra[i];
#pragma unroll
            for (int i = 0; i < 8; i++) sB[cur ^ 1][fkb + i][fr] = rb[i];
        }
        __syncthreads();
    }
    // epilogue: pack sign bits (>0) into 32-bit words (warp wn owns one word per row)
#pragma unroll
    for (int t = 0; t < 4; t++)
#pragma unroll
        for (int h = 0; h < 2; h++) {
            unsigned m = 0;
#pragma unroll
            for (int u = 0; u < 4; u++)
#pragma unroll
                for (int vv = 0; vv < 2; vv++)
                    if (acc[t][u][h * 2 + vv] > 0.f) m |= 1u << (u * 8 + qid * 2 + vv);
            m |= __shfl_xor_sync(~0u, m, 1);
            m |= __shfl_xor_sync(~0u, m, 2);
            if (qid == 0)
                g_bits[(size_t)(row0 + wm * 64 + t * 16 + h * 8 + grp) * NW + (col0 >> 5) + wn] = m;
        }
}

// ---------------- NCE gram: exp row/col partial sums + diag, no G ----------------
// grid (n/128, n/128), block 256
__global__ void __launch_bounds__(256) k_mma_nt_nce(
    const float* __restrict__ F, const float* __restrict__ Gm, int n,
    float* __restrict__ RP, float* __restrict__ CP)
{
    __shared__ float sA[2][16][132];
    __shared__ float sB[2][16][136];
    const int row0 = blockIdx.x * 128, col0 = blockIdx.y * 128;
    const int tid = threadIdx.x, lane = tid & 31, w = tid >> 5;
    const int wm = w >> 2, wn = w & 3, grp = lane >> 2, qid = lane & 3;

    float acc[4][4][4];
#pragma unroll
    for (int t = 0; t < 4; t++)
#pragma unroll
        for (int u = 0; u < 4; u++)
#pragma unroll
            for (int v = 0; v < 4; v++) acc[t][u][v] = 0.f;

    const int fr = tid >> 1, fkb = (tid & 1) * 8;
    float ra[8], rb[8];
    {
        const float* as_ = F + (size_t)(row0 + fr) * 128 + fkb;
        float4 a0 = *(const float4*)as_, a1 = *(const float4*)(as_ + 4);
        ra[0]=a0.x; ra[1]=a0.y; ra[2]=a0.z; ra[3]=a0.w; ra[4]=a1.x; ra[5]=a1.y; ra[6]=a1.z; ra[7]=a1.w;
        const float* bs_ = Gm + (size_t)(col0 + fr) * 128 + fkb;
        float4 b0 = *(const float4*)bs_, b1 = *(const float4*)(bs_ + 4);
        rb[0]=b0.x; rb[1]=b0.y; rb[2]=b0.z; rb[3]=b0.w; rb[4]=b1.x; rb[5]=b1.y; rb[6]=b1.z; rb[7]=b1.w;
    }
#pragma unroll
    for (int i = 0; i < 8; i++) sA[0][fkb + i][fr] = ra[i];
#pragma unroll
    for (int i = 0; i < 8; i++) sB[0][fkb + i][fr] = rb[i];
    __syncthreads();

    for (int it = 0; it < 8; ++it) {
        const int cur = it & 1;
        const bool more = it < 7;
        if (more) {
            int kt = (it + 1) * 16;
            const float* as_ = F + (size_t)(row0 + fr) * 128 + kt + fkb;
            float4 a0 = *(const float4*)as_, a1 = *(const float4*)(as_ + 4);
            ra[0]=a0.x; ra[1]=a0.y; ra[2]=a0.z; ra[3]=a0.w; ra[4]=a1.x; ra[5]=a1.y; ra[6]=a1.z; ra[7]=a1.w;
            const float* bs_ = Gm + (size_t)(col0 + fr) * 128 + kt + fkb;
            float4 b0 = *(const float4*)bs_, b1 = *(const float4*)(bs_ + 4);
            rb[0]=b0.x; rb[1]=b0.y; rb[2]=b0.z; rb[3]=b0.w; rb[4]=b1.x; rb[5]=b1.y; rb[6]=b1.z; rb[7]=b1.w;
        }
        mma_tile_1p(acc, sA[cur], sB[cur], wm, wn, grp, qid);
        if (more) {
#pragma unroll
            for (int i = 0; i < 8; i++) sA[cur ^ 1][fkb + i][fr] = ra[i];
#pragma unroll
            for (int i = 0; i < 8; i++) sB[cur ^ 1][fkb + i][fr] = rb[i];
        }
        __syncthreads();
    }

    // diag capture (raw), then exponentiate in place
    if (blockIdx.x == blockIdx.y) {
#pragma unroll
        for (int t = 0; t < 4; t++)
#pragma unroll
            for (int u = 0; u < 4; u++)
#pragma unroll
                for (int v = 0; v < 4; v++) {
                    int r = wm * 64 + t * 16 + (v >> 1) * 8 + grp;
                    int c = wn * 32 + u * 8 + qid * 2 + (v & 1);
                    if (r == c) g_diag[row0 + r] = acc[t][u][v];
                }
    }
#pragma unroll
    for (int t = 0; t < 4; t++)
#pragma unroll
        for (int u = 0; u < 4; u++)
#pragma unroll
            for (int v = 0; v < 4; v++)
                acc[t][u][v] = __expf(acc[t][u][v] * INVT - INVT);

    float* red = (float*)sA;
    // row partial sums (over this tile's 128 cols)
#pragma unroll
    for (int t = 0; t < 4; t++)
#pragma unroll
        for (int h = 0; h < 2; h++) {
            float rs = 0.f;
#pragma unroll
            for (int u = 0; u < 4; u++)
#pragma unroll
                for (int vv = 0; vv < 2; vv++) rs += acc[t][u][h * 2 + vv];
            rs += __shfl_xor_sync(~0u, rs, 1);
            rs += __shfl_xor_sync(~0u, rs, 2);
            if (qid == 0) red[wn * 128 + wm * 64 + t * 16 + h * 8 + grp] = rs;
        }
    __syncthreads();
    if (tid < 128)
        RP[(size_t)blockIdx.y * n + row0 + tid] = red[tid] + red[128 + tid] + red[256 + tid] + red[384 + tid];
    __syncthreads();
    // col partial sums (over this tile's 128 rows)
#pragma unroll
    for (int u = 0; u < 4; u++)
#pragma unroll
        for (int vv = 0; vv < 2; vv++) {
            float cs = 0.f;
#pragma unroll
            for (int t = 0; t < 4; t++)
#pragma unroll
                for (int h = 0; h < 2; h++) cs += acc[t][u][h * 2 + vv];
            cs += __shfl_xor_sync(~0u, cs, 4);
            cs += __shfl_xor_sync(~0u, cs, 8);
            cs += __shfl_xor_sync(~0u, cs, 16);
            if (grp == 0) red[wm * 128 + wn * 32 + u * 8 + qid * 2 + vv] = cs;
        }
    __syncthreads();
    if (tid < 128)
        CP[(size_t)blockIdx.x * n + col0 + tid] = red[tid] + red[128 + tid];
}

// ---------------- binary-adjacency GEMM: Y[M,128] = A_bits @ H[K,128] ----------------
// grid (M/128, K/Kchunk, 2), block 256
__global__ void __launch_bounds__(256) k_mma_bin(
    const unsigned* __restrict__ bits, int nw,
    const float* __restrict__ H0, const float* __restrict__ H1,
    float* __restrict__ P, int M, int Kchunk, int nsl)
{
    __shared__ float sA[2][16][132];
    __shared__ float sB[2][16][136];
    const float* H = blockIdx.z ? H1 : H0;
    const int row0 = blockIdx.x * 128;
    const int k0 = blockIdx.y * Kchunk;
    float* Pout = P + (size_t)(blockIdx.z * nsl + blockIdx.y) * ((size_t)M * 128);
    const int tid = threadIdx.x, lane = tid & 31, w = tid >> 5;
    const int wm = w >> 2, wn = w & 3, grp = lane >> 2, qid = lane & 3;

    float acc[4][4][4];
#pragma unroll
    for (int t = 0; t < 4; t++)
#pragma unroll
        for (int u = 0; u < 4; u++)
#pragma unroll
            for (int v = 0; v < 4; v++) acc[t][u][v] = 0.f;

    const int br = tid & 127, bkh = tid >> 7;       // A expansion: 2 threads/row, 8 bits each
    const int bk = tid >> 4, bnb = (tid & 15) * 8;  // B tile loader
    unsigned wreg; float rb[8];
    {
        wreg = bits[(size_t)(row0 + br) * nw + (k0 >> 5)];
        const float* bs_ = H + (size_t)(k0 + bk) * 128 + bnb;
        float4 b0 = *(const float4*)bs_, b1 = *(const float4*)(bs_ + 4);
        rb[0]=b0.x; rb[1]=b0.y; rb[2]=b0.z; rb[3]=b0.w; rb[4]=b1.x; rb[5]=b1.y; rb[6]=b1.z; rb[7]=b1.w;
    }
    const int nIter = Kchunk / 16;
    {
        int hs = (k0 & 16) + bkh * 8;
#pragma unroll
        for (int i = 0; i < 8; i++) sA[0][bkh * 8 + i][br] = ((wreg >> (hs + i)) & 1u) ? 1.0f : 0.0f;
#pragma unroll
        for (int i = 0; i < 8; i++) sB[0][bk][bnb + i] = rb[i];
    }
    __syncthreads();

    for (int it = 0; it < nIter; ++it) {
        const int cur = it & 1;
        const bool more = (it + 1) < nIter;
        int ktn = k0 + (it + 1) * 16;
        if (more) {
            wreg = bits[(size_t)(row0 + br) * nw + (ktn >> 5)];
            const float* bs_ = H + (size_t)(ktn + bk) * 128 + bnb;
            float4 b0 = *(const float4*)bs_, b1 = *(const float4*)(bs_ + 4);
            rb[0]=b0.x; rb[1]=b0.y; rb[2]=b0.z; rb[3]=b0.w; rb[4]=b1.x; rb[5]=b1.y; rb[6]=b1.z; rb[7]=b1.w;
        }
        mma_tile_1p(acc, sA[cur], sB[cur], wm, wn, grp, qid);
        if (more) {
            int hs = (ktn & 16) + bkh * 8;
#pragma unroll
            for (int i = 0; i < 8; i++) sA[cur ^ 1][bkh * 8 + i][br] = ((wreg >> (hs + i)) & 1u) ? 1.0f : 0.0f;
#pragma unroll
            for (int i = 0; i < 8; i++) sB[cur ^ 1][bk][bnb + i] = rb[i];
        }
        __syncthreads();
    }
#pragma unroll
    for (int t = 0; t < 4; t++) {
        int r = row0 + wm * 64 + t * 16 + grp;
#pragma unroll
        for (int u = 0; u < 4; u++) {
            int c = wn * 32 + u * 8 + qid * 2;
            *(float2*)(Pout + (size_t)r * 128 + c)       = make_float2(acc[t][u][0], acc[t][u][1]);
            *(float2*)(Pout + (size_t)(r + 8) * 128 + c) = make_float2(acc[t][u][2], acc[t][u][3]);
        }
    }
}

// ---------------- reduce partials + bias + l2norm (+optional concat copy) ----------------
// grid (M,1,2), block 128
__global__ void k_red_l2(const float* __restrict__ P, int nsl, int cnt,
                         const float* __restrict__ bias,
                         float* __restrict__ O0, float* __restrict__ O1,
                         float* __restrict__ C0, float* __restrict__ C1, int cld)
{
    int z = blockIdx.z, r = blockIdx.x, t = threadIdx.x;
    const float* Pz = P + (size_t)z * nsl * cnt;
    float s = bias[t];
    for (int k = 0; k < nsl; k++) s += Pz[(size_t)k * cnt + r * 128 + t];
    float q = s * s;
    for (int o = 16; o; o >>= 1) q += __shfl_xor_sync(~0u, q, o);
    __shared__ float ws[4];
    if ((t & 31) == 0) ws[t >> 5] = q;
    __syncthreads();
    float v = s * rsqrtf(ws[0] + ws[1] + ws[2] + ws[3]);
    float* O = z ? O1 : O0;
    O[(size_t)r * 128 + t] = v;
    if (C0) { float* C = z ? C1 : C0; C[(size_t)r * cld + t] = v; }
}

// ---------------- reduce partials with D^-1/2 row scale; writes into concat at offset ----------------
__global__ void k_reduce_s(const float* __restrict__ P, int nsl, int cnt,
                           float* __restrict__ O0, float* __restrict__ O1, int oldd, int ooff,
                           float* __restrict__ S0, float* __restrict__ S1,
                           const float* __restrict__ dinv)
{
    int z = blockIdx.z;
    float* O = z ? O1 : O0;
    const float* Pz = P + (size_t)z * nsl * cnt;
    int i = blockIdx.x * 256 + threadIdx.x;
    float s = 0.f;
    for (int k = 0; k < nsl; k++) s += Pz[(size_t)k * cnt + i];
    int r = i >> 7, c = i & 127;
    float d = dinv[r];
    O[(size_t)r * oldd + ooff + c] = d * s;
    if (S0) { float* S = z ? S1 : S0; S[i] = d * d * s; }
}

// ---------------- degree (popc) + D^-1/2 scale, grid (NN,1,2), block 128 ----------------
__global__ void k_dinv_scale()
{
    int r = blockIdx.x, t = threadIdx.x, z = blockIdx.z;
    __shared__ float sh[2];
    float c = 0.f;
    if (t < 64) c = (float)__popc(g_bits[r * NW + t]);
    for (int o = 16; o; o >>= 1) c += __shfl_xor_sync(~0u, c, o);
    if (t < 64 && (t & 31) == 0) sh[t >> 5] = c;
    __syncthreads();
    float dinv = rsqrtf(sh[0] + sh[1]);
    const float* F = z ? g_fes : g_fet;
    g_hs[z][(size_t)r * 128 + t] = F[(size_t)r * 128 + t] * dinv;
    if (z == 0 && t == 0) g_dinv[r] = dinv;
}

__global__ void k_dinvp()
{
    int i = blockIdx.x * 256 + threadIdx.x;
    int s = 0;
#pragma unroll
    for (int w = 0; w < NWP; w++) s += __popc(g_bitsp[i * NWP + w]);
    g_dinvp[i] = rsqrtf((float)s);
}

// ---------------- pooling scores ----------------
__global__ void k_scores(const float* __restrict__ Wp, const float* __restrict__ bp)
{
    int warp = threadIdx.x >> 5, lane = threadIdx.x & 31;
    int r = blockIdx.x * 8 + warp;
    const float* x = g_fg[0] + (size_t)r * DD;
    float s = x[lane] * Wp[lane] + x[lane + 32] * Wp[lane + 32]
            + x[lane + 64] * Wp[lane + 64] + x[lane + 96] * Wp[lane + 96];
    for (int o = 16; o; o >>= 1) s += __shfl_xor_sync(~0u, s, o);
    if (lane == 0) g_scores[r] = 1.f / (1.f + __expf(-(s + bp[0])));
}

// ---------------- top-1024 bitonic ----------------
__global__ void k_topk()
{
    __shared__ float sv[2048];
    __shared__ int   si[2048];
    int t = threadIdx.x;
    sv[t] = g_scores[t];               si[t] = t;
    sv[t + 1024] = g_scores[t + 1024]; si[t + 1024] = t + 1024;
    __syncthreads();
    for (int k = 2; k <= 2048; k <<= 1)
        for (int j = k >> 1; j > 0; j >>= 1) {
            int i = ((t & ~(j - 1)) << 1) | (t & (j - 1));
            int p = i | j;
            float a = sv[i], b = sv[p];
            int ia = si[i], ib = si[p];
            bool agtb = (a > b) || (a == b && ia < ib);
            bool up = ((i & k) == 0);
            if (up ^ agtb) { sv[i] = b; sv[p] = a; si[i] = ib; si[p] = ia; }
            __syncthreads();
        }
    g_vals[t] = sv[t];
    g_idx[t] = si[t];
}

// ---------------- gather pooled features (+concat copy + D^-1/2 scale) ----------------
__global__ void k_gather()
{
    int z = blockIdx.z;
    int gi = blockIdx.x * 256 + threadIdx.x;
    int r = gi >> 7, c = gi & 127;
    float v = g_fg[z][(size_t)g_idx[r] * DD + c] * g_vals[r];
    g_catp[z][(size_t)r * 256 + c] = v;
    g_nhs[z][gi] = v * g_dinvp[r];
}

// ---------------- pooled 2-hop adjacency bitmask ----------------
__global__ void k_subbits()
{
    int gi = blockIdx.x * 256 + threadIdx.x;
    int i = gi >> 10, j = gi & 1023;
    const unsigned* bi = g_bits + (size_t)g_idx[i] * NW;
    const unsigned* bj = g_bits + (size_t)g_idx[j] * NW;
    bool c = false;
    for (int w = 0; w < NW && !c; w++) c = (bi[w] & bj[w]) != 0u;
    unsigned word = __ballot_sync(~0u, c);
    if ((j & 31) == 0) g_bitsp[i * NWP + (j >> 5)] = word;
}

// ---------------- NCE combine: loss terms from partial sums ----------------
__global__ void k_nce_comb(const float* __restrict__ RP, const float* __restrict__ CP,
                           int ntile, int n, float* __restrict__ RL, float* __restrict__ CL)
{
    int i = blockIdx.x * 256 + threadIdx.x;
    const float* Pp; float* O; int idx;
    if (i < n) { Pp = RP; O = RL; idx = i; }
    else       { Pp = CP; O = CL; idx = i - n; }
    float s = 0.f;
    for (int k = 0; k < ntile; k++) s += Pp[(size_t)k * n + idx];
    O[idx] = INVT + __logf(s) - g_diag[idx] * INVT;
}

// ---------------- final reduction ----------------
__global__ void k_final(float* __restrict__ out)
{
    int t = threadIdx.x;
    float sg = 0.f, sp = 0.f;
    for (int i = t; i < NN; i += 256) sg += g_rl[i] + g_cl[i];
    for (int i = t; i < KP; i += 256) sp += g_rlp[i] + g_clp[i];
    for (int o = 16; o; o >>= 1) {
        sg += __shfl_xor_sync(~0u, sg, o);
        sp += __shfl_xor_sync(~0u, sp, o);
    }
    __shared__ float wg[8], wp[8];
    if ((t & 31) == 0) { wg[t >> 5] = sg; wp[t >> 5] = sp; }
    __syncthreads();
    if (t == 0) {
        float a = 0, b = 0;
        for (int i = 0; i < 8; i++) { a += wg[i]; b += wp[i]; }
        out[0] = a * (1.f / NN) + b * (1.f / KP);
    }
}

// ---------------- host ----------------
extern "C" void kernel_launch(void* const* d_in, const int* in_sizes, int n_in,
                              void* d_out, int out_size)
{
    (void)in_sizes; (void)n_in; (void)out_size;
    const float* fs    = (const float*)d_in[0];
    const float* ft    = (const float*)d_in[1];
    const float* We    = (const float*)d_in[2];
    const float* be    = (const float*)d_in[3];
    const float* Wg    = (const float*)d_in[4];
    const float* bg    = (const float*)d_in[5];
    const float* Wpool = (const float*)d_in[6];
    const float* bpool = (const float*)d_in[7];
    const float* Wgp   = (const float*)d_in[8];
    const float* bgp   = (const float*)d_in[9];

    void* p;
    cudaGetSymbolAddress(&p, g_fet);   float* FET  = (float*)p;
    cudaGetSymbolAddress(&p, g_fes);   float* FES  = (float*)p;
    cudaGetSymbolAddress(&p, g_bits);  unsigned* BITS  = (unsigned*)p;
    cudaGetSymbolAddress(&p, g_bitsp); unsigned* BITSP = (unsigned*)p;
    cudaGetSymbolAddress(&p, g_dinv);  float* DINV  = (float*)p;
    cudaGetSymbolAddress(&p, g_dinvp); float* DINVP = (float*)p;
    cudaGetSymbolAddress(&p, g_hs);    float* HS   = (float*)p;
    cudaGetSymbolAddress(&p, g_nhs);   float* NHS  = (float*)p;
    cudaGetSymbolAddress(&p, g_fg);    float* FG   = (float*)p;
    cudaGetSymbolAddress(&p, g_fp);    float* FP   = (float*)p;
    cudaGetSymbolAddress(&p, g_cat);   float* CAT  = (float*)p;
    cudaGetSymbolAddress(&p, g_catp);  float* CATP = (float*)p;
    cudaGetSymbolAddress(&p, g_part);  float* PART = (float*)p;
    cudaGetSymbolAddress(&p, g_rp);    float* RP   = (float*)p;
    cudaGetSymbolAddress(&p, g_cp);    float* CP   = (float*)p;
    cudaGetSymbolAddress(&p, g_rl);    float* RL   = (float*)p;
    cudaGetSymbolAddress(&p, g_cl);    float* CL   = (float*)p;
    cudaGetSymbolAddress(&p, g_rlp);   float* RLP  = (float*)p;
    cudaGetSymbolAddress(&p, g_clp);   float* CLP  = (float*)p;

    const int ND = NN * DD;    // 262144
    const int KD = KP * DD;    // 131072
    const int CATLD = 384, CATPLD = 256;

    // 1) embed: f = l2norm(x @ We + be); z=0 teacher(ft), z=1 student(fs)
    k_mma_nn<<<dim3(16, 4, 2), 256>>>(ft, fs, CD, We, PART, NN, 128, 4);
    k_red_l2<<<dim3(NN, 1, 2), 128>>>(PART, 4, ND, be, FET, FES, CAT, CAT + NN * CATLD, CATLD);

    // 2) adjacency bits from teacher gram (fused; self-loops automatic since diag=1>0)
    k_mma_nt_adj<<<dim3(16, 16), 256>>>(FET);
    k_dinv_scale<<<dim3(NN, 1, 2), 128>>>();

    // 3) TAGConv k=2 via binary MMA: h_{i+1} = D^-1/2 A (D^-1/2 h_i)
    k_mma_bin<<<dim3(16, 4, 2), 256>>>(BITS, NW, HS, HS + ND, PART, NN, 512, 4);
    k_reduce_s<<<dim3(ND / 256, 1, 2), 256>>>(PART, 4, ND, CAT, CAT + NN * CATLD, CATLD, 128, HS, HS + ND, DINV);
    k_mma_bin<<<dim3(16, 4, 2), 256>>>(BITS, NW, HS, HS + ND, PART, NN, 512, 4);
    k_reduce_s<<<dim3(ND / 256, 1, 2), 256>>>(PART, 4, ND, CAT, CAT + NN * CATLD, CATLD, 256, (float*)0, (float*)0, DINV);

    // 4) concat GEMM (K=384, split 3) + bias + l2norm -> FG
    k_mma_nn<<<dim3(16, 3, 2), 256>>>(CAT, CAT + NN * CATLD, CATLD, Wg, PART, NN, 128, 3);
    k_red_l2<<<dim3(NN, 1, 2), 128>>>(PART, 3, ND, bg, FG, FG + ND, (float*)0, (float*)0, 0);

    // 5) stage-1 NCE: G = f_gt @ f_gs^T with fused exp-sum epilogue
    k_mma_nt_nce<<<dim3(16, 16), 256>>>(FG, FG + ND, NN, RP, CP);
    k_nce_comb<<<2 * NN / 256, 256>>>(RP, CP, 16, NN, RL, CL);

    // 6) pooling
    k_scores<<<NN / 8, 256>>>(Wpool, bpool);
    k_topk<<<1, 1024>>>();
    k_subbits<<<KP * KP / 256, 256>>>();
    k_dinvp<<<KP / 256, 256>>>();
    k_gather<<<dim3(KD / 256, 1, 2), 256>>>();

    // 7) pooled TAGConv k=1
    k_mma_bin<<<dim3(8, 2, 2), 256>>>(BITSP, NWP, NHS, NHS + KD, PART, KP, 512, 2);
    k_reduce_s<<<dim3(KD / 256, 1, 2), 256>>>(PART, 2, KD, CATP, CATP + KP * CATPLD, CATPLD, 128, (float*)0, (float*)0, DINVP);
    k_mma_nn<<<dim3(8, 2, 2), 256>>>(CATP, CATP + KP * CATPLD, CATPLD, Wgp, PART, KP, 128, 2);
    k_red_l2<<<dim3(KP, 1, 2), 128>>>(PART, 2, KD, bgp, FP, FP + KD, (float*)0, (float*)0, 0);

    // 8) pooled NCE
    k_mma_nt_nce<<<dim3(8, 8), 256>>>(FP, FP + KD, KP, RP, CP);
    k_nce_comb<<<2 * KP / 256, 256>>>(RP, CP, 8, KP, RLP, CLP);

    // 9) final scalar
    k_final<<<1, 256>>>((float*)d_out);
}

// round 4
// speedup vs baseline: 2.2242x; 1.0513x over previous
#include <cuda_runtime.h>

// ---------------- problem constants ----------------
#define NN 2048
#define CD 512
#define DD 128
#define KP 1024
#define NW 64            // 2048 bits / 32
#define NWP 32           // 1024 bits / 32
#define INVT 14.285714285714286f

// ---------------- device scratch ----------------
__device__ __align__(16) float g_fet[NN*DD];
__device__ __align__(16) float g_fes[NN*DD];
__device__ unsigned g_bits[NN*NW];
__device__ unsigned g_bitsp[KP*NWP];
__device__ float g_dinv[NN];
__device__ float g_dinvp[KP];
__device__ __align__(16) float g_hs[2][NN*DD];     // D^-1/2-scaled features
__device__ __align__(16) float g_nhs[2][KP*DD];
__device__ __align__(16) float g_fg[2][NN*DD];     // [0]=teacher,[1]=student
__device__ __align__(16) float g_fp[2][KP*DD];
__device__ __align__(16) float g_cat[2][NN*384];   // concat [h0|h1|h2]
__device__ __align__(16) float g_catp[2][KP*256];  // pooled concat
__device__ int   g_idx[KP];
__device__ float g_vals[KP];
__device__ __align__(16) float g_part[16][NN*DD];  // split-K partials
__device__ float g_rp[16*NN], g_cp[16*NN], g_diag[NN];
__device__ float g_rp2[8*KP], g_cp2[8*KP], g_diagp[KP];

// ---------------- tf32 helpers ----------------
__device__ __forceinline__ unsigned f2tf(float x) {
    unsigned r; asm("cvt.rna.tf32.f32 %0, %1;" : "=r"(r) : "f"(x)); return r;
}
__device__ __forceinline__ void mma8(float c[4], unsigned a0, unsigned a1, unsigned a2, unsigned a3,
                                     unsigned b0, unsigned b1) {
    asm volatile("mma.sync.aligned.m16n8k8.row.col.f32.tf32.tf32.f32 "
                 "{%0,%1,%2,%3}, {%4,%5,%6,%7}, {%8,%9}, {%0,%1,%2,%3};\n"
                 : "+f"(c[0]), "+f"(c[1]), "+f"(c[2]), "+f"(c[3])
                 : "r"(a0), "r"(a1), "r"(a2), "r"(a3), "r"(b0), "r"(b1));
}

// ---- MMA over one 16-K stage, 3-pass tf32 split (fp32-accurate) ----
__device__ __forceinline__ void mma_tile_split(
    float acc[4][4][4], const float (*__restrict__ sa)[132], const float (*__restrict__ sb)[136],
    int wm, int wn, int grp, int qid)
{
#pragma unroll
    for (int kk = 0; kk < 16; kk += 8) {
        float araw[4][4], braw[4][2];
        unsigned ah[4][4], bh[4][2];
#pragma unroll
        for (int t = 0; t < 4; t++) {
            int r = wm*64 + t*16 + grp;
            araw[t][0] = sa[kk+qid][r];   araw[t][1] = sa[kk+qid][r+8];
            araw[t][2] = sa[kk+qid+4][r]; araw[t][3] = sa[kk+qid+4][r+8];
#pragma unroll
            for (int j = 0; j < 4; j++) ah[t][j] = f2tf(araw[t][j]);
        }
#pragma unroll
        for (int u = 0; u < 4; u++) {
            int c = wn*32 + u*8 + grp;
            braw[u][0] = sb[kk+qid][c]; braw[u][1] = sb[kk+qid+4][c];
            bh[u][0] = f2tf(braw[u][0]); bh[u][1] = f2tf(braw[u][1]);
        }
#pragma unroll
        for (int t = 0; t < 4; t++)
#pragma unroll
            for (int u = 0; u < 4; u++)
                mma8(acc[t][u], ah[t][0],ah[t][1],ah[t][2],ah[t][3], bh[u][0],bh[u][1]);
        {
            unsigned bl[4][2];
#pragma unroll
            for (int u = 0; u < 4; u++) {
                bl[u][0] = f2tf(braw[u][0] - __uint_as_float(bh[u][0]));
                bl[u][1] = f2tf(braw[u][1] - __uint_as_float(bh[u][1]));
            }
#pragma unroll
            for (int t = 0; t < 4; t++)
#pragma unroll
                for (int u = 0; u < 4; u++)
                    mma8(acc[t][u], ah[t][0],ah[t][1],ah[t][2],ah[t][3], bl[u][0],bl[u][1]);
        }
        {
            unsigned al[4][4];
#pragma unroll
            for (int t = 0; t < 4; t++)
#pragma unroll
                for (int j = 0; j < 4; j++)
                    al[t][j] = f2tf(araw[t][j] - __uint_as_float(ah[t][j]));
#pragma unroll
            for (int t = 0; t < 4; t++)
#pragma unroll
                for (int u = 0; u < 4; u++)
                    mma8(acc[t][u], al[t][0],al[t][1],al[t][2],al[t][3], bh[u][0],bh[u][1]);
        }
    }
}

// ---- MMA over one 16-K stage, single-pass tf32 ----
__device__ __forceinline__ void mma_tile_1p(
    float acc[4][4][4], const float (*__restrict__ sa)[132], const float (*__restrict__ sb)[136],
    int wm, int wn, int grp, int qid)
{
#pragma unroll
    for (int kk = 0; kk < 16; kk += 8) {
        unsigned ah[4][4], bh[4][2];
#pragma unroll
        for (int t = 0; t < 4; t++) {
            int r = wm*64 + t*16 + grp;
            ah[t][0] = f2tf(sa[kk+qid][r]);   ah[t][1] = f2tf(sa[kk+qid][r+8]);
            ah[t][2] = f2tf(sa[kk+qid+4][r]); ah[t][3] = f2tf(sa[kk+qid+4][r+8]);
        }
#pragma unroll
        for (int u = 0; u < 4; u++) {
            int c = wn*32 + u*8 + grp;
            bh[u][0] = f2tf(sb[kk+qid][c]); bh[u][1] = f2tf(sb[kk+qid+4][c]);
        }
#pragma unroll
        for (int t = 0; t < 4; t++)
#pragma unroll
            for (int u = 0; u < 4; u++)
                mma8(acc[t][u], ah[t][0],ah[t][1],ah[t][2],ah[t][3], bh[u][0],bh[u][1]);
    }
}

// ---------------- NN GEMM, split-tf32, double-buffered: C[M,128]=A[M,K]@B[K,128] ----------------
// grid (M/128, K/Kchunk, 2), block 256
__global__ void __launch_bounds__(256) k_mma_nn(
    const float* __restrict__ A0, const float* __restrict__ A1, int lda,
    const float* __restrict__ B,
    float* __restrict__ P, int M, int Kchunk, int nsl)
{
    __shared__ float sA[2][16][132];
    __shared__ float sB[2][16][136];
    const float* A = blockIdx.z ? A1 : A0;
    const int row0 = blockIdx.x * 128;
    const int k0 = blockIdx.y * Kchunk;
    float* Pout = P + (size_t)(blockIdx.z * nsl + blockIdx.y) * ((size_t)M * 128);
    const int tid = threadIdx.x, lane = tid & 31, w = tid >> 5;
    const int wm = w >> 2, wn = w & 3, grp = lane >> 2, qid = lane & 3;

    float acc[4][4][4];
#pragma unroll
    for (int t = 0; t < 4; t++)
#pragma unroll
        for (int u = 0; u < 4; u++)
#pragma unroll
            for (int v = 0; v < 4; v++) acc[t][u][v] = 0.f;

    const int ar = tid >> 1, akb = (tid & 1) * 8;
    const int bk = tid >> 4, bnb = (tid & 15) * 8;
    float ra[8], rb[8];

    {
        const float* as_ = A + (size_t)(row0 + ar) * lda + k0 + akb;
        float4 a0 = *(const float4*)as_, a1 = *(const float4*)(as_ + 4);
        ra[0]=a0.x; ra[1]=a0.y; ra[2]=a0.z; ra[3]=a0.w; ra[4]=a1.x; ra[5]=a1.y; ra[6]=a1.z; ra[7]=a1.w;
        const float* bs_ = B + (size_t)(k0 + bk) * 128 + bnb;
        float4 b0 = *(const float4*)bs_, b1 = *(const float4*)(bs_ + 4);
        rb[0]=b0.x; rb[1]=b0.y; rb[2]=b0.z; rb[3]=b0.w; rb[4]=b1.x; rb[5]=b1.y; rb[6]=b1.z; rb[7]=b1.w;
    }
    const int nIter = Kchunk / 16;
#pragma unroll
    for (int i = 0; i < 8; i++) sA[0][akb + i][ar] = ra[i];
#pragma unroll
    for (int i = 0; i < 8; i++) sB[0][bk][bnb + i] = rb[i];
    __syncthreads();

    for (int it = 0; it < nIter; ++it) {
        const int cur = it & 1;
        const bool more = (it + 1) < nIter;
        if (more) {
            int kt = k0 + (it + 1) * 16;
            const float* as_ = A + (size_t)(row0 + ar) * lda + kt + akb;
            float4 a0 = *(const float4*)as_, a1 = *(const float4*)(as_ + 4);
            ra[0]=a0.x; ra[1]=a0.y; ra[2]=a0.z; ra[3]=a0.w; ra[4]=a1.x; ra[5]=a1.y; ra[6]=a1.z; ra[7]=a1.w;
            const float* bs_ = B + (size_t)(kt + bk) * 128 + bnb;
            float4 b0 = *(const float4*)bs_, b1 = *(const float4*)(bs_ + 4);
            rb[0]=b0.x; rb[1]=b0.y; rb[2]=b0.z; rb[3]=b0.w; rb[4]=b1.x; rb[5]=b1.y; rb[6]=b1.z; rb[7]=b1.w;
        }
        mma_tile_split(acc, sA[cur], sB[cur], wm, wn, grp, qid);
        if (more) {
#pragma unroll
            for (int i = 0; i < 8; i++) sA[cur ^ 1][akb + i][ar] = ra[i];
#pragma unroll
            for (int i = 0; i < 8; i++) sB[cur ^ 1][bk][bnb + i] = rb[i];
        }
        __syncthreads();
    }
#pragma unroll
    for (int t = 0; t < 4; t++) {
        int r = row0 + wm * 64 + t * 16 + grp;
#pragma unroll
        for (int u = 0; u < 4; u++) {
            int c = wn * 32 + u * 8 + qid * 2;
            *(float2*)(Pout + (size_t)r * 128 + c)       = make_float2(acc[t][u][0], acc[t][u][1]);
            *(float2*)(Pout + (size_t)(r + 8) * 128 + c) = make_float2(acc[t][u][2], acc[t][u][3]);
        }
    }
}

// ---------------- adjacency gram: bits = (F F^T > 0), fused epilogue, no G ----------------
// grid (16,16), block 256
__global__ void __launch_bounds__(256) k_mma_nt_adj(const float* __restrict__ F)
{
    __shared__ float sA[2][16][132];
    __shared__ float sB[2][16][136];
    const int row0 = blockIdx.x * 128, col0 = blockIdx.y * 128;
    const int tid = threadIdx.x, lane = tid & 31, w = tid >> 5;
    const int wm = w >> 2, wn = w & 3, grp = lane >> 2, qid = lane & 3;

    float acc[4][4][4];
#pragma unroll
    for (int t = 0; t < 4; t++)
#pragma unroll
        for (int u = 0; u < 4; u++)
#pragma unroll
            for (int v = 0; v < 4; v++) acc[t][u][v] = 0.f;

    const int fr = tid >> 1, fkb = (tid & 1) * 8;
    float ra[8], rb[8];
    {
        const float* as_ = F + (size_t)(row0 + fr) * 128 + fkb;
        float4 a0 = *(const float4*)as_, a1 = *(const float4*)(as_ + 4);
        ra[0]=a0.x; ra[1]=a0.y; ra[2]=a0.z; ra[3]=a0.w; ra[4]=a1.x; ra[5]=a1.y; ra[6]=a1.z; ra[7]=a1.w;
        const float* bs_ = F + (size_t)(col0 + fr) * 128 + fkb;
        float4 b0 = *(const float4*)bs_, b1 = *(const float4*)(bs_ + 4);
        rb[0]=b0.x; rb[1]=b0.y; rb[2]=b0.z; rb[3]=b0.w; rb[4]=b1.x; rb[5]=b1.y; rb[6]=b1.z; rb[7]=b1.w;
    }
#pragma unroll
    for (int i = 0; i < 8; i++) sA[0][fkb + i][fr] = ra[i];
#pragma unroll
    for (int i = 0; i < 8; i++) sB[0][fkb + i][fr] = rb[i];
    __syncthreads();

    for (int it = 0; it < 8; ++it) {
        const int cur = it & 1;
        const bool more = it < 7;
        if (more) {
            int kt = (it + 1) * 16;
            const float* as_ = F + (size_t)(row0 + fr) * 128 + kt + fkb;
            float4 a0 = *(const float4*)as_, a1 = *(const float4*)(as_ + 4);
            ra[0]=a0.x; ra[1]=a0.y; ra[2]=a0.z; ra[3]=a0.w; ra[4]=a1.x; ra[5]=a1.y; ra[6]=a1.z; ra[7]=a1.w;
            const float* bs_ = F + (size_t)(col0 + fr) * 128 + kt + fkb;
            float4 b0 = *(const float4*)bs_, b1 = *(const float4*)(bs_ + 4);
            rb[0]=b0.x; rb[1]=b0.y; rb[2]=b0.z; rb[3]=b0.w; rb[4]=b1.x; rb[5]=b1.y; rb[6]=b1.z; rb[7]=b1.w;
        }
        mma_tile_split(acc, sA[cur], sB[cur], wm, wn, grp, qid);
        if (more) {
#pragma unroll
            for (int i = 0; i < 8; i++) sA[cur ^ 1][fkb + i][fr] = ra[i];
#pragma unroll
            for (int i = 0; i < 8; i++) sB[cur ^ 1][fkb + i][fr] = rb[i];
        }
        __syncthreads();
    }
    // epilogue: pack sign bits (>0) into 32-bit words (warp wn owns one word per row)
#pragma unroll
    for (int t = 0; t < 4; t++)
#pragma unroll
        for (int h = 0; h < 2; h++) {
            unsigned m = 0;
#pragma unroll
            for (int u = 0; u < 4; u++)
#pragma unroll
                for (int vv = 0; vv < 2; vv++)
                    if (acc[t][u][h * 2 + vv] > 0.f) m |= 1u << (u * 8 + qid * 2 + vv);
            m |= __shfl_xor_sync(~0u, m, 1);
            m |= __shfl_xor_sync(~0u, m, 2);
            if (qid == 0)
                g_bits[(size_t)(row0 + wm * 64 + t * 16 + h * 8 + grp) * NW + (col0 >> 5) + wn] = m;
        }
}

// ---------------- NCE gram: exp row/col partial sums + diag, no G ----------------
// grid (n/128, n/128), block 256, 2 CTAs/SM
__global__ void __launch_bounds__(256, 2) k_mma_nt_nce(
    const float* __restrict__ F, const float* __restrict__ Gm, int n,
    float* __restrict__ RP, float* __restrict__ CP, float* __restrict__ diag)
{
    __shared__ float sA[2][16][132];
    __shared__ float sB[2][16][136];
    const int row0 = blockIdx.x * 128, col0 = blockIdx.y * 128;
    const int tid = threadIdx.x, lane = tid & 31, w = tid >> 5;
    const int wm = w >> 2, wn = w & 3, grp = lane >> 2, qid = lane & 3;

    float acc[4][4][4];
#pragma unroll
    for (int t = 0; t < 4; t++)
#pragma unroll
        for (int u = 0; u < 4; u++)
#pragma unroll
            for (int v = 0; v < 4; v++) acc[t][u][v] = 0.f;

    const int fr = tid >> 1, fkb = (tid & 1) * 8;
    float ra[8], rb[8];
    {
        const float* as_ = F + (size_t)(row0 + fr) * 128 + fkb;
        float4 a0 = *(const float4*)as_, a1 = *(const float4*)(as_ + 4);
        ra[0]=a0.x; ra[1]=a0.y; ra[2]=a0.z; ra[3]=a0.w; ra[4]=a1.x; ra[5]=a1.y; ra[6]=a1.z; ra[7]=a1.w;
        const float* bs_ = Gm + (size_t)(col0 + fr) * 128 + fkb;
        float4 b0 = *(const float4*)bs_, b1 = *(const float4*)(bs_ + 4);
        rb[0]=b0.x; rb[1]=b0.y; rb[2]=b0.z; rb[3]=b0.w; rb[4]=b1.x; rb[5]=b1.y; rb[6]=b1.z; rb[7]=b1.w;
    }
#pragma unroll
    for (int i = 0; i < 8; i++) sA[0][fkb + i][fr] = ra[i];
#pragma unroll
    for (int i = 0; i < 8; i++) sB[0][fkb + i][fr] = rb[i];
    __syncthreads();

    for (int it = 0; it < 8; ++it) {
        const int cur = it & 1;
        const bool more = it < 7;
        if (more) {
            int kt = (it + 1) * 16;
            const float* as_ = F + (size_t)(row0 + fr) * 128 + kt + fkb;
            float4 a0 = *(const float4*)as_, a1 = *(const float4*)(as_ + 4);
            ra[0]=a0.x; ra[1]=a0.y; ra[2]=a0.z; ra[3]=a0.w; ra[4]=a1.x; ra[5]=a1.y; ra[6]=a1.z; ra[7]=a1.w;
            const float* bs_ = Gm + (size_t)(col0 + fr) * 128 + kt + fkb;
            float4 b0 = *(const float4*)bs_, b1 = *(const float4*)(bs_ + 4);
            rb[0]=b0.x; rb[1]=b0.y; rb[2]=b0.z; rb[3]=b0.w; rb[4]=b1.x; rb[5]=b1.y; rb[6]=b1.z; rb[7]=b1.w;
        }
        mma_tile_1p(acc, sA[cur], sB[cur], wm, wn, grp, qid);
        if (more) {
#pragma unroll
            for (int i = 0; i < 8; i++) sA[cur ^ 1][fkb + i][fr] = ra[i];
#pragma unroll
            for (int i = 0; i < 8; i++) sB[cur ^ 1][fkb + i][fr] = rb[i];
        }
        __syncthreads();
    }

    // diag capture (raw), then exponentiate in place
    if (blockIdx.x == blockIdx.y) {
#pragma unroll
        for (int t = 0; t < 4; t++)
#pragma unroll
            for (int u = 0; u < 4; u++)
#pragma unroll
                for (int v = 0; v < 4; v++) {
                    int r = wm * 64 + t * 16 + (v >> 1) * 8 + grp;
                    int c = wn * 32 + u * 8 + qid * 2 + (v & 1);
                    if (r == c) diag[row0 + r] = acc[t][u][v];
                }
    }
#pragma unroll
    for (int t = 0; t < 4; t++)
#pragma unroll
        for (int u = 0; u < 4; u++)
#pragma unroll
            for (int v = 0; v < 4; v++)
                acc[t][u][v] = __expf(acc[t][u][v] * INVT - INVT);

    float* red = (float*)sA;
    // row partial sums (over this tile's 128 cols)
#pragma unroll
    for (int t = 0; t < 4; t++)
#pragma unroll
        for (int h = 0; h < 2; h++) {
            float rs = 0.f;
#pragma unroll
            for (int u = 0; u < 4; u++)
#pragma unroll
                for (int vv = 0; vv < 2; vv++) rs += acc[t][u][h * 2 + vv];
            rs += __shfl_xor_sync(~0u, rs, 1);
            rs += __shfl_xor_sync(~0u, rs, 2);
            if (qid == 0) red[wn * 128 + wm * 64 + t * 16 + h * 8 + grp] = rs;
        }
    __syncthreads();
    if (tid < 128)
        RP[(size_t)blockIdx.y * n + row0 + tid] = red[tid] + red[128 + tid] + red[256 + tid] + red[384 + tid];
    __syncthreads();
    // col partial sums (over this tile's 128 rows)
#pragma unroll
    for (int u = 0; u < 4; u++)
#pragma unroll
        for (int vv = 0; vv < 2; vv++) {
            float cs = 0.f;
#pragma unroll
            for (int t = 0; t < 4; t++)
#pragma unroll
                for (int h = 0; h < 2; h++) cs += acc[t][u][h * 2 + vv];
            cs += __shfl_xor_sync(~0u, cs, 4);
            cs += __shfl_xor_sync(~0u, cs, 8);
            cs += __shfl_xor_sync(~0u, cs, 16);
            if (grp == 0) red[wm * 128 + wn * 32 + u * 8 + qid * 2 + vv] = cs;
        }
    __syncthreads();
    if (tid < 128)
        CP[(size_t)blockIdx.x * n + col0 + tid] = red[tid] + red[128 + tid];
}

// ---------------- binary-adjacency GEMM: Y[M,128] = A_bits @ H[K,128] ----------------
// grid (M/128, K/Kchunk, 2), block 256, 2 CTAs/SM
__global__ void __launch_bounds__(256, 2) k_mma_bin(
    const unsigned* __restrict__ bits, int nw,
    const float* __restrict__ H0, const float* __restrict__ H1,
    float* __restrict__ P, int M, int Kchunk, int nsl)
{
    __shared__ float sA[2][16][132];
    __shared__ float sB[2][16][136];
    const float* H = blockIdx.z ? H1 : H0;
    const int row0 = blockIdx.x * 128;
    const int k0 = blockIdx.y * Kchunk;
    float* Pout = P + (size_t)(blockIdx.z * nsl + blockIdx.y) * ((size_t)M * 128);
    const int tid = threadIdx.x, lane = tid & 31, w = tid >> 5;
    const int wm = w >> 2, wn = w & 3, grp = lane >> 2, qid = lane & 3;

    float acc[4][4][4];
#pragma unroll
    for (int t = 0; t < 4; t++)
#pragma unroll
        for (int u = 0; u < 4; u++)
#pragma unroll
            for (int v = 0; v < 4; v++) acc[t][u][v] = 0.f;

    const int br = tid & 127, bkh = tid >> 7;       // A expansion: 2 threads/row, 8 bits each
    const int bk = tid >> 4, bnb = (tid & 15) * 8;  // B tile loader
    unsigned wreg; float rb[8];
    {
        wreg = bits[(size_t)(row0 + br) * nw + (k0 >> 5)];
        const float* bs_ = H + (size_t)(k0 + bk) * 128 + bnb;
        float4 b0 = *(const float4*)bs_, b1 = *(const float4*)(bs_ + 4);
        rb[0]=b0.x; rb[1]=b0.y; rb[2]=b0.z; rb[3]=b0.w; rb[4]=b1.x; rb[5]=b1.y; rb[6]=b1.z; rb[7]=b1.w;
    }
    const int nIter = Kchunk / 16;
    {
        int hs = (k0 & 16) + bkh * 8;
#pragma unroll
        for (int i = 0; i < 8; i++) sA[0][bkh * 8 + i][br] = ((wreg >> (hs + i)) & 1u) ? 1.0f : 0.0f;
#pragma unroll
        for (int i = 0; i < 8; i++) sB[0][bk][bnb + i] = rb[i];
    }
    __syncthreads();

    for (int it = 0; it < nIter; ++it) {
        const int cur = it & 1;
        const bool more = (it + 1) < nIter;
        int ktn = k0 + (it + 1) * 16;
        if (more) {
            wreg = bits[(size_t)(row0 + br) * nw + (ktn >> 5)];
            const float* bs_ = H + (size_t)(ktn + bk) * 128 + bnb;
            float4 b0 = *(const float4*)bs_, b1 = *(const float4*)(bs_ + 4);
            rb[0]=b0.x; rb[1]=b0.y; rb[2]=b0.z; rb[3]=b0.w; rb[4]=b1.x; rb[5]=b1.y; rb[6]=b1.z; rb[7]=b1.w;
        }
        mma_tile_1p(acc, sA[cur], sB[cur], wm, wn, grp, qid);
        if (more) {
            int hs = (ktn & 16) + bkh * 8;
#pragma unroll
            for (int i = 0; i < 8; i++) sA[cur ^ 1][bkh * 8 + i][br] = ((wreg >> (hs + i)) & 1u) ? 1.0f : 0.0f;
#pragma unroll
            for (int i = 0; i < 8; i++) sB[cur ^ 1][bk][bnb + i] = rb[i];
        }
        __syncthreads();
    }
#pragma unroll
    for (int t = 0; t < 4; t++) {
        int r = row0 + wm * 64 + t * 16 + grp;
#pragma unroll
        for (int u = 0; u < 4; u++) {
            int c = wn * 32 + u * 8 + qid * 2;
            *(float2*)(Pout + (size_t)r * 128 + c)       = make_float2(acc[t][u][0], acc[t][u][1]);
            *(float2*)(Pout + (size_t)(r + 8) * 128 + c) = make_float2(acc[t][u][2], acc[t][u][3]);
        }
    }
}

// ---------------- reduce partials + bias + l2norm (+optional concat copy) ----------------
// grid (M,1,2), block 128
__global__ void k_red_l2(const float* __restrict__ P, int nsl, int cnt,
                         const float* __restrict__ bias,
                         float* __restrict__ O0, float* __restrict__ O1,
                         float* __restrict__ C0, float* __restrict__ C1, int cld)
{
    int z = blockIdx.z, r = blockIdx.x, t = threadIdx.x;
    const float* Pz = P + (size_t)z * nsl * cnt;
    float s = bias[t];
    for (int k = 0; k < nsl; k++) s += Pz[(size_t)k * cnt + r * 128 + t];
    float q = s * s;
    for (int o = 16; o; o >>= 1) q += __shfl_xor_sync(~0u, q, o);
    __shared__ float ws[4];
    if ((t & 31) == 0) ws[t >> 5] = q;
    __syncthreads();
    float v = s * rsqrtf(ws[0] + ws[1] + ws[2] + ws[3]);
    float* O = z ? O1 : O0;
    O[(size_t)r * 128 + t] = v;
    if (C0) { float* C = z ? C1 : C0; C[(size_t)r * cld + t] = v; }
}

// ---------------- reduce partials with D^-1/2 row scale; writes into concat at offset ----------------
__global__ void k_reduce_s(const float* __restrict__ P, int nsl, int cnt,
                           float* __restrict__ O0, float* __restrict__ O1, int oldd, int ooff,
                           float* __restrict__ S0, float* __restrict__ S1,
                           const float* __restrict__ dinv)
{
    int z = blockIdx.z;
    float* O = z ? O1 : O0;
    const float* Pz = P + (size_t)z * nsl * cnt;
    int i = blockIdx.x * 256 + threadIdx.x;
    float s = 0.f;
    for (int k = 0; k < nsl; k++) s += Pz[(size_t)k * cnt + i];
    int r = i >> 7, c = i & 127;
    float d = dinv[r];
    O[(size_t)r * oldd + ooff + c] = d * s;
    if (S0) { float* S = z ? S1 : S0; S[i] = d * d * s; }
}

// ---------------- degree (popc) + D^-1/2 scale, grid (NN,1,2), block 128 ----------------
__global__ void k_dinv_scale()
{
    int r = blockIdx.x, t = threadIdx.x, z = blockIdx.z;
    __shared__ float sh[2];
    float c = 0.f;
    if (t < 64) c = (float)__popc(g_bits[r * NW + t]);
    for (int o = 16; o; o >>= 1) c += __shfl_xor_sync(~0u, c, o);
    if (t < 64 && (t & 31) == 0) sh[t >> 5] = c;
    __syncthreads();
    float dinv = rsqrtf(sh[0] + sh[1]);
    const float* F = z ? g_fes : g_fet;
    g_hs[z][(size_t)r * 128 + t] = F[(size_t)r * 128 + t] * dinv;
    if (z == 0 && t == 0) g_dinv[r] = dinv;
}

// ---------------- scores + top-1024 in one block ----------------
__global__ void k_pool1(const float* __restrict__ Wp, const float* __restrict__ bp)
{
    __shared__ float sv[2048];
    __shared__ int   si[2048];
    int t = threadIdx.x, lane = t & 31, w = t >> 5;
    float w0 = Wp[lane], w1 = Wp[lane + 32], w2 = Wp[lane + 64], w3 = Wp[lane + 96];
    float bb = bp[0];
    for (int r = w; r < NN; r += 32) {
        const float* x = g_fg[0] + (size_t)r * DD;
        float s = x[lane] * w0 + x[lane + 32] * w1 + x[lane + 64] * w2 + x[lane + 96] * w3;
        for (int o = 16; o; o >>= 1) s += __shfl_xor_sync(~0u, s, o);
        if (lane == 0) { sv[r] = 1.f / (1.f + __expf(-(s + bb))); si[r] = r; }
    }
    __syncthreads();
    for (int k = 2; k <= 2048; k <<= 1)
        for (int j = k >> 1; j > 0; j >>= 1) {
            int i = ((t & ~(j - 1)) << 1) | (t & (j - 1));
            int p = i | j;
            float a = sv[i], b = sv[p];
            int ia = si[i], ib = si[p];
            bool agtb = (a > b) || (a == b && ia < ib);
            bool up = ((i & k) == 0);
            if (up ^ agtb) { sv[i] = b; sv[p] = a; si[i] = ib; si[p] = ia; }
            __syncthreads();
        }
    g_vals[t] = sv[t];
    g_idx[t] = si[t];
}

// ---------------- pooled 2-hop adjacency bits + dinvp, one row per block ----------------
__global__ void k_pool2()
{
    __shared__ unsigned sbi[NW];
    __shared__ int ws[8];
    int i = blockIdx.x, t = threadIdx.x;
    const unsigned* bi = g_bits + (size_t)g_idx[i] * NW;
    if (t < NW) sbi[t] = bi[t];
    __syncthreads();
    int cnt = 0;
    for (int jb = 0; jb < KP; jb += 256) {
        int j = jb + t;
        const unsigned* bj = g_bits + (size_t)g_idx[j] * NW;
        bool c = false;
        for (int w = 0; w < NW && !c; w++) c = (sbi[w] & bj[w]) != 0u;
        unsigned word = __ballot_sync(~0u, c);
        cnt += c ? 1 : 0;
        if ((t & 31) == 0) g_bitsp[i * NWP + (j >> 5)] = word;
    }
    for (int o = 16; o; o >>= 1) cnt += __shfl_xor_sync(~0u, cnt, o);
    if ((t & 31) == 0) ws[t >> 5] = cnt;
    __syncthreads();
    if (t == 0) {
        int s = 0;
        for (int k = 0; k < 8; k++) s += ws[k];
        g_dinvp[i] = rsqrtf((float)s);
    }
}

// ---------------- gather pooled features (+concat copy + D^-1/2 scale) ----------------
__global__ void k_gather()
{
    int z = blockIdx.z;
    int gi = blockIdx.x * 256 + threadIdx.x;
    int r = gi >> 7, c = gi & 127;
    float v = g_fg[z][(size_t)g_idx[r] * DD + c] * g_vals[r];
    g_catp[z][(size_t)r * 256 + c] = v;
    g_nhs[z][gi] = v * g_dinvp[r];
}

// ---------------- final: NCE combine for both stages + scalar ----------------
__global__ void k_final(float* __restrict__ out)
{
    int t = threadIdx.x;   // 1024 threads
    float sg = 0.f, sp = 0.f;
    for (int i = t; i < NN; i += 1024) {
        float s1 = 0.f, s2 = 0.f;
        for (int k = 0; k < 16; k++) { s1 += g_rp[k * NN + i]; s2 += g_cp[k * NN + i]; }
        sg += 2.f * INVT + __logf(s1) + __logf(s2) - 2.f * g_diag[i] * INVT;
    }
    {
        int i = t;
        float s1 = 0.f, s2 = 0.f;
        for (int k = 0; k < 8; k++) { s1 += g_rp2[k * KP + i]; s2 += g_cp2[k * KP + i]; }
        sp += 2.f * INVT + __logf(s1) + __logf(s2) - 2.f * g_diagp[i] * INVT;
    }
    for (int o = 16; o; o >>= 1) {
        sg += __shfl_xor_sync(~0u, sg, o);
        sp += __shfl_xor_sync(~0u, sp, o);
    }
    __shared__ float wg[32], wp[32];
    if ((t & 31) == 0) { wg[t >> 5] = sg; wp[t >> 5] = sp; }
    __syncthreads();
    if (t == 0) {
        float a = 0.f, b = 0.f;
        for (int i = 0; i < 32; i++) { a += wg[i]; b += wp[i]; }
        out[0] = a * (1.f / NN) + b * (1.f / KP);
    }
}

// ---------------- host ----------------
extern "C" void kernel_launch(void* const* d_in, const int* in_sizes, int n_in,
                              void* d_out, int out_size)
{
    (void)in_sizes; (void)n_in; (void)out_size;
    const float* fs    = (const float*)d_in[0];
    const float* ft    = (const float*)d_in[1];
    const float* We    = (const float*)d_in[2];
    const float* be    = (const float*)d_in[3];
    const float* Wg    = (const float*)d_in[4];
    const float* bg    = (const float*)d_in[5];
    const float* Wpool = (const float*)d_in[6];
    const float* bpool = (const float*)d_in[7];
    const float* Wgp   = (const float*)d_in[8];
    const float* bgp   = (const float*)d_in[9];

    void* p;
    cudaGetSymbolAddress(&p, g_fet);   float* FET  = (float*)p;
    cudaGetSymbolAddress(&p, g_fes);   float* FES  = (float*)p;
    cudaGetSymbolAddress(&p, g_bits);  unsigned* BITS  = (unsigned*)p;
    cudaGetSymbolAddress(&p, g_bitsp); unsigned* BITSP = (unsigned*)p;
    cudaGetSymbolAddress(&p, g_dinv);  float* DINV  = (float*)p;
    cudaGetSymbolAddress(&p, g_dinvp); float* DINVP = (float*)p;
    cudaGetSymbolAddress(&p, g_hs);    float* HS   = (float*)p;
    cudaGetSymbolAddress(&p, g_nhs);   float* NHS  = (float*)p;
    cudaGetSymbolAddress(&p, g_fg);    float* FG   = (float*)p;
    cudaGetSymbolAddress(&p, g_fp);    float* FP   = (float*)p;
    cudaGetSymbolAddress(&p, g_cat);   float* CAT  = (float*)p;
    cudaGetSymbolAddress(&p, g_catp);  float* CATP = (float*)p;
    cudaGetSymbolAddress(&p, g_part);  float* PART = (float*)p;
    cudaGetSymbolAddress(&p, g_rp);    float* RP   = (float*)p;
    cudaGetSymbolAddress(&p, g_cp);    float* CP   = (float*)p;
    cudaGetSymbolAddress(&p, g_rp2);   float* RP2  = (float*)p;
    cudaGetSymbolAddress(&p, g_cp2);   float* CP2  = (float*)p;
    cudaGetSymbolAddress(&p, g_diag);  float* DG1  = (float*)p;
    cudaGetSymbolAddress(&p, g_diagp); float* DG2  = (float*)p;

    const int ND = NN * DD;    // 262144
    const int KD = KP * DD;    // 131072
    const int CATLD = 384, CATPLD = 256;

    // 1) embed: f = l2norm(x @ We + be); z=0 teacher(ft), z=1 student(fs)
    k_mma_nn<<<dim3(16, 8, 2), 256>>>(ft, fs, CD, We, PART, NN, 64, 8);
    k_red_l2<<<dim3(NN, 1, 2), 128>>>(PART, 8, ND, be, FET, FES, CAT, CAT + NN * CATLD, CATLD);

    // 2) adjacency bits from teacher gram (fused; self-loops automatic since diag=1>0)
    k_mma_nt_adj<<<dim3(16, 16), 256>>>(FET);
    k_dinv_scale<<<dim3(NN, 1, 2), 128>>>();

    // 3) TAGConv k=2 via binary MMA: h_{i+1} = D^-1/2 A (D^-1/2 h_i)
    k_mma_bin<<<dim3(16, 8, 2), 256>>>(BITS, NW, HS, HS + ND, PART, NN, 256, 8);
    k_reduce_s<<<dim3(ND / 256, 1, 2), 256>>>(PART, 8, ND, CAT, CAT + NN * CATLD, CATLD, 128, HS, HS + ND, DINV);
    k_mma_bin<<<dim3(16, 8, 2), 256>>>(BITS, NW, HS, HS + ND, PART, NN, 256, 8);
    k_reduce_s<<<dim3(ND / 256, 1, 2), 256>>>(PART, 8, ND, CAT, CAT + NN * CATLD, CATLD, 256, (float*)0, (float*)0, DINV);

    // 4) concat GEMM (K=384, Kchunk=96 -> 4 slots) + bias + l2norm -> FG
    k_mma_nn<<<dim3(16, 4, 2), 256>>>(CAT, CAT + NN * CATLD, CATLD, Wg, PART, NN, 96, 4);
    k_red_l2<<<dim3(NN, 1, 2), 128>>>(PART, 4, ND, bg, FG, FG + ND, (float*)0, (float*)0, 0);

    // 5) stage-1 NCE: G = f_gt @ f_gs^T with fused exp-sum epilogue
    k_mma_nt_nce<<<dim3(16, 16), 256>>>(FG, FG + ND, NN, RP, CP, DG1);

    // 6) pooling: scores+topk, subbits+dinvp, gather
    k_pool1<<<1, 1024>>>(Wpool, bpool);
    k_pool2<<<KP, 256>>>();
    k_gather<<<dim3(KD / 256, 1, 2), 256>>>();

    // 7) pooled TAGConv k=1
    k_mma_bin<<<dim3(8, 4, 2), 256>>>(BITSP, NWP, NHS, NHS + KD, PART, KP, 256, 4);
    k_reduce_s<<<dim3(KD / 256, 1, 2), 256>>>(PART, 4, KD, CATP, CATP + KP * CATPLD, CATPLD, 128, (float*)0, (float*)0, DINVP);
    k_mma_nn<<<dim3(8, 2, 2), 256>>>(CATP, CATP + KP * CATPLD, CATPLD, Wgp, PART, KP, 128, 2);
    k_red_l2<<<dim3(KP, 1, 2), 128>>>(PART, 2, KD, bgp, FP, FP + KD, (float*)0, (float*)0, 0);

    // 8) pooled NCE
    k_mma_nt_nce<<<dim3(8, 8), 256>>>(FP, FP + KD, KP, RP2, CP2, DG2);

    // 9) NCE combine (both stages) + final scalar
    k_final<<<1, 1024>>>((float*)d_out);
}

// round 5
// speedup vs baseline: 2.4336x; 1.0941x over previous
#include <cuda_runtime.h>
#include <math.h>

// ---------------- problem constants ----------------
#define NN 2048
#define CD 512
#define DD 128
#define KP 1024
#define NW 64            // 2048 bits / 32
#define NWP 32           // 1024 bits / 32
#define INVT 14.285714285714286f

// ---------------- device scratch ----------------
__device__ __align__(16) float g_fet[NN*DD];
__device__ __align__(16) float g_fes[NN*DD];
__device__ unsigned g_bits[NN*NW];
__device__ unsigned g_bitsp[KP*NWP];
__device__ float g_dinv[NN];
__device__ float g_dinvp[KP];
__device__ __align__(16) float g_hs[2][NN*DD];     // D^-1/2-scaled features
__device__ __align__(16) float g_nhs[2][KP*DD];
__device__ __align__(16) float g_fg[2][NN*DD];     // [0]=teacher,[1]=student
__device__ __align__(16) float g_fp[2][KP*DD];
__device__ __align__(16) float g_cat[2][NN*384];   // concat [h0|h1|h2]
__device__ __align__(16) float g_catp[2][KP*256];  // pooled concat
__device__ int   g_idx[KP];
__device__ float g_vals[KP];
__device__ __align__(16) float g_part[16][NN*DD];  // split-K partials
__device__ float g_rp[16*NN], g_cp[16*NN], g_diag[NN];
__device__ float g_rp2[8*KP], g_cp2[8*KP], g_diagp[KP];

// ---------------- tf32 helpers ----------------
__device__ __forceinline__ unsigned f2tf(float x) {
    unsigned r; asm("cvt.rna.tf32.f32 %0, %1;" : "=r"(r) : "f"(x)); return r;
}
__device__ __forceinline__ void mma8(float c[4], unsigned a0, unsigned a1, unsigned a2, unsigned a3,
                                     unsigned b0, unsigned b1) {
    asm volatile("mma.sync.aligned.m16n8k8.row.col.f32.tf32.tf32.f32 "
                 "{%0,%1,%2,%3}, {%4,%5,%6,%7}, {%8,%9}, {%0,%1,%2,%3};\n"
                 : "+f"(c[0]), "+f"(c[1]), "+f"(c[2]), "+f"(c[3])
                 : "r"(a0), "r"(a1), "r"(a2), "r"(a3), "r"(b0), "r"(b1));
}

// ---- MMA over one 16-K stage, 3-pass tf32 split (fp32-accurate) ----
__device__ __forceinline__ void mma_tile_split(
    float acc[4][4][4], const float (*__restrict__ sa)[132], const float (*__restrict__ sb)[136],
    int wm, int wn, int grp, int qid)
{
#pragma unroll
    for (int kk = 0; kk < 16; kk += 8) {
        float araw[4][4], braw[4][2];
        unsigned ah[4][4], bh[4][2];
#pragma unroll
        for (int t = 0; t < 4; t++) {
            int r = wm*64 + t*16 + grp;
            araw[t][0] = sa[kk+qid][r];   araw[t][1] = sa[kk+qid][r+8];
            araw[t][2] = sa[kk+qid+4][r]; araw[t][3] = sa[kk+qid+4][r+8];
#pragma unroll
            for (int j = 0; j < 4; j++) ah[t][j] = f2tf(araw[t][j]);
        }
#pragma unroll
        for (int u = 0; u < 4; u++) {
            int c = wn*32 + u*8 + grp;
            braw[u][0] = sb[kk+qid][c]; braw[u][1] = sb[kk+qid+4][c];
            bh[u][0] = f2tf(braw[u][0]); bh[u][1] = f2tf(braw[u][1]);
        }
#pragma unroll
        for (int t = 0; t < 4; t++)
#pragma unroll
            for (int u = 0; u < 4; u++)
                mma8(acc[t][u], ah[t][0],ah[t][1],ah[t][2],ah[t][3], bh[u][0],bh[u][1]);
        {
            unsigned bl[4][2];
#pragma unroll
            for (int u = 0; u < 4; u++) {
                bl[u][0] = f2tf(braw[u][0] - __uint_as_float(bh[u][0]));
                bl[u][1] = f2tf(braw[u][1] - __uint_as_float(bh[u][1]));
            }
#pragma unroll
            for (int t = 0; t < 4; t++)
#pragma unroll
                for (int u = 0; u < 4; u++)
                    mma8(acc[t][u], ah[t][0],ah[t][1],ah[t][2],ah[t][3], bl[u][0],bl[u][1]);
        }
        {
            unsigned al[4][4];
#pragma unroll
            for (int t = 0; t < 4; t++)
#pragma unroll
                for (int j = 0; j < 4; j++)
                    al[t][j] = f2tf(araw[t][j] - __uint_as_float(ah[t][j]));
#pragma unroll
            for (int t = 0; t < 4; t++)
#pragma unroll
                for (int u = 0; u < 4; u++)
                    mma8(acc[t][u], al[t][0],al[t][1],al[t][2],al[t][3], bh[u][0],bh[u][1]);
        }
    }
}

// ---- MMA over one 16-K stage, single-pass tf32 ----
__device__ __forceinline__ void mma_tile_1p(
    float acc[4][4][4], const float (*__restrict__ sa)[132], const float (*__restrict__ sb)[136],
    int wm, int wn, int grp, int qid)
{
#pragma unroll
    for (int kk = 0; kk < 16; kk += 8) {
        unsigned ah[4][4], bh[4][2];
#pragma unroll
        for (int t = 0; t < 4; t++) {
            int r = wm*64 + t*16 + grp;
            ah[t][0] = f2tf(sa[kk+qid][r]);   ah[t][1] = f2tf(sa[kk+qid][r+8]);
            ah[t][2] = f2tf(sa[kk+qid+4][r]); ah[t][3] = f2tf(sa[kk+qid+4][r+8]);
        }
#pragma unroll
        for (int u = 0; u < 4; u++) {
            int c = wn*32 + u*8 + grp;
            bh[u][0] = f2tf(sb[kk+qid][c]); bh[u][1] = f2tf(sb[kk+qid+4][c]);
        }
#pragma unroll
        for (int t = 0; t < 4; t++)
#pragma unroll
            for (int u = 0; u < 4; u++)
                mma8(acc[t][u], ah[t][0],ah[t][1],ah[t][2],ah[t][3], bh[u][0],bh[u][1]);
    }
}

// ---------------- NN GEMM, split-tf32, double-buffered: C[M,128]=A[M,K]@B[K,128] ----------------
// grid (M/128, K/Kchunk, 2), block 256
__global__ void __launch_bounds__(256) k_mma_nn(
    const float* __restrict__ A0, const float* __restrict__ A1, int lda,
    const float* __restrict__ B,
    float* __restrict__ P, int M, int Kchunk, int nsl)
{
    __shared__ float sA[2][16][132];
    __shared__ float sB[2][16][136];
    const float* A = blockIdx.z ? A1 : A0;
    const int row0 = blockIdx.x * 128;
    const int k0 = blockIdx.y * Kchunk;
    float* Pout = P + (size_t)(blockIdx.z * nsl + blockIdx.y) * ((size_t)M * 128);
    const int tid = threadIdx.x, lane = tid & 31, w = tid >> 5;
    const int wm = w >> 2, wn = w & 3, grp = lane >> 2, qid = lane & 3;

    float acc[4][4][4];
#pragma unroll
    for (int t = 0; t < 4; t++)
#pragma unroll
        for (int u = 0; u < 4; u++)
#pragma unroll
            for (int v = 0; v < 4; v++) acc[t][u][v] = 0.f;

    const int ar = tid >> 1, akb = (tid & 1) * 8;
    const int bk = tid >> 4, bnb = (tid & 15) * 8;
    float ra[8], rb[8];

    {
        const float* as_ = A + (size_t)(row0 + ar) * lda + k0 + akb;
        float4 a0 = *(const float4*)as_, a1 = *(const float4*)(as_ + 4);
        ra[0]=a0.x; ra[1]=a0.y; ra[2]=a0.z; ra[3]=a0.w; ra[4]=a1.x; ra[5]=a1.y; ra[6]=a1.z; ra[7]=a1.w;
        const float* bs_ = B + (size_t)(k0 + bk) * 128 + bnb;
        float4 b0 = *(const float4*)bs_, b1 = *(const float4*)(bs_ + 4);
        rb[0]=b0.x; rb[1]=b0.y; rb[2]=b0.z; rb[3]=b0.w; rb[4]=b1.x; rb[5]=b1.y; rb[6]=b1.z; rb[7]=b1.w;
    }
    const int nIter = Kchunk / 16;
#pragma unroll
    for (int i = 0; i < 8; i++) sA[0][akb + i][ar] = ra[i];
#pragma unroll
    for (int i = 0; i < 8; i++) sB[0][bk][bnb + i] = rb[i];
    __syncthreads();

    for (int it = 0; it < nIter; ++it) {
        const int cur = it & 1;
        const bool more = (it + 1) < nIter;
        if (more) {
            int kt = k0 + (it + 1) * 16;
            const float* as_ = A + (size_t)(row0 + ar) * lda + kt + akb;
            float4 a0 = *(const float4*)as_, a1 = *(const float4*)(as_ + 4);
            ra[0]=a0.x; ra[1]=a0.y; ra[2]=a0.z; ra[3]=a0.w; ra[4]=a1.x; ra[5]=a1.y; ra[6]=a1.z; ra[7]=a1.w;
            const float* bs_ = B + (size_t)(kt + bk) * 128 + bnb;
            float4 b0 = *(const float4*)bs_, b1 = *(const float4*)(bs_ + 4);
            rb[0]=b0.x; rb[1]=b0.y; rb[2]=b0.z; rb[3]=b0.w; rb[4]=b1.x; rb[5]=b1.y; rb[6]=b1.z; rb[7]=b1.w;
        }
        mma_tile_split(acc, sA[cur], sB[cur], wm, wn, grp, qid);
        if (more) {
#pragma unroll
            for (int i = 0; i < 8; i++) sA[cur ^ 1][akb + i][ar] = ra[i];
#pragma unroll
            for (int i = 0; i < 8; i++) sB[cur ^ 1][bk][bnb + i] = rb[i];
        }
        __syncthreads();
    }
#pragma unroll
    for (int t = 0; t < 4; t++) {
        int r = row0 + wm * 64 + t * 16 + grp;
#pragma unroll
        for (int u = 0; u < 4; u++) {
            int c = wn * 32 + u * 8 + qid * 2;
            *(float2*)(Pout + (size_t)r * 128 + c)       = make_float2(acc[t][u][0], acc[t][u][1]);
            *(float2*)(Pout + (size_t)(r + 8) * 128 + c) = make_float2(acc[t][u][2], acc[t][u][3]);
        }
    }
}

// ---------------- adjacency gram (SYMMETRIC): bits = (F F^T > 0), upper-triangle tiles only ----------------
// grid (136), block 256.  Off-diagonal tiles also emit the transposed bit-block.
__global__ void __launch_bounds__(256) k_mma_nt_adj(const float* __restrict__ F)
{
    __shared__ float sA[2][16][132];
    __shared__ float sB[2][16][136];
    __shared__ unsigned srow[128][5];
    // triangular decode: tiles (bx, by) with bx <= by
    int i = blockIdx.x;
    int by = (int)((sqrtf(8.f * i + 1.f) - 1.f) * 0.5f);
    while ((by + 1) * (by + 2) / 2 <= i) by++;
    while (by * (by + 1) / 2 > i) by--;
    int bx = i - by * (by + 1) / 2;
    const int row0 = bx * 128, col0 = by * 128;
    const int tid = threadIdx.x, lane = tid & 31, w = tid >> 5;
    const int wm = w >> 2, wn = w & 3, grp = lane >> 2, qid = lane & 3;

    float acc[4][4][4];
#pragma unroll
    for (int t = 0; t < 4; t++)
#pragma unroll
        for (int u = 0; u < 4; u++)
#pragma unroll
            for (int v = 0; v < 4; v++) acc[t][u][v] = 0.f;

    const int fr = tid >> 1, fkb = (tid & 1) * 8;
    float ra[8], rb[8];
    {
        const float* as_ = F + (size_t)(row0 + fr) * 128 + fkb;
        float4 a0 = *(const float4*)as_, a1 = *(const float4*)(as_ + 4);
        ra[0]=a0.x; ra[1]=a0.y; ra[2]=a0.z; ra[3]=a0.w; ra[4]=a1.x; ra[5]=a1.y; ra[6]=a1.z; ra[7]=a1.w;
        const float* bs_ = F + (size_t)(col0 + fr) * 128 + fkb;
        float4 b0 = *(const float4*)bs_, b1 = *(const float4*)(bs_ + 4);
        rb[0]=b0.x; rb[1]=b0.y; rb[2]=b0.z; rb[3]=b0.w; rb[4]=b1.x; rb[5]=b1.y; rb[6]=b1.z; rb[7]=b1.w;
    }
#pragma unroll
    for (int i2 = 0; i2 < 8; i2++) sA[0][fkb + i2][fr] = ra[i2];
#pragma unroll
    for (int i2 = 0; i2 < 8; i2++) sB[0][fkb + i2][fr] = rb[i2];
    __syncthreads();

    for (int it = 0; it < 8; ++it) {
        const int cur = it & 1;
        const bool more = it < 7;
        if (more) {
            int kt = (it + 1) * 16;
            const float* as_ = F + (size_t)(row0 + fr) * 128 + kt + fkb;
            float4 a0 = *(const float4*)as_, a1 = *(const float4*)(as_ + 4);
            ra[0]=a0.x; ra[1]=a0.y; ra[2]=a0.z; ra[3]=a0.w; ra[4]=a1.x; ra[5]=a1.y; ra[6]=a1.z; ra[7]=a1.w;
            const float* bs_ = F + (size_t)(col0 + fr) * 128 + kt + fkb;
            float4 b0 = *(const float4*)bs_, b1 = *(const float4*)(bs_ + 4);
            rb[0]=b0.x; rb[1]=b0.y; rb[2]=b0.z; rb[3]=b0.w; rb[4]=b1.x; rb[5]=b1.y; rb[6]=b1.z; rb[7]=b1.w;
        }
        mma_tile_split(acc, sA[cur], sB[cur], wm, wn, grp, qid);
        if (more) {
#pragma unroll
            for (int i2 = 0; i2 < 8; i2++) sA[cur ^ 1][fkb + i2][fr] = ra[i2];
#pragma unroll
            for (int i2 = 0; i2 < 8; i2++) sB[cur ^ 1][fkb + i2][fr] = rb[i2];
        }
        __syncthreads();
    }
    // epilogue: pack sign bits (>0) into 32-bit words (warp wn owns one word per row)
#pragma unroll
    for (int t = 0; t < 4; t++)
#pragma unroll
        for (int h = 0; h < 2; h++) {
            unsigned m = 0;
#pragma unroll
            for (int u = 0; u < 4; u++)
#pragma unroll
                for (int vv = 0; vv < 2; vv++)
                    if (acc[t][u][h * 2 + vv] > 0.f) m |= 1u << (u * 8 + qid * 2 + vv);
            m |= __shfl_xor_sync(~0u, m, 1);
            m |= __shfl_xor_sync(~0u, m, 2);
            if (qid == 0) {
                int rl = wm * 64 + t * 16 + h * 8 + grp;
                g_bits[(size_t)(row0 + rl) * NW + (col0 >> 5) + wn] = m;
                srow[rl][wn] = m;
            }
        }
    if (row0 != col0) {
        __syncthreads();
        // transposed block: for each column j and row-word w, gather 32 bits
        for (int idx = tid; idx < 512; idx += 256) {
            int j = idx >> 2, wq = idx & 3;
            unsigned o = 0;
#pragma unroll
            for (int b = 0; b < 32; b++)
                o |= ((srow[wq * 32 + b][j >> 5] >> (j & 31)) & 1u) << b;
            g_bits[(size_t)(col0 + j) * NW + (row0 >> 5) + wq] = o;
        }
    }
}

// ---------------- NCE gram: exp row/col partial sums + diag, no G ----------------
// grid (n/128, n/128), block 256, 2 CTAs/SM
__global__ void __launch_bounds__(256, 2) k_mma_nt_nce(
    const float* __restrict__ F, const float* __restrict__ Gm, int n,
    float* __restrict__ RP, float* __restrict__ CP, float* __restrict__ diag)
{
    __shared__ float sA[2][16][132];
    __shared__ float sB[2][16][136];
    const int row0 = blockIdx.x * 128, col0 = blockIdx.y * 128;
    const int tid = threadIdx.x, lane = tid & 31, w = tid >> 5;
    const int wm = w >> 2, wn = w & 3, grp = lane >> 2, qid = lane & 3;

    float acc[4][4][4];
#pragma unroll
    for (int t = 0; t < 4; t++)
#pragma unroll
        for (int u = 0; u < 4; u++)
#pragma unroll
            for (int v = 0; v < 4; v++) acc[t][u][v] = 0.f;

    const int fr = tid >> 1, fkb = (tid & 1) * 8;
    float ra[8], rb[8];
    {
        const float* as_ = F + (size_t)(row0 + fr) * 128 + fkb;
        float4 a0 = *(const float4*)as_, a1 = *(const float4*)(as_ + 4);
        ra[0]=a0.x; ra[1]=a0.y; ra[2]=a0.z; ra[3]=a0.w; ra[4]=a1.x; ra[5]=a1.y; ra[6]=a1.z; ra[7]=a1.w;
        const float* bs_ = Gm + (size_t)(col0 + fr) * 128 + fkb;
        float4 b0 = *(const float4*)bs_, b1 = *(const float4*)(bs_ + 4);
        rb[0]=b0.x; rb[1]=b0.y; rb[2]=b0.z; rb[3]=b0.w; rb[4]=b1.x; rb[5]=b1.y; rb[6]=b1.z; rb[7]=b1.w;
    }
#pragma unroll
    for (int i = 0; i < 8; i++) sA[0][fkb + i][fr] = ra[i];
#pragma unroll
    for (int i = 0; i < 8; i++) sB[0][fkb + i][fr] = rb[i];
    __syncthreads();

    for (int it = 0; it < 8; ++it) {
        const int cur = it & 1;
        const bool more = it < 7;
        if (more) {
            int kt = (it + 1) * 16;
            const float* as_ = F + (size_t)(row0 + fr) * 128 + kt + fkb;
            float4 a0 = *(const float4*)as_, a1 = *(const float4*)(as_ + 4);
            ra[0]=a0.x; ra[1]=a0.y; ra[2]=a0.z; ra[3]=a0.w; ra[4]=a1.x; ra[5]=a1.y; ra[6]=a1.z; ra[7]=a1.w;
            const float* bs_ = Gm + (size_t)(col0 + fr) * 128 + kt + fkb;
            float4 b0 = *(const float4*)bs_, b1 = *(const float4*)(bs_ + 4);
            rb[0]=b0.x; rb[1]=b0.y; rb[2]=b0.z; rb[3]=b0.w; rb[4]=b1.x; rb[5]=b1.y; rb[6]=b1.z; rb[7]=b1.w;
        }
        mma_tile_1p(acc, sA[cur], sB[cur], wm, wn, grp, qid);
        if (more) {
#pragma unroll
            for (int i = 0; i < 8; i++) sA[cur ^ 1][fkb + i][fr] = ra[i];
#pragma unroll
            for (int i = 0; i < 8; i++) sB[cur ^ 1][fkb + i][fr] = rb[i];
        }
        __syncthreads();
    }

    // diag capture (raw), then exponentiate in place
    if (blockIdx.x == blockIdx.y) {
#pragma unroll
        for (int t = 0; t < 4; t++)
#pragma unroll
            for (int u = 0; u < 4; u++)
#pragma unroll
                for (int v = 0; v < 4; v++) {
                    int r = wm * 64 + t * 16 + (v >> 1) * 8 + grp;
                    int c = wn * 32 + u * 8 + qid * 2 + (v & 1);
                    if (r == c) diag[row0 + r] = acc[t][u][v];
                }
    }
#pragma unroll
    for (int t = 0; t < 4; t++)
#pragma unroll
        for (int u = 0; u < 4; u++)
#pragma unroll
            for (int v = 0; v < 4; v++)
                acc[t][u][v] = __expf(acc[t][u][v] * INVT - INVT);

    float* red = (float*)sA;
    // row partial sums (over this tile's 128 cols)
#pragma unroll
    for (int t = 0; t < 4; t++)
#pragma unroll
        for (int h = 0; h < 2; h++) {
            float rs = 0.f;
#pragma unroll
            for (int u = 0; u < 4; u++)
#pragma unroll
                for (int vv = 0; vv < 2; vv++) rs += acc[t][u][h * 2 + vv];
            rs += __shfl_xor_sync(~0u, rs, 1);
            rs += __shfl_xor_sync(~0u, rs, 2);
            if (qid == 0) red[wn * 128 + wm * 64 + t * 16 + h * 8 + grp] = rs;
        }
    __syncthreads();
    if (tid < 128)
        RP[(size_t)blockIdx.y * n + row0 + tid] = red[tid] + red[128 + tid] + red[256 + tid] + red[384 + tid];
    __syncthreads();
    // col partial sums (over this tile's 128 rows)
#pragma unroll
    for (int u = 0; u < 4; u++)
#pragma unroll
        for (int vv = 0; vv < 2; vv++) {
            float cs = 0.f;
#pragma unroll
            for (int t = 0; t < 4; t++)
#pragma unroll
                for (int h = 0; h < 2; h++) cs += acc[t][u][h * 2 + vv];
            cs += __shfl_xor_sync(~0u, cs, 4);
            cs += __shfl_xor_sync(~0u, cs, 8);
            cs += __shfl_xor_sync(~0u, cs, 16);
            if (grp == 0) red[wm * 128 + wn * 32 + u * 8 + qid * 2 + vv] = cs;
        }
    __syncthreads();
    if (tid < 128)
        CP[(size_t)blockIdx.x * n + col0 + tid] = red[tid] + red[128 + tid];
}

// ---------------- binary-adjacency GEMM: Y[M,128] = A_bits @ H[K,128] ----------------
// grid (M/128, K/Kchunk, 2), block 256, 2 CTAs/SM
__global__ void __launch_bounds__(256, 2) k_mma_bin(
    const unsigned* __restrict__ bits, int nw,
    const float* __restrict__ H0, const float* __restrict__ H1,
    float* __restrict__ P, int M, int Kchunk, int nsl)
{
    __shared__ float sA[2][16][132];
    __shared__ float sB[2][16][136];
    const float* H = blockIdx.z ? H1 : H0;
    const int row0 = blockIdx.x * 128;
    const int k0 = blockIdx.y * Kchunk;
    float* Pout = P + (size_t)(blockIdx.z * nsl + blockIdx.y) * ((size_t)M * 128);
    const int tid = threadIdx.x, lane = tid & 31, w = tid >> 5;
    const int wm = w >> 2, wn = w & 3, grp = lane >> 2, qid = lane & 3;

    float acc[4][4][4];
#pragma unroll
    for (int t = 0; t < 4; t++)
#pragma unroll
        for (int u = 0; u < 4; u++)
#pragma unroll
            for (int v = 0; v < 4; v++) acc[t][u][v] = 0.f;

    const int br = tid & 127, bkh = tid >> 7;       // A expansion: 2 threads/row, 8 bits each
    const int bk = tid >> 4, bnb = (tid & 15) * 8;  // B tile loader
    unsigned wreg; float rb[8];
    {
        wreg = bits[(size_t)(row0 + br) * nw + (k0 >> 5)];
        const float* bs_ = H + (size_t)(k0 + bk) * 128 + bnb;
        float4 b0 = *(const float4*)bs_, b1 = *(const float4*)(bs_ + 4);
        rb[0]=b0.x; rb[1]=b0.y; rb[2]=b0.z; rb[3]=b0.w; rb[4]=b1.x; rb[5]=b1.y; rb[6]=b1.z; rb[7]=b1.w;
    }
    const int nIter = Kchunk / 16;
    {
        int hs = (k0 & 16) + bkh * 8;
#pragma unroll
        for (int i = 0; i < 8; i++) sA[0][bkh * 8 + i][br] = ((wreg >> (hs + i)) & 1u) ? 1.0f : 0.0f;
#pragma unroll
        for (int i = 0; i < 8; i++) sB[0][bk][bnb + i] = rb[i];
    }
    __syncthreads();

    for (int it = 0; it < nIter; ++it) {
        const int cur = it & 1;
        const bool more = (it + 1) < nIter;
        int ktn = k0 + (it + 1) * 16;
        if (more) {
            wreg = bits[(size_t)(row0 + br) * nw + (ktn >> 5)];
            const float* bs_ = H + (size_t)(ktn + bk) * 128 + bnb;
            float4 b0 = *(const float4*)bs_, b1 = *(const float4*)(bs_ + 4);
            rb[0]=b0.x; rb[1]=b0.y; rb[2]=b0.z; rb[3]=b0.w; rb[4]=b1.x; rb[5]=b1.y; rb[6]=b1.z; rb[7]=b1.w;
        }
        mma_tile_1p(acc, sA[cur], sB[cur], wm, wn, grp, qid);
        if (more) {
            int hs = (ktn & 16) + bkh * 8;
#pragma unroll
            for (int i = 0; i < 8; i++) sA[cur ^ 1][bkh * 8 + i][br] = ((wreg >> (hs + i)) & 1u) ? 1.0f : 0.0f;
#pragma unroll
            for (int i = 0; i < 8; i++) sB[cur ^ 1][bk][bnb + i] = rb[i];
        }
        __syncthreads();
    }
#pragma unroll
    for (int t = 0; t < 4; t++) {
        int r = row0 + wm * 64 + t * 16 + grp;
#pragma unroll
        for (int u = 0; u < 4; u++) {
            int c = wn * 32 + u * 8 + qid * 2;
            *(float2*)(Pout + (size_t)r * 128 + c)       = make_float2(acc[t][u][0], acc[t][u][1]);
            *(float2*)(Pout + (size_t)(r + 8) * 128 + c) = make_float2(acc[t][u][2], acc[t][u][3]);
        }
    }
}

// ---------------- reduce partials + bias + l2norm (+optional concat copy) ----------------
// grid (M,1,2), block 128
__global__ void k_red_l2(const float* __restrict__ P, int nsl, int cnt,
                         const float* __restrict__ bias,
                         float* __restrict__ O0, float* __restrict__ O1,
                         float* __restrict__ C0, float* __restrict__ C1, int cld)
{
    int z = blockIdx.z, r = blockIdx.x, t = threadIdx.x;
    const float* Pz = P + (size_t)z * nsl * cnt;
    float s = bias[t];
    for (int k = 0; k < nsl; k++) s += Pz[(size_t)k * cnt + r * 128 + t];
    float q = s * s;
    for (int o = 16; o; o >>= 1) q += __shfl_xor_sync(~0u, q, o);
    __shared__ float ws[4];
    if ((t & 31) == 0) ws[t >> 5] = q;
    __syncthreads();
    float v = s * rsqrtf(ws[0] + ws[1] + ws[2] + ws[3]);
    float* O = z ? O1 : O0;
    O[(size_t)r * 128 + t] = v;
    if (C0) { float* C = z ? C1 : C0; C[(size_t)r * cld + t] = v; }
}

// ---------------- reduce partials with D^-1/2 row scale; writes into concat at offset ----------------
__global__ void k_reduce_s(const float* __restrict__ P, int nsl, int cnt,
                           float* __restrict__ O0, float* __restrict__ O1, int oldd, int ooff,
                           float* __restrict__ S0, float* __restrict__ S1,
                           const float* __restrict__ dinv)
{
    int z = blockIdx.z;
    float* O = z ? O1 : O0;
    const float* Pz = P + (size_t)z * nsl * cnt;
    int i = blockIdx.x * 256 + threadIdx.x;
    float s = 0.f;
    for (int k = 0; k < nsl; k++) s += Pz[(size_t)k * cnt + i];
    int r = i >> 7, c = i & 127;
    float d = dinv[r];
    O[(size_t)r * oldd + ooff + c] = d * s;
    if (S0) { float* S = z ? S1 : S0; S[i] = d * d * s; }
}

// ---------------- degree (popc) + D^-1/2 scale, grid (NN), block 256 (both z) ----------------
__global__ void k_dinv_scale()
{
    int r = blockIdx.x, t = threadIdx.x;
    __shared__ float sh[2];
    float c = 0.f;
    if (t < 64) c = (float)__popc(g_bits[r * NW + t]);
    for (int o = 16; o; o >>= 1) c += __shfl_xor_sync(~0u, c, o);
    if (t < 64 && (t & 31) == 0) sh[t >> 5] = c;
    __syncthreads();
    float dinv = rsqrtf(sh[0] + sh[1]);
    int z = t >> 7, tc = t & 127;
    const float* F = z ? g_fes : g_fet;
    g_hs[z][(size_t)r * 128 + tc] = F[(size_t)r * 128 + tc] * dinv;
    if (t == 0) g_dinv[r] = dinv;
}

// ---------------- scores + top-1024 in one block ----------------
__global__ void k_pool1(const float* __restrict__ Wp, const float* __restrict__ bp)
{
    __shared__ float sv[2048];
    __shared__ int   si[2048];
    int t = threadIdx.x, lane = t & 31, w = t >> 5;
    float w0 = Wp[lane], w1 = Wp[lane + 32], w2 = Wp[lane + 64], w3 = Wp[lane + 96];
    float bb = bp[0];
    for (int r = w; r < NN; r += 32) {
        const float* x = g_fg[0] + (size_t)r * DD;
        float s = x[lane] * w0 + x[lane + 32] * w1 + x[lane + 64] * w2 + x[lane + 96] * w3;
        for (int o = 16; o; o >>= 1) s += __shfl_xor_sync(~0u, s, o);
        if (lane == 0) { sv[r] = 1.f / (1.f + __expf(-(s + bb))); si[r] = r; }
    }
    __syncthreads();
    for (int k = 2; k <= 2048; k <<= 1)
        for (int j = k >> 1; j > 0; j >>= 1) {
            int i = ((t & ~(j - 1)) << 1) | (t & (j - 1));
            int p = i | j;
            float a = sv[i], b = sv[p];
            int ia = si[i], ib = si[p];
            bool agtb = (a > b) || (a == b && ia < ib);
            bool up = ((i & k) == 0);
            if (up ^ agtb) { sv[i] = b; sv[p] = a; si[i] = ib; si[p] = ia; }
            __syncthreads();
        }
    g_vals[t] = sv[t];
    g_idx[t] = si[t];
}

// ---------------- pooled 2-hop adjacency bits + dinvp, one row per block ----------------
__global__ void k_pool2()
{
    __shared__ unsigned sbi[NW];
    __shared__ int ws[8];
    int i = blockIdx.x, t = threadIdx.x;
    const unsigned* bi = g_bits + (size_t)g_idx[i] * NW;
    if (t < NW) sbi[t] = bi[t];
    __syncthreads();
    int cnt = 0;
    for (int jb = 0; jb < KP; jb += 256) {
        int j = jb + t;
        const unsigned* bj = g_bits + (size_t)g_idx[j] * NW;
        bool c = false;
        for (int w = 0; w < NW && !c; w++) c = (sbi[w] & bj[w]) != 0u;
        unsigned word = __ballot_sync(~0u, c);
        cnt += c ? 1 : 0;
        if ((t & 31) == 0) g_bitsp[i * NWP + (j >> 5)] = word;
    }
    for (int o = 16; o; o >>= 1) cnt += __shfl_xor_sync(~0u, cnt, o);
    if ((t & 31) == 0) ws[t >> 5] = cnt;
    __syncthreads();
    if (t == 0) {
        int s = 0;
        for (int k = 0; k < 8; k++) s += ws[k];
        g_dinvp[i] = rsqrtf((float)s);
    }
}

// ---------------- gather pooled features (+concat copy + D^-1/2 scale) ----------------
__global__ void k_gather()
{
    int z = blockIdx.z;
    int gi = blockIdx.x * 256 + threadIdx.x;
    int r = gi >> 7, c = gi & 127;
    float v = g_fg[z][(size_t)g_idx[r] * DD + c] * g_vals[r];
    g_catp[z][(size_t)r * 256 + c] = v;
    g_nhs[z][gi] = v * g_dinvp[r];
}

// ---------------- final: NCE combine for both stages + scalar ----------------
__global__ void k_final(float* __restrict__ out)
{
    int t = threadIdx.x;   // 1024 threads
    float sg = 0.f, sp = 0.f;
    for (int i = t; i < NN; i += 1024) {
        float s1 = 0.f, s2 = 0.f;
        for (int k = 0; k < 16; k++) { s1 += g_rp[k * NN + i]; s2 += g_cp[k * NN + i]; }
        sg += 2.f * INVT + __logf(s1) + __logf(s2) - 2.f * g_diag[i] * INVT;
    }
    {
        int i = t;
        float s1 = 0.f, s2 = 0.f;
        for (int k = 0; k < 8; k++) { s1 += g_rp2[k * KP + i]; s2 += g_cp2[k * KP + i]; }
        sp += 2.f * INVT + __logf(s1) + __logf(s2) - 2.f * g_diagp[i] * INVT;
    }
    for (int o = 16; o; o >>= 1) {
        sg += __shfl_xor_sync(~0u, sg, o);
        sp += __shfl_xor_sync(~0u, sp, o);
    }
    __shared__ float wg[32], wp[32];
    if ((t & 31) == 0) { wg[t >> 5] = sg; wp[t >> 5] = sp; }
    __syncthreads();
    if (t == 0) {
        float a = 0.f, b = 0.f;
        for (int i = 0; i < 32; i++) { a += wg[i]; b += wp[i]; }
        out[0] = a * (1.f / NN) + b * (1.f / KP);
    }
}

// ---------------- host ----------------
extern "C" void kernel_launch(void* const* d_in, const int* in_sizes, int n_in,
                              void* d_out, int out_size)
{
    (void)in_sizes; (void)n_in; (void)out_size;
    const float* fs    = (const float*)d_in[0];
    const float* ft    = (const float*)d_in[1];
    const float* We    = (const float*)d_in[2];
    const float* be    = (const float*)d_in[3];
    const float* Wg    = (const float*)d_in[4];
    const float* bg    = (const float*)d_in[5];
    const float* Wpool = (const float*)d_in[6];
    const float* bpool = (const float*)d_in[7];
    const float* Wgp   = (const float*)d_in[8];
    const float* bgp   = (const float*)d_in[9];

    void* p;
    cudaGetSymbolAddress(&p, g_fet);   float* FET  = (float*)p;
    cudaGetSymbolAddress(&p, g_fes);   float* FES  = (float*)p;
    cudaGetSymbolAddress(&p, g_bits);  unsigned* BITS  = (unsigned*)p;
    cudaGetSymbolAddress(&p, g_bitsp); unsigned* BITSP = (unsigned*)p;
    cudaGetSymbolAddress(&p, g_dinv);  float* DINV  = (float*)p;
    cudaGetSymbolAddress(&p, g_dinvp); float* DINVP = (float*)p;
    cudaGetSymbolAddress(&p, g_hs);    float* HS   = (float*)p;
    cudaGetSymbolAddress(&p, g_nhs);   float* NHS  = (float*)p;
    cudaGetSymbolAddress(&p, g_fg);    float* FG   = (float*)p;
    cudaGetSymbolAddress(&p, g_fp);    float* FP   = (float*)p;
    cudaGetSymbolAddress(&p, g_cat);   float* CAT  = (float*)p;
    cudaGetSymbolAddress(&p, g_catp);  float* CATP = (float*)p;
    cudaGetSymbolAddress(&p, g_part);  float* PART = (float*)p;
    cudaGetSymbolAddress(&p, g_rp);    float* RP   = (float*)p;
    cudaGetSymbolAddress(&p, g_cp);    float* CP   = (float*)p;
    cudaGetSymbolAddress(&p, g_rp2);   float* RP2  = (float*)p;
    cudaGetSymbolAddress(&p, g_cp2);   float* CP2  = (float*)p;
    cudaGetSymbolAddress(&p, g_diag);  float* DG1  = (float*)p;
    cudaGetSymbolAddress(&p, g_diagp); float* DG2  = (float*)p;

    const int ND = NN * DD;    // 262144
    const int KD = KP * DD;    // 131072
    const int CATLD = 384, CATPLD = 256;

    // fork/join resources (created per call; kernel_launch is invoked only a few
    // times outside the timed graph replays, so the handle cost is negligible)
    cudaStream_t sB;
    cudaEvent_t evF, evJ;
    cudaStreamCreateWithFlags(&sB, cudaStreamNonBlocking);
    cudaEventCreateWithFlags(&evF, cudaEventDisableTiming);
    cudaEventCreateWithFlags(&evJ, cudaEventDisableTiming);

    // 1) embed: f = l2norm(x @ We + be); z=0 teacher(ft), z=1 student(fs)
    k_mma_nn<<<dim3(16, 8, 2), 256>>>(ft, fs, CD, We, PART, NN, 64, 8);
    k_red_l2<<<dim3(NN, 1, 2), 128>>>(PART, 8, ND, be, FET, FES, CAT, CAT + NN * CATLD, CATLD);

    // 2) adjacency bits from teacher gram (symmetric: 136 upper-triangle tiles)
    k_mma_nt_adj<<<136, 256>>>(FET);
    k_dinv_scale<<<NN, 256>>>();

    // 3) TAGConv k=2 via binary MMA: h_{i+1} = D^-1/2 A (D^-1/2 h_i)
    k_mma_bin<<<dim3(16, 8, 2), 256>>>(BITS, NW, HS, HS + ND, PART, NN, 256, 8);
    k_reduce_s<<<dim3(ND / 256, 1, 2), 256>>>(PART, 8, ND, CAT, CAT + NN * CATLD, CATLD, 128, HS, HS + ND, DINV);
    k_mma_bin<<<dim3(16, 8, 2), 256>>>(BITS, NW, HS, HS + ND, PART, NN, 256, 8);
    k_reduce_s<<<dim3(ND / 256, 1, 2), 256>>>(PART, 8, ND, CAT, CAT + NN * CATLD, CATLD, 256, (float*)0, (float*)0, DINV);

    // 4) concat GEMM (K=384, Kchunk=96 -> 4 slots) + bias + l2norm -> FG
    k_mma_nn<<<dim3(16, 4, 2), 256>>>(CAT, CAT + NN * CATLD, CATLD, Wg, PART, NN, 96, 4);
    k_red_l2<<<dim3(NN, 1, 2), 128>>>(PART, 4, ND, bg, FG, FG + ND, (float*)0, (float*)0, 0);

    // 5) stage-1 NCE on side stream, overlapped with the pooling chain
    cudaEventRecord(evF, 0);
    cudaStreamWaitEvent(sB, evF, 0);
    k_mma_nt_nce<<<dim3(16, 16), 256, 0, sB>>>(FG, FG + ND, NN, RP, CP, DG1);
    cudaEventRecord(evJ, sB);

    // 6) pooling: scores+topk, subbits+dinvp, gather (default stream, concurrent with NCE1)
    k_pool1<<<1, 1024>>>(Wpool, bpool);
    k_pool2<<<KP, 256>>>();
    k_gather<<<dim3(KD / 256, 1, 2), 256>>>();

    // 7) pooled TAGConv k=1
    k_mma_bin<<<dim3(8, 4, 2), 256>>>(BITSP, NWP, NHS, NHS + KD, PART, KP, 256, 4);
    k_reduce_s<<<dim3(KD / 256, 1, 2), 256>>>(PART, 4, KD, CATP, CATP + KP * CATPLD, CATPLD, 128, (float*)0, (float*)0, DINVP);
    k_mma_nn<<<dim3(8, 2, 2), 256>>>(CATP, CATP + KP * CATPLD, CATPLD, Wgp, PART, KP, 128, 2);
    k_red_l2<<<dim3(KP, 1, 2), 128>>>(PART, 2, KD, bgp, FP, FP + KD, (float*)0, (float*)0, 0);

    // 8) pooled NCE
    k_mma_nt_nce<<<dim3(8, 8), 256>>>(FP, FP + KD, KP, RP2, CP2, DG2);

    // 9) join + NCE combine (both stages) + final scalar
    cudaStreamWaitEvent(0, evJ, 0);
    k_final<<<1, 1024>>>((float*)d_out);
}

// round 6
// speedup vs baseline: 2.9692x; 1.2201x over previous
#include <cuda_runtime.h>
#include <math.h>

// ---------------- problem constants ----------------
#define NN 2048
#define CD 512
#define DD 128
#define KP 1024
#define NW 64            // 2048 bits / 32
#define NWP 32           // 1024 bits / 32
#define INVT 14.285714285714286f

// ---------------- device scratch ----------------
__device__ __align__(16) float g_fet[NN*DD];
__device__ __align__(16) float g_fes[NN*DD];
__device__ unsigned g_bits[NN*NW];
__device__ unsigned g_bitsp[KP*NWP];
__device__ float g_dinv[NN];
__device__ float g_dinvp[KP];
__device__ __align__(16) float g_fg[2][NN*DD];     // [0]=teacher,[1]=student
__device__ __align__(16) float g_fp[2][KP*DD];
__device__ __align__(16) float g_cat[2][NN*384];   // concat [h0|h1|h2]
__device__ __align__(16) float g_catp[2][KP*256];  // pooled concat [newh|h1p]
__device__ float g_scores[NN];
__device__ int   g_idx[KP];
__device__ float g_vals[KP];
__device__ __align__(16) float g_part[16][NN*DD];  // split-K partials
__device__ float g_rp[16*NN], g_cp[16*NN], g_diag[NN];
__device__ float g_rp2[8*KP], g_cp2[8*KP], g_diagp[KP];

// ---------------- tf32 helpers ----------------
__device__ __forceinline__ unsigned f2tf(float x) {
    unsigned r; asm("cvt.rna.tf32.f32 %0, %1;" : "=r"(r) : "f"(x)); return r;
}
__device__ __forceinline__ void mma8(float c[4], unsigned a0, unsigned a1, unsigned a2, unsigned a3,
                                     unsigned b0, unsigned b1) {
    asm volatile("mma.sync.aligned.m16n8k8.row.col.f32.tf32.tf32.f32 "
                 "{%0,%1,%2,%3}, {%4,%5,%6,%7}, {%8,%9}, {%0,%1,%2,%3};\n"
                 : "+f"(c[0]), "+f"(c[1]), "+f"(c[2]), "+f"(c[3])
                 : "r"(a0), "r"(a1), "r"(a2), "r"(a3), "r"(b0), "r"(b1));
}

// ---- MMA over one 16-K stage, 3-pass tf32 split (fp32-accurate) ----
__device__ __forceinline__ void mma_tile_split(
    float acc[4][4][4], const float (*__restrict__ sa)[132], const float (*__restrict__ sb)[136],
    int wm, int wn, int grp, int qid)
{
#pragma unroll
    for (int kk = 0; kk < 16; kk += 8) {
        float araw[4][4], braw[4][2];
        unsigned ah[4][4], bh[4][2];
#pragma unroll
        for (int t = 0; t < 4; t++) {
            int r = wm*64 + t*16 + grp;
            araw[t][0] = sa[kk+qid][r];   araw[t][1] = sa[kk+qid][r+8];
            araw[t][2] = sa[kk+qid+4][r]; araw[t][3] = sa[kk+qid+4][r+8];
#pragma unroll
            for (int j = 0; j < 4; j++) ah[t][j] = f2tf(araw[t][j]);
        }
#pragma unroll
        for (int u = 0; u < 4; u++) {
            int c = wn*32 + u*8 + grp;
            braw[u][0] = sb[kk+qid][c]; braw[u][1] = sb[kk+qid+4][c];
            bh[u][0] = f2tf(braw[u][0]); bh[u][1] = f2tf(braw[u][1]);
        }
#pragma unroll
        for (int t = 0; t < 4; t++)
#pragma unroll
            for (int u = 0; u < 4; u++)
                mma8(acc[t][u], ah[t][0],ah[t][1],ah[t][2],ah[t][3], bh[u][0],bh[u][1]);
        {
            unsigned bl[4][2];
#pragma unroll
            for (int u = 0; u < 4; u++) {
                bl[u][0] = f2tf(braw[u][0] - __uint_as_float(bh[u][0]));
                bl[u][1] = f2tf(braw[u][1] - __uint_as_float(bh[u][1]));
            }
#pragma unroll
            for (int t = 0; t < 4; t++)
#pragma unroll
                for (int u = 0; u < 4; u++)
                    mma8(acc[t][u], ah[t][0],ah[t][1],ah[t][2],ah[t][3], bl[u][0],bl[u][1]);
        }
        {
            unsigned al[4][4];
#pragma unroll
            for (int t = 0; t < 4; t++)
#pragma unroll
                for (int j = 0; j < 4; j++)
                    al[t][j] = f2tf(araw[t][j] - __uint_as_float(ah[t][j]));
#pragma unroll
            for (int t = 0; t < 4; t++)
#pragma unroll
                for (int u = 0; u < 4; u++)
                    mma8(acc[t][u], al[t][0],al[t][1],al[t][2],al[t][3], bh[u][0],bh[u][1]);
        }
    }
}

// ---- MMA over one 16-K stage, single-pass tf32 ----
__device__ __forceinline__ void mma_tile_1p(
    float acc[4][4][4], const float (*__restrict__ sa)[132], const float (*__restrict__ sb)[136],
    int wm, int wn, int grp, int qid)
{
#pragma unroll
    for (int kk = 0; kk < 16; kk += 8) {
        unsigned ah[4][4], bh[4][2];
#pragma unroll
        for (int t = 0; t < 4; t++) {
            int r = wm*64 + t*16 + grp;
            ah[t][0] = f2tf(sa[kk+qid][r]);   ah[t][1] = f2tf(sa[kk+qid][r+8]);
            ah[t][2] = f2tf(sa[kk+qid+4][r]); ah[t][3] = f2tf(sa[kk+qid+4][r+8]);
        }
#pragma unroll
        for (int u = 0; u < 4; u++) {
            int c = wn*32 + u*8 + grp;
            bh[u][0] = f2tf(sb[kk+qid][c]); bh[u][1] = f2tf(sb[kk+qid+4][c]);
        }
#pragma unroll
        for (int t = 0; t < 4; t++)
#pragma unroll
            for (int u = 0; u < 4; u++)
                mma8(acc[t][u], ah[t][0],ah[t][1],ah[t][2],ah[t][3], bh[u][0],bh[u][1]);
    }
}

// ---------------- NN GEMM, split-tf32, double-buffered: C[M,128]=A[M,K]@B[K,128] ----------------
// grid (M/128, K/Kchunk, 2), block 256
__global__ void __launch_bounds__(256) k_mma_nn(
    const float* __restrict__ A0, const float* __restrict__ A1, int lda,
    const float* __restrict__ B,
    float* __restrict__ P, int M, int Kchunk, int nsl)
{
    __shared__ float sA[2][16][132];
    __shared__ float sB[2][16][136];
    const float* A = blockIdx.z ? A1 : A0;
    const int row0 = blockIdx.x * 128;
    const int k0 = blockIdx.y * Kchunk;
    float* Pout = P + (size_t)(blockIdx.z * nsl + blockIdx.y) * ((size_t)M * 128);
    const int tid = threadIdx.x, lane = tid & 31, w = tid >> 5;
    const int wm = w >> 2, wn = w & 3, grp = lane >> 2, qid = lane & 3;

    float acc[4][4][4];
#pragma unroll
    for (int t = 0; t < 4; t++)
#pragma unroll
        for (int u = 0; u < 4; u++)
#pragma unroll
            for (int v = 0; v < 4; v++) acc[t][u][v] = 0.f;

    const int ar = tid >> 1, akb = (tid & 1) * 8;
    const int bk = tid >> 4, bnb = (tid & 15) * 8;
    float ra[8], rb[8];

    {
        const float* as_ = A + (size_t)(row0 + ar) * lda + k0 + akb;
        float4 a0 = *(const float4*)as_, a1 = *(const float4*)(as_ + 4);
        ra[0]=a0.x; ra[1]=a0.y; ra[2]=a0.z; ra[3]=a0.w; ra[4]=a1.x; ra[5]=a1.y; ra[6]=a1.z; ra[7]=a1.w;
        const float* bs_ = B + (size_t)(k0 + bk) * 128 + bnb;
        float4 b0 = *(const float4*)bs_, b1 = *(const float4*)(bs_ + 4);
        rb[0]=b0.x; rb[1]=b0.y; rb[2]=b0.z; rb[3]=b0.w; rb[4]=b1.x; rb[5]=b1.y; rb[6]=b1.z; rb[7]=b1.w;
    }
    const int nIter = Kchunk / 16;
#pragma unroll
    for (int i = 0; i < 8; i++) sA[0][akb + i][ar] = ra[i];
#pragma unroll
    for (int i = 0; i < 8; i++) sB[0][bk][bnb + i] = rb[i];
    __syncthreads();

    for (int it = 0; it < nIter; ++it) {
        const int cur = it & 1;
        const bool more = (it + 1) < nIter;
        if (more) {
            int kt = k0 + (it + 1) * 16;
            const float* as_ = A + (size_t)(row0 + ar) * lda + kt + akb;
            float4 a0 = *(const float4*)as_, a1 = *(const float4*)(as_ + 4);
            ra[0]=a0.x; ra[1]=a0.y; ra[2]=a0.z; ra[3]=a0.w; ra[4]=a1.x; ra[5]=a1.y; ra[6]=a1.z; ra[7]=a1.w;
            const float* bs_ = B + (size_t)(kt + bk) * 128 + bnb;
            float4 b0 = *(const float4*)bs_, b1 = *(const float4*)(bs_ + 4);
            rb[0]=b0.x; rb[1]=b0.y; rb[2]=b0.z; rb[3]=b0.w; rb[4]=b1.x; rb[5]=b1.y; rb[6]=b1.z; rb[7]=b1.w;
        }
        mma_tile_split(acc, sA[cur], sB[cur], wm, wn, grp, qid);
        if (more) {
#pragma unroll
            for (int i = 0; i < 8; i++) sA[cur ^ 1][akb + i][ar] = ra[i];
#pragma unroll
            for (int i = 0; i < 8; i++) sB[cur ^ 1][bk][bnb + i] = rb[i];
        }
        __syncthreads();
    }
#pragma unroll
    for (int t = 0; t < 4; t++) {
        int r = row0 + wm * 64 + t * 16 + grp;
#pragma unroll
        for (int u = 0; u < 4; u++) {
            int c = wn * 32 + u * 8 + qid * 2;
            *(float2*)(Pout + (size_t)r * 128 + c)       = make_float2(acc[t][u][0], acc[t][u][1]);
            *(float2*)(Pout + (size_t)(r + 8) * 128 + c) = make_float2(acc[t][u][2], acc[t][u][3]);
        }
    }
}

// ---------------- adjacency gram (SYMMETRIC): bits = (F F^T > 0), upper-triangle tiles only ----------------
// grid (136), block 256.  Off-diagonal tiles also emit the transposed bit-block.
__global__ void __launch_bounds__(256) k_mma_nt_adj(const float* __restrict__ F)
{
    __shared__ float sA[2][16][132];
    __shared__ float sB[2][16][136];
    __shared__ unsigned srow[128][5];
    int i = blockIdx.x;
    int by = (int)((sqrtf(8.f * i + 1.f) - 1.f) * 0.5f);
    while ((by + 1) * (by + 2) / 2 <= i) by++;
    while (by * (by + 1) / 2 > i) by--;
    int bx = i - by * (by + 1) / 2;
    const int row0 = bx * 128, col0 = by * 128;
    const int tid = threadIdx.x, lane = tid & 31, w = tid >> 5;
    const int wm = w >> 2, wn = w & 3, grp = lane >> 2, qid = lane & 3;

    float acc[4][4][4];
#pragma unroll
    for (int t = 0; t < 4; t++)
#pragma unroll
        for (int u = 0; u < 4; u++)
#pragma unroll
            for (int v = 0; v < 4; v++) acc[t][u][v] = 0.f;

    const int fr = tid >> 1, fkb = (tid & 1) * 8;
    float ra[8], rb[8];
    {
        const float* as_ = F + (size_t)(row0 + fr) * 128 + fkb;
        float4 a0 = *(const float4*)as_, a1 = *(const float4*)(as_ + 4);
        ra[0]=a0.x; ra[1]=a0.y; ra[2]=a0.z; ra[3]=a0.w; ra[4]=a1.x; ra[5]=a1.y; ra[6]=a1.z; ra[7]=a1.w;
        const float* bs_ = F + (size_t)(col0 + fr) * 128 + fkb;
        float4 b0 = *(const float4*)bs_, b1 = *(const float4*)(bs_ + 4);
        rb[0]=b0.x; rb[1]=b0.y; rb[2]=b0.z; rb[3]=b0.w; rb[4]=b1.x; rb[5]=b1.y; rb[6]=b1.z; rb[7]=b1.w;
    }
#pragma unroll
    for (int i2 = 0; i2 < 8; i2++) sA[0][fkb + i2][fr] = ra[i2];
#pragma unroll
    for (int i2 = 0; i2 < 8; i2++) sB[0][fkb + i2][fr] = rb[i2];
    __syncthreads();

    for (int it = 0; it < 8; ++it) {
        const int cur = it & 1;
        const bool more = it < 7;
        if (more) {
            int kt = (it + 1) * 16;
            const float* as_ = F + (size_t)(row0 + fr) * 128 + kt + fkb;
            float4 a0 = *(const float4*)as_, a1 = *(const float4*)(as_ + 4);
            ra[0]=a0.x; ra[1]=a0.y; ra[2]=a0.z; ra[3]=a0.w; ra[4]=a1.x; ra[5]=a1.y; ra[6]=a1.z; ra[7]=a1.w;
            const float* bs_ = F + (size_t)(col0 + fr) * 128 + kt + fkb;
            float4 b0 = *(const float4*)bs_, b1 = *(const float4*)(bs_ + 4);
            rb[0]=b0.x; rb[1]=b0.y; rb[2]=b0.z; rb[3]=b0.w; rb[4]=b1.x; rb[5]=b1.y; rb[6]=b1.z; rb[7]=b1.w;
        }
        mma_tile_split(acc, sA[cur], sB[cur], wm, wn, grp, qid);
        if (more) {
#pragma unroll
            for (int i2 = 0; i2 < 8; i2++) sA[cur ^ 1][fkb + i2][fr] = ra[i2];
#pragma unroll
            for (int i2 = 0; i2 < 8; i2++) sB[cur ^ 1][fkb + i2][fr] = rb[i2];
        }
        __syncthreads();
    }
#pragma unroll
    for (int t = 0; t < 4; t++)
#pragma unroll
        for (int h = 0; h < 2; h++) {
            unsigned m = 0;
#pragma unroll
            for (int u = 0; u < 4; u++)
#pragma unroll
                for (int vv = 0; vv < 2; vv++)
                    if (acc[t][u][h * 2 + vv] > 0.f) m |= 1u << (u * 8 + qid * 2 + vv);
            m |= __shfl_xor_sync(~0u, m, 1);
            m |= __shfl_xor_sync(~0u, m, 2);
            if (qid == 0) {
                int rl = wm * 64 + t * 16 + h * 8 + grp;
                g_bits[(size_t)(row0 + rl) * NW + (col0 >> 5) + wn] = m;
                srow[rl][wn] = m;
            }
        }
    if (row0 != col0) {
        __syncthreads();
        for (int idx = tid; idx < 512; idx += 256) {
            int j = idx >> 2, wq = idx & 3;
            unsigned o = 0;
#pragma unroll
            for (int b = 0; b < 32; b++)
                o |= ((srow[wq * 32 + b][j >> 5] >> (j & 31)) & 1u) << b;
            g_bits[(size_t)(col0 + j) * NW + (row0 >> 5) + wq] = o;
        }
    }
}

// ---------------- NCE gram: exp row/col partial sums + diag, no G ----------------
// grid (n/128, n/128), block 256, 2 CTAs/SM
__global__ void __launch_bounds__(256, 2) k_mma_nt_nce(
    const float* __restrict__ F, const float* __restrict__ Gm, int n,
    float* __restrict__ RP, float* __restrict__ CP, float* __restrict__ diag)
{
    __shared__ float sA[2][16][132];
    __shared__ float sB[2][16][136];
    const int row0 = blockIdx.x * 128, col0 = blockIdx.y * 128;
    const int tid = threadIdx.x, lane = tid & 31, w = tid >> 5;
    const int wm = w >> 2, wn = w & 3, grp = lane >> 2, qid = lane & 3;

    float acc[4][4][4];
#pragma unroll
    for (int t = 0; t < 4; t++)
#pragma unroll
        for (int u = 0; u < 4; u++)
#pragma unroll
            for (int v = 0; v < 4; v++) acc[t][u][v] = 0.f;

    const int fr = tid >> 1, fkb = (tid & 1) * 8;
    float ra[8], rb[8];
    {
        const float* as_ = F + (size_t)(row0 + fr) * 128 + fkb;
        float4 a0 = *(const float4*)as_, a1 = *(const float4*)(as_ + 4);
        ra[0]=a0.x; ra[1]=a0.y; ra[2]=a0.z; ra[3]=a0.w; ra[4]=a1.x; ra[5]=a1.y; ra[6]=a1.z; ra[7]=a1.w;
        const float* bs_ = Gm + (size_t)(col0 + fr) * 128 + fkb;
        float4 b0 = *(const float4*)bs_, b1 = *(const float4*)(bs_ + 4);
        rb[0]=b0.x; rb[1]=b0.y; rb[2]=b0.z; rb[3]=b0.w; rb[4]=b1.x; rb[5]=b1.y; rb[6]=b1.z; rb[7]=b1.w;
    }
#pragma unroll
    for (int i = 0; i < 8; i++) sA[0][fkb + i][fr] = ra[i];
#pragma unroll
    for (int i = 0; i < 8; i++) sB[0][fkb + i][fr] = rb[i];
    __syncthreads();

    for (int it = 0; it < 8; ++it) {
        const int cur = it & 1;
        const bool more = it < 7;
        if (more) {
            int kt = (it + 1) * 16;
            const float* as_ = F + (size_t)(row0 + fr) * 128 + kt + fkb;
            float4 a0 = *(const float4*)as_, a1 = *(const float4*)(as_ + 4);
            ra[0]=a0.x; ra[1]=a0.y; ra[2]=a0.z; ra[3]=a0.w; ra[4]=a1.x; ra[5]=a1.y; ra[6]=a1.z; ra[7]=a1.w;
            const float* bs_ = Gm + (size_t)(col0 + fr) * 128 + kt + fkb;
            float4 b0 = *(const float4*)bs_, b1 = *(const float4*)(bs_ + 4);
            rb[0]=b0.x; rb[1]=b0.y; rb[2]=b0.z; rb[3]=b0.w; rb[4]=b1.x; rb[5]=b1.y; rb[6]=b1.z; rb[7]=b1.w;
        }
        mma_tile_1p(acc, sA[cur], sB[cur], wm, wn, grp, qid);
        if (more) {
#pragma unroll
            for (int i = 0; i < 8; i++) sA[cur ^ 1][fkb + i][fr] = ra[i];
#pragma unroll
            for (int i = 0; i < 8; i++) sB[cur ^ 1][fkb + i][fr] = rb[i];
        }
        __syncthreads();
    }

    if (blockIdx.x == blockIdx.y) {
#pragma unroll
        for (int t = 0; t < 4; t++)
#pragma unroll
            for (int u = 0; u < 4; u++)
#pragma unroll
                for (int v = 0; v < 4; v++) {
                    int r = wm * 64 + t * 16 + (v >> 1) * 8 + grp;
                    int c = wn * 32 + u * 8 + qid * 2 + (v & 1);
                    if (r == c) diag[row0 + r] = acc[t][u][v];
                }
    }
#pragma unroll
    for (int t = 0; t < 4; t++)
#pragma unroll
        for (int u = 0; u < 4; u++)
#pragma unroll
            for (int v = 0; v < 4; v++)
                acc[t][u][v] = __expf(acc[t][u][v] * INVT - INVT);

    float* red = (float*)sA;
#pragma unroll
    for (int t = 0; t < 4; t++)
#pragma unroll
        for (int h = 0; h < 2; h++) {
            float rs = 0.f;
#pragma unroll
            for (int u = 0; u < 4; u++)
#pragma unroll
                for (int vv = 0; vv < 2; vv++) rs += acc[t][u][h * 2 + vv];
            rs += __shfl_xor_sync(~0u, rs, 1);
            rs += __shfl_xor_sync(~0u, rs, 2);
            if (qid == 0) red[wn * 128 + wm * 64 + t * 16 + h * 8 + grp] = rs;
        }
    __syncthreads();
    if (tid < 128)
        RP[(size_t)blockIdx.y * n + row0 + tid] = red[tid] + red[128 + tid] + red[256 + tid] + red[384 + tid];
    __syncthreads();
#pragma unroll
    for (int u = 0; u < 4; u++)
#pragma unroll
        for (int vv = 0; vv < 2; vv++) {
            float cs = 0.f;
#pragma unroll
            for (int t = 0; t < 4; t++)
#pragma unroll
                for (int h = 0; h < 2; h++) cs += acc[t][u][h * 2 + vv];
            cs += __shfl_xor_sync(~0u, cs, 4);
            cs += __shfl_xor_sync(~0u, cs, 8);
            cs += __shfl_xor_sync(~0u, cs, 16);
            if (grp == 0) red[wm * 128 + wn * 32 + u * 8 + qid * 2 + vv] = cs;
        }
    __syncthreads();
    if (tid < 128)
        CP[(size_t)blockIdx.x * n + col0 + tid] = red[tid] + red[128 + tid];
}

// ---------------- binary-adjacency GEMM: Y[M,128] = A_bits @ (dinv ⊙ H[K,:]) ----------------
// grid (M/128, K/Kchunk, 2), block 256, 2 CTAs/SM.  dinv row-scale folded into B loader.
__global__ void __launch_bounds__(256, 2) k_mma_bin(
    const unsigned* __restrict__ bits, int nw,
    const float* __restrict__ H0, const float* __restrict__ H1, int ldh,
    const float* __restrict__ dinv,
    float* __restrict__ P, int M, int Kchunk, int nsl)
{
    __shared__ float sA[2][16][132];
    __shared__ float sB[2][16][136];
    const float* H = blockIdx.z ? H1 : H0;
    const int row0 = blockIdx.x * 128;
    const int k0 = blockIdx.y * Kchunk;
    float* Pout = P + (size_t)(blockIdx.z * nsl + blockIdx.y) * ((size_t)M * 128);
    const int tid = threadIdx.x, lane = tid & 31, w = tid >> 5;
    const int wm = w >> 2, wn = w & 3, grp = lane >> 2, qid = lane & 3;

    float acc[4][4][4];
#pragma unroll
    for (int t = 0; t < 4; t++)
#pragma unroll
        for (int u = 0; u < 4; u++)
#pragma unroll
            for (int v = 0; v < 4; v++) acc[t][u][v] = 0.f;

    const int br = tid & 127, bkh = tid >> 7;
    const int bk = tid >> 4, bnb = (tid & 15) * 8;
    unsigned wreg; float rb[8];
    {
        wreg = bits[(size_t)(row0 + br) * nw + (k0 >> 5)];
        float dv = dinv[k0 + bk];
        const float* bs_ = H + (size_t)(k0 + bk) * ldh + bnb;
        float4 b0 = *(const float4*)bs_, b1 = *(const float4*)(bs_ + 4);
        rb[0]=b0.x*dv; rb[1]=b0.y*dv; rb[2]=b0.z*dv; rb[3]=b0.w*dv;
        rb[4]=b1.x*dv; rb[5]=b1.y*dv; rb[6]=b1.z*dv; rb[7]=b1.w*dv;
    }
    const int nIter = Kchunk / 16;
    {
        int hs = (k0 & 16) + bkh * 8;
#pragma unroll
        for (int i = 0; i < 8; i++) sA[0][bkh * 8 + i][br] = ((wreg >> (hs + i)) & 1u) ? 1.0f : 0.0f;
#pragma unroll
        for (int i = 0; i < 8; i++) sB[0][bk][bnb + i] = rb[i];
    }
    __syncthreads();

    for (int it = 0; it < nIter; ++it) {
        const int cur = it & 1;
        const bool more = (it + 1) < nIter;
        int ktn = k0 + (it + 1) * 16;
        if (more) {
            wreg = bits[(size_t)(row0 + br) * nw + (ktn >> 5)];
            float dv = dinv[ktn + bk];
            const float* bs_ = H + (size_t)(ktn + bk) * ldh + bnb;
            float4 b0 = *(const float4*)bs_, b1 = *(const float4*)(bs_ + 4);
            rb[0]=b0.x*dv; rb[1]=b0.y*dv; rb[2]=b0.z*dv; rb[3]=b0.w*dv;
            rb[4]=b1.x*dv; rb[5]=b1.y*dv; rb[6]=b1.z*dv; rb[7]=b1.w*dv;
        }
        mma_tile_1p(acc, sA[cur], sB[cur], wm, wn, grp, qid);
        if (more) {
            int hs = (ktn & 16) + bkh * 8;
#pragma unroll
            for (int i = 0; i < 8; i++) sA[cur ^ 1][bkh * 8 + i][br] = ((wreg >> (hs + i)) & 1u) ? 1.0f : 0.0f;
#pragma unroll
            for (int i = 0; i < 8; i++) sB[cur ^ 1][bk][bnb + i] = rb[i];
        }
        __syncthreads();
    }
#pragma unroll
    for (int t = 0; t < 4; t++) {
        int r = row0 + wm * 64 + t * 16 + grp;
#pragma unroll
        for (int u = 0; u < 4; u++) {
            int c = wn * 32 + u * 8 + qid * 2;
            *(float2*)(Pout + (size_t)r * 128 + c)       = make_float2(acc[t][u][0], acc[t][u][1]);
            *(float2*)(Pout + (size_t)(r + 8) * 128 + c) = make_float2(acc[t][u][2], acc[t][u][3]);
        }
    }
}

// ---------------- reduce partials + bias + l2norm (+optional concat copy, +optional scores) ----------------
// grid (M/4, 1, 2), block 512 (4 rows x 128)
__global__ void k_red_l2(const float* __restrict__ P, int nsl, int cnt,
                         const float* __restrict__ bias,
                         float* __restrict__ O0, float* __restrict__ O1,
                         float* __restrict__ C0, float* __restrict__ C1, int cld,
                         const float* __restrict__ Wp, const float* __restrict__ bp)
{
    int z = blockIdx.z, t = threadIdx.x;
    int rloc = t >> 7, c = t & 127;
    int r = blockIdx.x * 4 + rloc;
    const float* Pz = P + (size_t)z * nsl * cnt;
    float s = bias[c];
    for (int k = 0; k < nsl; k++) s += Pz[(size_t)k * cnt + r * 128 + c];
    float q = s * s;
    for (int o = 16; o; o >>= 1) q += __shfl_xor_sync(~0u, q, o);
    __shared__ float ws[16];
    if ((t & 31) == 0) ws[t >> 5] = q;
    __syncthreads();
    float tot = ws[rloc * 4] + ws[rloc * 4 + 1] + ws[rloc * 4 + 2] + ws[rloc * 4 + 3];
    float v = s * rsqrtf(tot);
    float* O = z ? O1 : O0;
    O[(size_t)r * 128 + c] = v;
    if (C0) { float* C = z ? C1 : C0; C[(size_t)r * cld + c] = v; }
    if (Wp && z == 0) {
        float q2 = v * Wp[c];
        for (int o = 16; o; o >>= 1) q2 += __shfl_xor_sync(~0u, q2, o);
        __syncthreads();
        if ((t & 31) == 0) ws[t >> 5] = q2;
        __syncthreads();
        if (c == 0) {
            float sum = ws[rloc * 4] + ws[rloc * 4 + 1] + ws[rloc * 4 + 2] + ws[rloc * 4 + 3];
            g_scores[r] = 1.f / (1.f + __expf(-(sum + bp[0])));
        }
    }
}

// ---------------- reduce partials, float4, D^-1/2 row scale, write into concat at offset ----------------
// grid (cnt/1024, 1, 2), block 256
__global__ void k_reduce_s4(const float* __restrict__ P, int nsl, int cnt,
                            float* __restrict__ O0, float* __restrict__ O1, int oldd, int ooff,
                            const float* __restrict__ dinv)
{
    int z = blockIdx.z;
    float* O = z ? O1 : O0;
    const float* Pz = P + (size_t)z * nsl * cnt;
    int e = (blockIdx.x * 256 + threadIdx.x) * 4;
    float4 s = make_float4(0.f, 0.f, 0.f, 0.f);
    for (int k = 0; k < nsl; k++) {
        float4 v = *(const float4*)(Pz + (size_t)k * cnt + e);
        s.x += v.x; s.y += v.y; s.z += v.z; s.w += v.w;
    }
    int r = e >> 7, c = e & 127;
    float d = dinv[r];
    *(float4*)(O + (size_t)r * oldd + ooff + c) = make_float4(d * s.x, d * s.y, d * s.z, d * s.w);
}

// ---------------- degree popc only (dinv folded into bin loader), 8 rows/block ----------------
__global__ void k_dinv()
{
    int w = threadIdx.x >> 5, lane = threadIdx.x & 31;
    int r = blockIdx.x * 8 + w;
    int c = __popc(g_bits[r * NW + lane * 2]) + __popc(g_bits[r * NW + lane * 2 + 1]);
    for (int o = 16; o; o >>= 1) c += __shfl_xor_sync(~0u, c, o);
    if (lane == 0) g_dinv[r] = rsqrtf((float)c);
}

// ---------------- top-1024 selection: bitonic on packed 64-bit keys ----------------
__global__ void k_pool1()
{
    __shared__ unsigned long long sk[2048];
    int t = threadIdx.x;
    for (int r = t; r < 2048; r += 1024)
        sk[r] = ((unsigned long long)__float_as_uint(g_scores[r]) << 32) | (unsigned)(2047 - r);
    __syncthreads();
    for (int k = 2; k <= 2048; k <<= 1)
        for (int j = k >> 1; j > 0; j >>= 1) {
            int i = ((t & ~(j - 1)) << 1) | (t & (j - 1));
            int p = i | j;
            unsigned long long a = sk[i], b = sk[p];
            bool up = ((i & k) == 0);
            if (up ? (a < b) : (a > b)) { sk[i] = b; sk[p] = a; }
            __syncthreads();
        }
    unsigned long long key = sk[t];
    g_vals[t] = __uint_as_float((unsigned)(key >> 32));
    g_idx[t] = 2047 - (int)(unsigned)(key & 0xFFFFFFFFull);
}

// ---------------- pooled 2-hop bits + dinvp + gather (merged), one pooled row per block ----------------
__global__ void k_pool2()
{
    __shared__ unsigned sbi[NW];
    __shared__ int ws[8];
    int i = blockIdx.x, t = threadIdx.x;
    int ii = g_idx[i];
    const unsigned* bi = g_bits + (size_t)ii * NW;
    if (t < NW) sbi[t] = bi[t];
    __syncthreads();
    int cnt = 0;
    for (int jb = 0; jb < KP; jb += 256) {
        int j = jb + t;
        const unsigned* bj = g_bits + (size_t)g_idx[j] * NW;
        bool c = false;
        for (int w = 0; w < NW && !c; w++) c = (sbi[w] & bj[w]) != 0u;
        unsigned word = __ballot_sync(~0u, c);
        cnt += c ? 1 : 0;
        if ((t & 31) == 0) g_bitsp[i * NWP + (j >> 5)] = word;
    }
    for (int o = 16; o; o >>= 1) cnt += __shfl_xor_sync(~0u, cnt, o);
    if ((t & 31) == 0) ws[t >> 5] = cnt;
    // gather (independent of dinvp; loader applies dinvp later)
    float vl = g_vals[i];
    int z = t >> 7, c = t & 127;
    g_catp[z][(size_t)i * 256 + c] = g_fg[z][(size_t)ii * 128 + c] * vl;
    __syncthreads();
    if (t == 0) {
        int s = 0;
        for (int k = 0; k < 8; k++) s += ws[k];
        g_dinvp[i] = rsqrtf((float)s);
    }
}

// ---------------- final: NCE combine for both stages + scalar ----------------
__global__ void k_final(float* __restrict__ out)
{
    int t = threadIdx.x;   // 1024 threads
    float sg = 0.f, sp = 0.f;
    for (int i = t; i < NN; i += 1024) {
        float s1 = 0.f, s2 = 0.f;
        for (int k = 0; k < 16; k++) { s1 += g_rp[k * NN + i]; s2 += g_cp[k * NN + i]; }
        sg += 2.f * INVT + __logf(s1) + __logf(s2) - 2.f * g_diag[i] * INVT;
    }
    {
        int i = t;
        float s1 = 0.f, s2 = 0.f;
        for (int k = 0; k < 8; k++) { s1 += g_rp2[k * KP + i]; s2 += g_cp2[k * KP + i]; }
        sp += 2.f * INVT + __logf(s1) + __logf(s2) - 2.f * g_diagp[i] * INVT;
    }
    for (int o = 16; o; o >>= 1) {
        sg += __shfl_xor_sync(~0u, sg, o);
        sp += __shfl_xor_sync(~0u, sp, o);
    }
    __shared__ float wg[32], wp[32];
    if ((t & 31) == 0) { wg[t >> 5] = sg; wp[t >> 5] = sp; }
    __syncthreads();
    if (t == 0) {
        float a = 0.f, b = 0.f;
        for (int i = 0; i < 32; i++) { a += wg[i]; b += wp[i]; }
        out[0] = a * (1.f / NN) + b * (1.f / KP);
    }
}

// ---------------- host ----------------
extern "C" void kernel_launch(void* const* d_in, const int* in_sizes, int n_in,
                              void* d_out, int out_size)
{
    (void)in_sizes; (void)n_in; (void)out_size;
    const float* fs    = (const float*)d_in[0];
    const float* ft    = (const float*)d_in[1];
    const float* We    = (const float*)d_in[2];
    const float* be    = (const float*)d_in[3];
    const float* Wg    = (const float*)d_in[4];
    const float* bg    = (const float*)d_in[5];
    const float* Wpool = (const float*)d_in[6];
    const float* bpool = (const float*)d_in[7];
    const float* Wgp   = (const float*)d_in[8];
    const float* bgp   = (const float*)d_in[9];

    void* p;
    cudaGetSymbolAddress(&p, g_fet);   float* FET  = (float*)p;
    cudaGetSymbolAddress(&p, g_fes);   float* FES  = (float*)p;
    cudaGetSymbolAddress(&p, g_bits);  unsigned* BITS  = (unsigned*)p;
    cudaGetSymbolAddress(&p, g_bitsp); unsigned* BITSP = (unsigned*)p;
    cudaGetSymbolAddress(&p, g_dinv);  float* DINV  = (float*)p;
    cudaGetSymbolAddress(&p, g_dinvp); float* DINVP = (float*)p;
    cudaGetSymbolAddress(&p, g_fg);    float* FG   = (float*)p;
    cudaGetSymbolAddress(&p, g_fp);    float* FP   = (float*)p;
    cudaGetSymbolAddress(&p, g_cat);   float* CAT  = (float*)p;
    cudaGetSymbolAddress(&p, g_catp);  float* CATP = (float*)p;
    cudaGetSymbolAddress(&p, g_part);  float* PART = (float*)p;
    cudaGetSymbolAddress(&p, g_rp);    float* RP   = (float*)p;
    cudaGetSymbolAddress(&p, g_cp);    float* CP   = (float*)p;
    cudaGetSymbolAddress(&p, g_rp2);   float* RP2  = (float*)p;
    cudaGetSymbolAddress(&p, g_cp2);   float* CP2  = (float*)p;
    cudaGetSymbolAddress(&p, g_diag);  float* DG1  = (float*)p;
    cudaGetSymbolAddress(&p, g_diagp); float* DG2  = (float*)p;

    const int ND = NN * DD;    // 262144
    const int KD = KP * DD;    // 131072
    const int CATLD = 384, CATPLD = 256;

    cudaStream_t sB;
    cudaEvent_t evF, evJ;
    cudaStreamCreateWithFlags(&sB, cudaStreamNonBlocking);
    cudaEventCreateWithFlags(&evF, cudaEventDisableTiming);
    cudaEventCreateWithFlags(&evJ, cudaEventDisableTiming);

    // 1) embed: f = l2norm(x @ We + be); z=0 teacher(ft), z=1 student(fs)
    k_mma_nn<<<dim3(16, 8, 2), 256>>>(ft, fs, CD, We, PART, NN, 64, 8);
    k_red_l2<<<dim3(NN / 4, 1, 2), 512>>>(PART, 8, ND, be, FET, FES, CAT, CAT + NN * CATLD, CATLD, (float*)0, (float*)0);

    // 2) adjacency bits from teacher gram (symmetric) + degrees
    k_mma_nt_adj<<<136, 256>>>(FET);
    k_dinv<<<NN / 8, 256>>>();

    // 3) TAGConv k=2 via binary MMA (dinv scaling fused into B loader)
    k_mma_bin<<<dim3(16, 8, 2), 256>>>(BITS, NW, FET, FES, 128, DINV, PART, NN, 256, 8);
    k_reduce_s4<<<dim3(ND / 1024, 1, 2), 256>>>(PART, 8, ND, CAT, CAT + NN * CATLD, CATLD, 128, DINV);
    k_mma_bin<<<dim3(16, 8, 2), 256>>>(BITS, NW, CAT + 128, CAT + NN * CATLD + 128, CATLD, DINV, PART, NN, 256, 8);
    k_reduce_s4<<<dim3(ND / 1024, 1, 2), 256>>>(PART, 8, ND, CAT, CAT + NN * CATLD, CATLD, 256, DINV);

    // 4) concat GEMM (K=384, Kchunk=96) + bias + l2norm -> FG, + fused pooling scores (z=0)
    k_mma_nn<<<dim3(16, 4, 2), 256>>>(CAT, CAT + NN * CATLD, CATLD, Wg, PART, NN, 96, 4);
    k_red_l2<<<dim3(NN / 4, 1, 2), 512>>>(PART, 4, ND, bg, FG, FG + ND, (float*)0, (float*)0, 0, Wpool, bpool);

    // 5) stage-1 NCE on side stream, overlapped with the pooling chain
    cudaEventRecord(evF, 0);
    cudaStreamWaitEvent(sB, evF, 0);
    k_mma_nt_nce<<<dim3(16, 16), 256, 0, sB>>>(FG, FG + ND, NN, RP, CP, DG1);
    cudaEventRecord(evJ, sB);

    // 6) pooling: selection, then bits+dinvp+gather merged
    k_pool1<<<1, 1024>>>();
    k_pool2<<<KP, 256>>>();

    // 7) pooled TAGConv k=1 (dinvp fused into loader)
    k_mma_bin<<<dim3(8, 8, 2), 256>>>(BITSP, NWP, CATP, CATP + KP * CATPLD, CATPLD, DINVP, PART, KP, 128, 8);
    k_reduce_s4<<<dim3(KD / 1024, 1, 2), 256>>>(PART, 8, KD, CATP, CATP + KP * CATPLD, CATPLD, 128, DINVP);
    k_mma_nn<<<dim3(8, 4, 2), 256>>>(CATP, CATP + KP * CATPLD, CATPLD, Wgp, PART, KP, 64, 4);
    k_red_l2<<<dim3(KP / 4, 1, 2), 512>>>(PART, 4, KD, bgp, FP, FP + KD, (float*)0, (float*)0, 0, (float*)0, (float*)0);

    // 8) pooled NCE
    k_mma_nt_nce<<<dim3(8, 8), 256>>>(FP, FP + KD, KP, RP2, CP2, DG2);

    // 9) join + NCE combine (both stages) + final scalar
    cudaStreamWaitEvent(0, evJ, 0);
    k_final<<<1, 1024>>>((float*)d_out);
}